// round 8
// baseline (speedup 1.0000x reference)
#include <cuda_runtime.h>

#define NN 25000
#define NE 400000

#define INV_SQRT3 0.57735026919f
#define INV_SQRT2 0.70710678119f

// ---------------- scratch (device globals; allocation-free) ----------------
__device__ float4 d_g_s  [NN * 16];   // s   = s_in @ W1_0 /8           (N,64)
__device__ float4 d_g_v  [NN * 24];   // v   = v_in . W1_1 /sqrt32      (N,32,3) [u*3+c]
__device__ float4 d_g_scs[NN * 16];   // sc_s                           (N,64)
__device__ float4 d_g_scv[NN * 24];   // sc_v                           (N,96)  [u*3+c]
__device__ float4 d_g_ns [NN * 24];   // scatter accum s-part           (N,96)
__device__ float4 d_g_nv [NN * 96];   // scatter accum v-part           (N,3,128) [c][u]
__device__ float  d_W1K[8 * 64];      // Wfc1 natural [k][j], prescaled 1/sqrt(8)
__device__ float  d_W2K[64 * 64];     // Wfc2 natural [k][j], prescaled 1/8
__device__ float  d_W3K[64 * 256];    // Wfc3 natural [k][j], prescaled, zero-pad j>=224

// ---------------- f32x2 helpers ----------------
#define FMA2(d, a, b) \
    asm("fma.rn.f32x2 %0, %1, %2, %0;" : "+l"(d) : "l"(a), "l"(b))
#define PACK2(d, lo, hi) \
    asm("mov.b64 %0, {%1, %2};" : "=l"(d) : "f"(lo), "f"(hi))
#define UNPACK2(lo, hi, s) \
    asm("mov.b64 {%0, %1}, %2;" : "=f"(lo), "=f"(hi) : "l"(s))

__device__ __forceinline__ float silu_f(float x) {
    return x / (1.0f + __expf(-x));
}

__device__ __forceinline__ void red4(float* p, float a, float b, float c, float d) {
    asm volatile("red.global.add.v4.f32 [%0], {%1,%2,%3,%4};"
                 :: "l"(p), "f"(a), "f"(b), "f"(c), "f"(d) : "memory");
}

// ---------------- 8x8 register-tiled GEMM on shared memory ----------------
// D[j][e] = (silu of) sum_k A[k][j] * B[k][e];  A stride 64, B/D stride 128.
// 128 threads: thread t -> jt = t&7 (rows j0=8*jt), et = t>>3 (cols e0=8*et).
template <int KLEN, bool DOSILU>
__device__ __forceinline__ void gemm8x8(const float* __restrict__ sAm,
                                        const float* __restrict__ sBm,
                                        float* __restrict__ sD, int t) {
    int jt = t & 7, et = t >> 3;
    const float* Ap = sAm + jt * 8;
    const float* Bp = sBm + et * 8;
    unsigned long long acc[32];
#pragma unroll
    for (int i = 0; i < 32; ++i) acc[i] = 0ull;
#pragma unroll 4
    for (int k = 0; k < KLEN; ++k) {
        float4 a0 = *reinterpret_cast<const float4*>(Ap + k * 64);
        float4 a1 = *reinterpret_cast<const float4*>(Ap + k * 64 + 4);
        ulonglong2 b01 = *reinterpret_cast<const ulonglong2*>(Bp + k * 128);
        ulonglong2 b23 = *reinterpret_cast<const ulonglong2*>(Bp + k * 128 + 4);
        unsigned long long ap;
        PACK2(ap, a0.x, a0.x);
        FMA2(acc[0],  ap, b01.x); FMA2(acc[1],  ap, b01.y);
        FMA2(acc[2],  ap, b23.x); FMA2(acc[3],  ap, b23.y);
        PACK2(ap, a0.y, a0.y);
        FMA2(acc[4],  ap, b01.x); FMA2(acc[5],  ap, b01.y);
        FMA2(acc[6],  ap, b23.x); FMA2(acc[7],  ap, b23.y);
        PACK2(ap, a0.z, a0.z);
        FMA2(acc[8],  ap, b01.x); FMA2(acc[9],  ap, b01.y);
        FMA2(acc[10], ap, b23.x); FMA2(acc[11], ap, b23.y);
        PACK2(ap, a0.w, a0.w);
        FMA2(acc[12], ap, b01.x); FMA2(acc[13], ap, b01.y);
        FMA2(acc[14], ap, b23.x); FMA2(acc[15], ap, b23.y);
        PACK2(ap, a1.x, a1.x);
        FMA2(acc[16], ap, b01.x); FMA2(acc[17], ap, b01.y);
        FMA2(acc[18], ap, b23.x); FMA2(acc[19], ap, b23.y);
        PACK2(ap, a1.y, a1.y);
        FMA2(acc[20], ap, b01.x); FMA2(acc[21], ap, b01.y);
        FMA2(acc[22], ap, b23.x); FMA2(acc[23], ap, b23.y);
        PACK2(ap, a1.z, a1.z);
        FMA2(acc[24], ap, b01.x); FMA2(acc[25], ap, b01.y);
        FMA2(acc[26], ap, b23.x); FMA2(acc[27], ap, b23.y);
        PACK2(ap, a1.w, a1.w);
        FMA2(acc[28], ap, b01.x); FMA2(acc[29], ap, b01.y);
        FMA2(acc[30], ap, b23.x); FMA2(acc[31], ap, b23.y);
    }
    float* D = sD + (size_t)(jt * 8) * 128 + et * 8;
#pragma unroll
    for (int j = 0; j < 8; ++j) {
#pragma unroll
        for (int i = 0; i < 4; ++i) {
            float lo, hi;
            UNPACK2(lo, hi, acc[j * 4 + i]);
            if (DOSILU) { lo = silu_f(lo); hi = silu_f(hi); }
            unsigned long long p;
            PACK2(p, lo, hi);
            *reinterpret_cast<unsigned long long*>(D + j * 128 + 2 * i) = p;
        }
    }
}

// ---------------- kernel 0: zero accumulators + prescale weights ------------
__global__ void k_pre(const float* __restrict__ Wfc1,
                      const float* __restrict__ Wfc2,
                      const float* __restrict__ Wfc3) {
    int i = blockIdx.x * 256 + threadIdx.x;
    const int NZ = NN * 120;   // float4 count of (ns + nv)
    if (i < NZ) {
        float4 z = make_float4(0.f, 0.f, 0.f, 0.f);
        if (i < NN * 24) d_g_ns[i] = z;
        else             d_g_nv[i - NN * 24] = z;
    } else {
        int j = i - NZ;
        if (j < 512) {
            d_W1K[j] = Wfc1[j] * 0.3535533906f;
        } else if (j < 4608) {
            d_W2K[j - 512] = Wfc2[j - 512] * 0.125f;
        } else if (j < 4608 + 16384) {
            int m = j - 4608;
            int k = m >> 8, col = m & 255;
            float v = 0.f;
            if (col < 224) {
                float s = 0.03125f;  // (1/sqrt(64)) * (1/sqrt(16))
                if (col >= 192)      s *= INV_SQRT2;
                else if (col >= 160) s *= INV_SQRT3;
                v = Wfc3[k * 224 + col] * s;
            }
            d_W3K[m] = v;
        }
    }
}

// ---------------- kernel 2: node prep, persistent warp-per-node -------------
__global__ void __launch_bounds__(256) k_prep(const float* __restrict__ nh,
                                              const float* __restrict__ W1_0,
                                              const float* __restrict__ W1_1,
                                              const float* __restrict__ Wsc0,
                                              const float* __restrict__ Wsc1) {
    __shared__ float sW10[4096], sWsc0[4096], sW11[1024], sWsc1[1024], sIn[1280];
    int t = threadIdx.x;
    for (int i = t; i < 4096; i += 256) { sW10[i] = W1_0[i]; sWsc0[i] = Wsc0[i]; }
    for (int i = t; i < 1024; i += 256) { sW11[i] = W1_1[i]; sWsc1[i] = Wsc1[i]; }
    __syncthreads();

    int wid = t >> 5, l = t & 31;
    float* gs  = (float*)d_g_s;
    float* gv  = (float*)d_g_v;
    float* gss = (float*)d_g_scs;
    float* gsv = (float*)d_g_scv;
    float* row = sIn + wid * 160;

    for (int it = 0; it < 8; ++it) {
        int n = blockIdx.x * 64 + it * 8 + wid;
        if (n >= NN) break;
        {
            const float4* src = reinterpret_cast<const float4*>(nh + (size_t)n * 160);
            float4* dst = reinterpret_cast<float4*>(row);
            for (int i = l; i < 40; i += 32) dst[i] = __ldg(src + i);
        }
        __syncwarp();
#pragma unroll
        for (int r = 0; r < 2; ++r) {
            int o = l + r * 32;
            float a = 0.f, b = 0.f;
#pragma unroll 8
            for (int u = 0; u < 64; ++u) {
                float x = row[u];
                a += x * sW10[u * 64 + o];
                b += x * sWsc0[u * 64 + o];
            }
            gs [(size_t)n * 64 + o] = a * 0.125f;
            gss[(size_t)n * 64 + o] = b * 0.125f;
        }
#pragma unroll
        for (int r = 0; r < 3; ++r) {
            int o = l + r * 32;
            int up = o / 3, c = o - up * 3;
            float a = 0.f, b = 0.f;
#pragma unroll 8
            for (int u = 0; u < 32; ++u) {
                float x = row[64 + u * 3 + c];
                a += x * sW11[u * 32 + up];
                b += x * sWsc1[u * 32 + up];
            }
            gv [(size_t)n * 96 + o] = a * 0.1767766953f;
            gsv[(size_t)n * 96 + o] = b * 0.1767766953f;
        }
        __syncwarp();
    }
}

// ---------------- kernel 3: edge MLP (GEMM pipeline) + messages + scatter ---
// smem arena (floats): [0:4096) A-region (attS+W1K -> W2K -> Wc)
//                      [4096:12288) B-region (h1s -> wc chunk)
//                      [12288:20480) h2s
// 20480 floats = 81920 B -> 2 blocks/SM.
__global__ void __launch_bounds__(128) k_edge(const int* __restrict__ ei,
                                              const float* __restrict__ esh,
                                              const float* __restrict__ eattr) {
    extern __shared__ float sm[];
    float* sA  = sm;           // 4096
    float* sB  = sm + 4096;    // 8192
    float* sH2 = sm + 12288;   // 8192
    int t = threadIdx.x;
    int e = blockIdx.x * 128 + t;   // NE = 3125*128 exactly

    // ---- P0: stage att (transposed [k][e]) + W1K ----
    {
        const float4* ap = reinterpret_cast<const float4*>(eattr + (size_t)e * 8);
        float4 a0 = __ldg(ap), a1 = __ldg(ap + 1);
        sA[0 * 128 + t] = a0.x; sA[1 * 128 + t] = a0.y;
        sA[2 * 128 + t] = a0.z; sA[3 * 128 + t] = a0.w;
        sA[4 * 128 + t] = a1.x; sA[5 * 128 + t] = a1.y;
        sA[6 * 128 + t] = a1.z; sA[7 * 128 + t] = a1.w;
        for (int i = t; i < 512; i += 128) sA[1024 + i] = d_W1K[i];
    }
    __syncthreads();

    // ---- P1: h1s = silu(W1K @ attS) ----
    gemm8x8<8, true>(sA + 1024, sA, sB, t);
    __syncthreads();
    for (int i = t; i < 4096; i += 128) sA[i] = d_W2K[i];
    __syncthreads();

    // ---- P2: h2s = silu(W2K @ h1s) ----
    gemm8x8<64, true>(sA, sB, sH2, t);
    __syncthreads();

    // ---- edge state ----
    int src = __ldg(ei + e);
    int dst = __ldg(ei + NE + e);
    float4 sh = __ldg(reinterpret_cast<const float4*>(esh + (size_t)e * 4));
    const float4* sd4 = reinterpret_cast<const float4*>((const float*)d_g_s + (size_t)dst * 64);
    const float4* vd4 = reinterpret_cast<const float4*>((const float*)d_g_v + (size_t)dst * 96);
    float* nsp = (float*)d_g_ns + (size_t)src * 96;
    float* nvp = (float*)d_g_nv + (size_t)src * 384;

    // ---- P3: 4 chunks of 64 w-rows: GEMM then consume ----
#pragma unroll 1
    for (int c = 0; c < 4; ++c) {
        // load Wc[64][64] = d_W3K[:, 64c:64c+64]
#pragma unroll
        for (int r = 0; r < 8; ++r) {
            int idx4 = t + 128 * r;
            int k = idx4 >> 4;
            int jj = (idx4 & 15) * 4;
            *reinterpret_cast<float4*>(sA + k * 64 + jj) =
                *reinterpret_cast<const float4*>(d_W3K + k * 256 + 64 * c + jj);
        }
        __syncthreads();
        gemm8x8<64, false>(sA, sH2, sB, t);
        __syncthreads();

        if (c == 0) {
            // w0: m0 -> ns[0:64]
#pragma unroll 1
            for (int g = 0; g < 16; ++g) {
                float4 s4 = __ldg(sd4 + g);
                float w0 = sB[(4 * g + 0) * 128 + t];
                float w1 = sB[(4 * g + 1) * 128 + t];
                float w2 = sB[(4 * g + 2) * 128 + t];
                float w3 = sB[(4 * g + 3) * 128 + t];
                red4(nsp + 4 * g, w0 * s4.x * sh.x, w1 * s4.y * sh.x,
                                  w2 * s4.z * sh.x, w3 * s4.w * sh.x);
            }
        } else if (c == 1) {
            // w1: mv0 -> nv[cc][0:64]
#pragma unroll 1
            for (int g = 0; g < 16; ++g) {
                float4 s4 = __ldg(sd4 + g);
                float a = sB[(4 * g + 0) * 128 + t] * s4.x;
                float b = sB[(4 * g + 1) * 128 + t] * s4.y;
                float cc = sB[(4 * g + 2) * 128 + t] * s4.z;
                float d = sB[(4 * g + 3) * 128 + t] * s4.w;
                red4(nvp +       4 * g, a * sh.y, b * sh.y, cc * sh.y, d * sh.y);
                red4(nvp + 128 + 4 * g, a * sh.z, b * sh.z, cc * sh.z, d * sh.z);
                red4(nvp + 256 + 4 * g, a * sh.w, b * sh.w, cc * sh.w, d * sh.w);
            }
        } else if (c == 2) {
            // rows 0:32 = w2 (mv1), rows 32:64 = w3 (m1)
#pragma unroll 1
            for (int g = 0; g < 8; ++g) {
                const float4* vb = vd4 + g * 3;
                float4 b0 = __ldg(vb), b1 = __ldg(vb + 1), b2 = __ldg(vb + 2);
                float vv[12] = {b0.x, b0.y, b0.z, b0.w, b1.x, b1.y, b1.z, b1.w,
                                b2.x, b2.y, b2.z, b2.w};
                float m1[4], mv1[3][4];
#pragma unroll
                for (int i = 0; i < 4; ++i) {
                    int u = 4 * g + i;
                    float w2v = sB[u * 128 + t];
                    float w3v = sB[(32 + u) * 128 + t];
                    float vx = vv[i * 3], vy = vv[i * 3 + 1], vz = vv[i * 3 + 2];
                    mv1[0][i] = w2v * vx * sh.x;
                    mv1[1][i] = w2v * vy * sh.x;
                    mv1[2][i] = w2v * vz * sh.x;
                    m1[i] = w3v * (vx * sh.y + vy * sh.z + vz * sh.w);
                }
                red4(nsp + 64 + 4 * g, m1[0], m1[1], m1[2], m1[3]);
#pragma unroll
                for (int cc = 0; cc < 3; ++cc)
                    red4(nvp + cc * 128 + 64 + 4 * g,
                         mv1[cc][0], mv1[cc][1], mv1[cc][2], mv1[cc][3]);
            }
        } else {
            // rows 0:32 = w4 (mv2 cross product); rows 32:64 are zero-pad
#pragma unroll 1
            for (int g = 0; g < 8; ++g) {
                const float4* vb = vd4 + g * 3;
                float4 b0 = __ldg(vb), b1 = __ldg(vb + 1), b2 = __ldg(vb + 2);
                float vv[12] = {b0.x, b0.y, b0.z, b0.w, b1.x, b1.y, b1.z, b1.w,
                                b2.x, b2.y, b2.z, b2.w};
                float mv2[3][4];
#pragma unroll
                for (int i = 0; i < 4; ++i) {
                    int u = 4 * g + i;
                    float w4v = sB[u * 128 + t];
                    float vx = vv[i * 3], vy = vv[i * 3 + 1], vz = vv[i * 3 + 2];
                    mv2[0][i] = w4v * (vy * sh.w - vz * sh.z);
                    mv2[1][i] = w4v * (vz * sh.y - vx * sh.w);
                    mv2[2][i] = w4v * (vx * sh.z - vy * sh.y);
                }
#pragma unroll
                for (int cc = 0; cc < 3; ++cc)
                    red4(nvp + cc * 128 + 96 + 4 * g,
                         mv2[cc][0], mv2[cc][1], mv2[cc][2], mv2[cc][3]);
            }
        }
        __syncthreads();
    }
}

// ---------------- kernel 4: output projection + skip + RMS (R5 version) ----
__global__ void __launch_bounds__(256) k_out(float* __restrict__ out,
                                             const float* __restrict__ W2_0,
                                             const float* __restrict__ W2_1,
                                             const float* __restrict__ g0,
                                             const float* __restrict__ g1) {
    extern __shared__ float smo[];
    float* sW20 = smo;           // 6144
    float* sW21 = smo + 6144;    // 4096
    float* sG   = smo + 10240;   // 96 (+32 pad)
    float* sAcc = smo + 10368;   // 8 * 480 = 3840  (total 14208 fl = 56832 B)
    int t = threadIdx.x;
    for (int i = t; i < 6144; i += 256) sW20[i] = W2_0[i];
    for (int i = t; i < 4096; i += 256) sW21[i] = W2_1[i];
    if (t < 64) sG[t] = g0[t];
    else if (t < 96) sG[t] = g1[t - 64];
    __syncthreads();

    const float* gns = (const float*)d_g_ns;
    const float* gnv = (const float*)d_g_nv;
    const float* gss = (const float*)d_g_scs;
    const float* gsv = (const float*)d_g_scv;

    int wid = t >> 5, l = t & 31;
    float* acc = sAcc + wid * 480;

    for (int it = 0; it < 8; ++it) {
        int n = blockIdx.x * 64 + it * 8 + wid;
        if (n >= NN) break;
        for (int i = l; i < 480; i += 32)
            acc[i] = (i < 96) ? gns[(size_t)n * 96 + i]
                              : gnv[(size_t)n * 384 + i - 96];
        __syncwarp();

        float vs[2], vv[3];
        float ssq_s = 0.f, ssq_v = 0.f;
#pragma unroll
        for (int r = 0; r < 2; ++r) {
            int o = l + r * 32;
            float a = 0.f;
#pragma unroll 8
            for (int k = 0; k < 96; ++k) a += acc[k] * sW20[k * 64 + o];
            float val = a * 0.1020620726f + gss[(size_t)n * 64 + o];
            vs[r] = val;
            ssq_s += val * val;
        }
#pragma unroll
        for (int r = 0; r < 3; ++r) {
            int o = l + r * 32;
            int up = o / 3, c = o - up * 3;
            float a = 0.f;
#pragma unroll 8
            for (int u = 0; u < 128; ++u) a += acc[96 + c * 128 + u] * sW21[u * 32 + up];
            float val = a * 0.0883883476f + gsv[(size_t)n * 96 + o];
            vv[r] = val;
            ssq_v += val * val;
        }
#pragma unroll
        for (int d = 16; d; d >>= 1) {
            ssq_s += __shfl_xor_sync(0xffffffffu, ssq_s, d);
            ssq_v += __shfl_xor_sync(0xffffffffu, ssq_v, d);
        }
        float rs = rsqrtf(ssq_s * (1.0f / 64.0f) + 1e-5f);
        float rv = rsqrtf(ssq_v * (1.0f / 32.0f) + 1e-5f);
#pragma unroll
        for (int r = 0; r < 2; ++r) {
            int o = l + r * 32;
            out[(size_t)n * 160 + o] = vs[r] * rs * sG[o];
        }
#pragma unroll
        for (int r = 0; r < 3; ++r) {
            int o = l + r * 32;
            out[(size_t)n * 160 + 64 + o] = vv[r] * rv * sG[64 + o / 3];
        }
        __syncwarp();
    }
}

// ---------------- launch ----------------
extern "C" void kernel_launch(void* const* d_in, const int* in_sizes, int n_in,
                              void* d_out, int out_size) {
    const float* nh    = (const float*)d_in[0];
    const int*   ei    = (const int*)  d_in[1];
    const float* esh   = (const float*)d_in[2];
    const float* eattr = (const float*)d_in[3];
    const float* W1_0  = (const float*)d_in[4];
    const float* W1_1  = (const float*)d_in[5];
    const float* Wfc1  = (const float*)d_in[6];
    const float* Wfc2  = (const float*)d_in[7];
    const float* Wfc3  = (const float*)d_in[8];
    const float* W2_0  = (const float*)d_in[9];
    const float* W2_1  = (const float*)d_in[10];
    const float* Wsc0  = (const float*)d_in[11];
    const float* Wsc1  = (const float*)d_in[12];
    const float* g0    = (const float*)d_in[13];
    const float* g1    = (const float*)d_in[14];
    float* out = (float*)d_out;

    cudaFuncSetAttribute(k_edge, cudaFuncAttributeMaxDynamicSharedMemorySize, 81920);
    cudaFuncSetAttribute(k_out, cudaFuncAttributeMaxDynamicSharedMemorySize, 57344);

    k_pre<<<11802, 256>>>(Wfc1, Wfc2, Wfc3);              // zero + prescale
    k_prep<<<391, 256>>>(nh, W1_0, W1_1, Wsc0, Wsc1);     // 64 nodes/block
    k_edge<<<3125, 128, 81920>>>(ei, esh, eattr);
    k_out<<<391, 256, 57344>>>(out, W2_0, W2_1, g0, g1);  // 64 nodes/block
}

// round 9
// speedup vs baseline: 1.0907x; 1.0907x over previous
#include <cuda_runtime.h>

#define NN 25000
#define NE 400000

#define INV_SQRT3 0.57735026919f
#define INV_SQRT2 0.70710678119f

// ---------------- scratch (device globals; allocation-free) ----------------
__device__ float4 d_g_s  [NN * 16];   // s   = s_in @ W1_0 /8           (N,64)
__device__ float4 d_g_v  [NN * 24];   // v   = v_in . W1_1 /sqrt32      (N,32,3) [u*3+c]
__device__ float4 d_g_scs[NN * 16];   // sc_s                           (N,64)
__device__ float4 d_g_scv[NN * 24];   // sc_v                           (N,96)  [u*3+c]
__device__ float4 d_g_ns [NN * 24];   // scatter accum s-part           (N,96)
__device__ float4 d_g_nv [NN * 96];   // scatter accum v-part           (N,3,128) [c][u]
__device__ float  d_W1K[8 * 64];      // Wfc1 natural [k][j], prescaled 1/sqrt(8)
__device__ float  d_W2K[64 * 64];     // Wfc2 natural [k][j], prescaled 1/8
__device__ float  d_W3K[64 * 256];    // Wfc3 natural [k][j], prescaled, zero-pad j>=224

// ---------------- f32x2 helpers ----------------
#define FMA2(d, a, b) \
    asm("fma.rn.f32x2 %0, %1, %2, %0;" : "+l"(d) : "l"(a), "l"(b))
#define PACK2(d, lo, hi) \
    asm("mov.b64 %0, {%1, %2};" : "=l"(d) : "f"(lo), "f"(hi))
#define UNPACK2(lo, hi, s) \
    asm("mov.b64 {%0, %1}, %2;" : "=f"(lo), "=f"(hi) : "l"(s))

__device__ __forceinline__ float silu_f(float x) {
    return x / (1.0f + __expf(-x));
}

__device__ __forceinline__ void red4(float* p, float a, float b, float c, float d) {
    asm volatile("red.global.add.v4.f32 [%0], {%1,%2,%3,%4};"
                 :: "l"(p), "f"(a), "f"(b), "f"(c), "f"(d) : "memory");
}

// ---------------- 4x8 register-tiled GEMM on shared memory ----------------
// D[j][e] = (silu of) sum_k A[k][j] * B[k][e];  A stride 64, B/D stride 128.
// 256 threads: thread t -> jt = t&15 (rows j0=4*jt), et = t>>4 (cols e0=8*et).
template <int KLEN, bool DOSILU>
__device__ __forceinline__ void gemm4x8(const float* __restrict__ sAm,
                                        const float* __restrict__ sBm,
                                        float* __restrict__ sD, int t) {
    int jt = t & 15, et = t >> 4;
    const float* Ap = sAm + jt * 4;
    const float* Bp = sBm + et * 8;
    unsigned long long acc[16];
#pragma unroll
    for (int i = 0; i < 16; ++i) acc[i] = 0ull;
#pragma unroll 4
    for (int k = 0; k < KLEN; ++k) {
        float4 a0 = *reinterpret_cast<const float4*>(Ap + k * 64);
        ulonglong2 b01 = *reinterpret_cast<const ulonglong2*>(Bp + k * 128);
        ulonglong2 b23 = *reinterpret_cast<const ulonglong2*>(Bp + k * 128 + 4);
        unsigned long long ap;
        PACK2(ap, a0.x, a0.x);
        FMA2(acc[0],  ap, b01.x); FMA2(acc[1],  ap, b01.y);
        FMA2(acc[2],  ap, b23.x); FMA2(acc[3],  ap, b23.y);
        PACK2(ap, a0.y, a0.y);
        FMA2(acc[4],  ap, b01.x); FMA2(acc[5],  ap, b01.y);
        FMA2(acc[6],  ap, b23.x); FMA2(acc[7],  ap, b23.y);
        PACK2(ap, a0.z, a0.z);
        FMA2(acc[8],  ap, b01.x); FMA2(acc[9],  ap, b01.y);
        FMA2(acc[10], ap, b23.x); FMA2(acc[11], ap, b23.y);
        PACK2(ap, a0.w, a0.w);
        FMA2(acc[12], ap, b01.x); FMA2(acc[13], ap, b01.y);
        FMA2(acc[14], ap, b23.x); FMA2(acc[15], ap, b23.y);
    }
    float* D = sD + (size_t)(jt * 4) * 128 + et * 8;
#pragma unroll
    for (int j = 0; j < 4; ++j) {
#pragma unroll
        for (int i = 0; i < 4; ++i) {
            float lo, hi;
            UNPACK2(lo, hi, acc[j * 4 + i]);
            if (DOSILU) { lo = silu_f(lo); hi = silu_f(hi); }
            unsigned long long p;
            PACK2(p, lo, hi);
            *reinterpret_cast<unsigned long long*>(D + j * 128 + 2 * i) = p;
        }
    }
}

// ---------------- kernel 0: zero accumulators + prescale weights ------------
__global__ void k_pre(const float* __restrict__ Wfc1,
                      const float* __restrict__ Wfc2,
                      const float* __restrict__ Wfc3) {
    int i = blockIdx.x * 256 + threadIdx.x;
    const int NZ = NN * 120;   // float4 count of (ns + nv)
    if (i < NZ) {
        float4 z = make_float4(0.f, 0.f, 0.f, 0.f);
        if (i < NN * 24) d_g_ns[i] = z;
        else             d_g_nv[i - NN * 24] = z;
    } else {
        int j = i - NZ;
        if (j < 512) {
            d_W1K[j] = Wfc1[j] * 0.3535533906f;
        } else if (j < 4608) {
            d_W2K[j - 512] = Wfc2[j - 512] * 0.125f;
        } else if (j < 4608 + 16384) {
            int m = j - 4608;
            int k = m >> 8, col = m & 255;
            float v = 0.f;
            if (col < 224) {
                float s = 0.03125f;  // (1/sqrt(64)) * (1/sqrt(16))
                if (col >= 192)      s *= INV_SQRT2;
                else if (col >= 160) s *= INV_SQRT3;
                v = Wfc3[k * 224 + col] * s;
            }
            d_W3K[m] = v;
        }
    }
}

// ---------------- kernel 2: node prep, persistent warp-per-node -------------
__global__ void __launch_bounds__(256) k_prep(const float* __restrict__ nh,
                                              const float* __restrict__ W1_0,
                                              const float* __restrict__ W1_1,
                                              const float* __restrict__ Wsc0,
                                              const float* __restrict__ Wsc1) {
    __shared__ float sW10[4096], sWsc0[4096], sW11[1024], sWsc1[1024], sIn[1280];
    int t = threadIdx.x;
    for (int i = t; i < 4096; i += 256) { sW10[i] = W1_0[i]; sWsc0[i] = Wsc0[i]; }
    for (int i = t; i < 1024; i += 256) { sW11[i] = W1_1[i]; sWsc1[i] = Wsc1[i]; }
    __syncthreads();

    int wid = t >> 5, l = t & 31;
    float* gs  = (float*)d_g_s;
    float* gv  = (float*)d_g_v;
    float* gss = (float*)d_g_scs;
    float* gsv = (float*)d_g_scv;
    float* row = sIn + wid * 160;

    for (int it = 0; it < 8; ++it) {
        int n = blockIdx.x * 64 + it * 8 + wid;
        if (n >= NN) break;
        {
            const float4* src = reinterpret_cast<const float4*>(nh + (size_t)n * 160);
            float4* dst = reinterpret_cast<float4*>(row);
            for (int i = l; i < 40; i += 32) dst[i] = __ldg(src + i);
        }
        __syncwarp();
#pragma unroll
        for (int r = 0; r < 2; ++r) {
            int o = l + r * 32;
            float a = 0.f, b = 0.f;
#pragma unroll 8
            for (int u = 0; u < 64; ++u) {
                float x = row[u];
                a += x * sW10[u * 64 + o];
                b += x * sWsc0[u * 64 + o];
            }
            gs [(size_t)n * 64 + o] = a * 0.125f;
            gss[(size_t)n * 64 + o] = b * 0.125f;
        }
#pragma unroll
        for (int r = 0; r < 3; ++r) {
            int o = l + r * 32;
            int up = o / 3, c = o - up * 3;
            float a = 0.f, b = 0.f;
#pragma unroll 8
            for (int u = 0; u < 32; ++u) {
                float x = row[64 + u * 3 + c];
                a += x * sW11[u * 32 + up];
                b += x * sWsc1[u * 32 + up];
            }
            gv [(size_t)n * 96 + o] = a * 0.1767766953f;
            gsv[(size_t)n * 96 + o] = b * 0.1767766953f;
        }
        __syncwarp();
    }
}

// ---------------- kernel 3: edge MLP (GEMM pipeline) + messages + scatter ---
// 256 threads / 128 edges. smem arena (floats):
//   [0:4096)      A-region (attS+W1K -> W2K -> Wc)
//   [4096:12288)  B-region (h1s -> wc chunk outputs)
//   [12288:20480) h2s
// 20480 floats = 81920 B -> 2 blocks/SM, 16 warps/SM.
__global__ void __launch_bounds__(256) k_edge(const int* __restrict__ ei,
                                              const float* __restrict__ esh,
                                              const float* __restrict__ eattr) {
    extern __shared__ float sm[];
    float* sA  = sm;           // 4096
    float* sB  = sm + 4096;    // 8192
    float* sH2 = sm + 12288;   // 8192
    int t = threadIdx.x;
    int te = t & 127;          // edge lane
    int th = t >> 7;           // half index (0/1)
    int e = blockIdx.x * 128 + te;   // NE = 3125*128 exactly

    // ---- P0: stage att (transposed [k][e]) + W1K ----
    if (th == 0) {
        const float4* ap = reinterpret_cast<const float4*>(eattr + (size_t)e * 8);
        float4 a0 = __ldg(ap), a1 = __ldg(ap + 1);
        sA[0 * 128 + te] = a0.x; sA[1 * 128 + te] = a0.y;
        sA[2 * 128 + te] = a0.z; sA[3 * 128 + te] = a0.w;
        sA[4 * 128 + te] = a1.x; sA[5 * 128 + te] = a1.y;
        sA[6 * 128 + te] = a1.z; sA[7 * 128 + te] = a1.w;
    } else {
        for (int i = te; i < 512; i += 128) sA[1024 + i] = d_W1K[i];
    }
    __syncthreads();

    // ---- P1: h1s = silu(W1K @ attS) ----
    gemm4x8<8, true>(sA + 1024, sA, sB, t);
    __syncthreads();
    for (int i = t; i < 4096; i += 256) sA[i] = d_W2K[i];
    __syncthreads();

    // ---- P2: h2s = silu(W2K @ h1s) ----
    gemm4x8<64, true>(sA, sB, sH2, t);

    // ---- edge state (both halves load same edge data; LDG broadcasts) ----
    int src = __ldg(ei + e);
    int dst = __ldg(ei + NE + e);
    float4 sh = __ldg(reinterpret_cast<const float4*>(esh + (size_t)e * 4));
    const float4* sd4 = reinterpret_cast<const float4*>((const float*)d_g_s + (size_t)dst * 64);
    const float4* vd4 = reinterpret_cast<const float4*>((const float*)d_g_v + (size_t)dst * 96);
    float* nsp = (float*)d_g_ns + (size_t)src * 96;
    float* nvp = (float*)d_g_nv + (size_t)src * 384;
    __syncthreads();

    // ---- P3: 4 chunks of 64 w-rows: GEMM then consume (split by half) ----
#pragma unroll 1
    for (int c = 0; c < 4; ++c) {
        // load Wc[64][64] = d_W3K[:, 64c:64c+64]  (256 thr x 4 float4)
#pragma unroll
        for (int r = 0; r < 4; ++r) {
            int idx4 = t + 256 * r;
            int k = idx4 >> 4;
            int jj = (idx4 & 15) * 4;
            *reinterpret_cast<float4*>(sA + k * 64 + jj) =
                *reinterpret_cast<const float4*>(d_W3K + k * 256 + 64 * c + jj);
        }
        __syncthreads();
        gemm4x8<64, false>(sA, sH2, sB, t);
        __syncthreads();

        if (c == 0) {
            // w0: m0 -> ns[0:64]; halves take g=th*8..th*8+7
#pragma unroll 1
            for (int gg = 0; gg < 8; ++gg) {
                int g = th * 8 + gg;
                float4 s4 = __ldg(sd4 + g);
                float w0 = sB[(4 * g + 0) * 128 + te];
                float w1 = sB[(4 * g + 1) * 128 + te];
                float w2 = sB[(4 * g + 2) * 128 + te];
                float w3 = sB[(4 * g + 3) * 128 + te];
                red4(nsp + 4 * g, w0 * s4.x * sh.x, w1 * s4.y * sh.x,
                                  w2 * s4.z * sh.x, w3 * s4.w * sh.x);
            }
        } else if (c == 1) {
            // w1: mv0 -> nv[cc][0:64]
#pragma unroll 1
            for (int gg = 0; gg < 8; ++gg) {
                int g = th * 8 + gg;
                float4 s4 = __ldg(sd4 + g);
                float a = sB[(4 * g + 0) * 128 + te] * s4.x;
                float b = sB[(4 * g + 1) * 128 + te] * s4.y;
                float cc = sB[(4 * g + 2) * 128 + te] * s4.z;
                float d = sB[(4 * g + 3) * 128 + te] * s4.w;
                red4(nvp +       4 * g, a * sh.y, b * sh.y, cc * sh.y, d * sh.y);
                red4(nvp + 128 + 4 * g, a * sh.z, b * sh.z, cc * sh.z, d * sh.z);
                red4(nvp + 256 + 4 * g, a * sh.w, b * sh.w, cc * sh.w, d * sh.w);
            }
        } else if (c == 2) {
            // rows 0:32 = w2 (mv1), rows 32:64 = w3 (m1); halves g=th*4..th*4+3
#pragma unroll 1
            for (int gg = 0; gg < 4; ++gg) {
                int g = th * 4 + gg;
                const float4* vb = vd4 + g * 3;
                float4 b0 = __ldg(vb), b1 = __ldg(vb + 1), b2 = __ldg(vb + 2);
                float vv[12] = {b0.x, b0.y, b0.z, b0.w, b1.x, b1.y, b1.z, b1.w,
                                b2.x, b2.y, b2.z, b2.w};
                float m1[4], mv1[3][4];
#pragma unroll
                for (int i = 0; i < 4; ++i) {
                    int u = 4 * g + i;
                    float w2v = sB[u * 128 + te];
                    float w3v = sB[(32 + u) * 128 + te];
                    float vx = vv[i * 3], vy = vv[i * 3 + 1], vz = vv[i * 3 + 2];
                    mv1[0][i] = w2v * vx * sh.x;
                    mv1[1][i] = w2v * vy * sh.x;
                    mv1[2][i] = w2v * vz * sh.x;
                    m1[i] = w3v * (vx * sh.y + vy * sh.z + vz * sh.w);
                }
                red4(nsp + 64 + 4 * g, m1[0], m1[1], m1[2], m1[3]);
#pragma unroll
                for (int cc = 0; cc < 3; ++cc)
                    red4(nvp + cc * 128 + 64 + 4 * g,
                         mv1[cc][0], mv1[cc][1], mv1[cc][2], mv1[cc][3]);
            }
        } else {
            // rows 0:32 = w4 (mv2 cross product); rows 32:64 are zero-pad
#pragma unroll 1
            for (int gg = 0; gg < 4; ++gg) {
                int g = th * 4 + gg;
                const float4* vb = vd4 + g * 3;
                float4 b0 = __ldg(vb), b1 = __ldg(vb + 1), b2 = __ldg(vb + 2);
                float vv[12] = {b0.x, b0.y, b0.z, b0.w, b1.x, b1.y, b1.z, b1.w,
                                b2.x, b2.y, b2.z, b2.w};
                float mv2[3][4];
#pragma unroll
                for (int i = 0; i < 4; ++i) {
                    int u = 4 * g + i;
                    float w4v = sB[u * 128 + te];
                    float vx = vv[i * 3], vy = vv[i * 3 + 1], vz = vv[i * 3 + 2];
                    mv2[0][i] = w4v * (vy * sh.w - vz * sh.z);
                    mv2[1][i] = w4v * (vz * sh.y - vx * sh.w);
                    mv2[2][i] = w4v * (vx * sh.z - vy * sh.y);
                }
#pragma unroll
                for (int cc = 0; cc < 3; ++cc)
                    red4(nvp + cc * 128 + 96 + 4 * g,
                         mv2[cc][0], mv2[cc][1], mv2[cc][2], mv2[cc][3]);
            }
        }
        __syncthreads();
    }
}

// ---------------- kernel 4: output projection + skip + RMS (R5 version) ----
__global__ void __launch_bounds__(256) k_out(float* __restrict__ out,
                                             const float* __restrict__ W2_0,
                                             const float* __restrict__ W2_1,
                                             const float* __restrict__ g0,
                                             const float* __restrict__ g1) {
    extern __shared__ float smo[];
    float* sW20 = smo;           // 6144
    float* sW21 = smo + 6144;    // 4096
    float* sG   = smo + 10240;   // 96 (+32 pad)
    float* sAcc = smo + 10368;   // 8 * 480 = 3840  (total 14208 fl = 56832 B)
    int t = threadIdx.x;
    for (int i = t; i < 6144; i += 256) sW20[i] = W2_0[i];
    for (int i = t; i < 4096; i += 256) sW21[i] = W2_1[i];
    if (t < 64) sG[t] = g0[t];
    else if (t < 96) sG[t] = g1[t - 64];
    __syncthreads();

    const float* gns = (const float*)d_g_ns;
    const float* gnv = (const float*)d_g_nv;
    const float* gss = (const float*)d_g_scs;
    const float* gsv = (const float*)d_g_scv;

    int wid = t >> 5, l = t & 31;
    float* acc = sAcc + wid * 480;

    for (int it = 0; it < 8; ++it) {
        int n = blockIdx.x * 64 + it * 8 + wid;
        if (n >= NN) break;
        for (int i = l; i < 480; i += 32)
            acc[i] = (i < 96) ? gns[(size_t)n * 96 + i]
                              : gnv[(size_t)n * 384 + i - 96];
        __syncwarp();

        float vs[2], vv[3];
        float ssq_s = 0.f, ssq_v = 0.f;
#pragma unroll
        for (int r = 0; r < 2; ++r) {
            int o = l + r * 32;
            float a = 0.f;
#pragma unroll 8
            for (int k = 0; k < 96; ++k) a += acc[k] * sW20[k * 64 + o];
            float val = a * 0.1020620726f + gss[(size_t)n * 64 + o];
            vs[r] = val;
            ssq_s += val * val;
        }
#pragma unroll
        for (int r = 0; r < 3; ++r) {
            int o = l + r * 32;
            int up = o / 3, c = o - up * 3;
            float a = 0.f;
#pragma unroll 8
            for (int u = 0; u < 128; ++u) a += acc[96 + c * 128 + u] * sW21[u * 32 + up];
            float val = a * 0.0883883476f + gsv[(size_t)n * 96 + o];
            vv[r] = val;
            ssq_v += val * val;
        }
#pragma unroll
        for (int d = 16; d; d >>= 1) {
            ssq_s += __shfl_xor_sync(0xffffffffu, ssq_s, d);
            ssq_v += __shfl_xor_sync(0xffffffffu, ssq_v, d);
        }
        float rs = rsqrtf(ssq_s * (1.0f / 64.0f) + 1e-5f);
        float rv = rsqrtf(ssq_v * (1.0f / 32.0f) + 1e-5f);
#pragma unroll
        for (int r = 0; r < 2; ++r) {
            int o = l + r * 32;
            out[(size_t)n * 160 + o] = vs[r] * rs * sG[o];
        }
#pragma unroll
        for (int r = 0; r < 3; ++r) {
            int o = l + r * 32;
            out[(size_t)n * 160 + 64 + o] = vv[r] * rv * sG[64 + o / 3];
        }
        __syncwarp();
    }
}

// ---------------- launch ----------------
extern "C" void kernel_launch(void* const* d_in, const int* in_sizes, int n_in,
                              void* d_out, int out_size) {
    const float* nh    = (const float*)d_in[0];
    const int*   ei    = (const int*)  d_in[1];
    const float* esh   = (const float*)d_in[2];
    const float* eattr = (const float*)d_in[3];
    const float* W1_0  = (const float*)d_in[4];
    const float* W1_1  = (const float*)d_in[5];
    const float* Wfc1  = (const float*)d_in[6];
    const float* Wfc2  = (const float*)d_in[7];
    const float* Wfc3  = (const float*)d_in[8];
    const float* W2_0  = (const float*)d_in[9];
    const float* W2_1  = (const float*)d_in[10];
    const float* Wsc0  = (const float*)d_in[11];
    const float* Wsc1  = (const float*)d_in[12];
    const float* g0    = (const float*)d_in[13];
    const float* g1    = (const float*)d_in[14];
    float* out = (float*)d_out;

    cudaFuncSetAttribute(k_edge, cudaFuncAttributeMaxDynamicSharedMemorySize, 81920);
    cudaFuncSetAttribute(k_out, cudaFuncAttributeMaxDynamicSharedMemorySize, 57344);

    k_pre<<<11802, 256>>>(Wfc1, Wfc2, Wfc3);              // zero + prescale
    k_prep<<<391, 256>>>(nh, W1_0, W1_1, Wsc0, Wsc1);     // 64 nodes/block
    k_edge<<<3125, 256, 81920>>>(ei, esh, eattr);
    k_out<<<391, 256, 57344>>>(out, W2_0, W2_1, g0, g1);  // 64 nodes/block
}

// round 10
// speedup vs baseline: 1.3880x; 1.2725x over previous
#include <cuda_runtime.h>

#define NN 25000
#define NE 400000

#define INV_SQRT3 0.57735026919f
#define INV_SQRT2 0.70710678119f

// ---------------- scratch (device globals; allocation-free) ----------------
__device__ float4 d_g_s  [NN * 16];   // s   = s_in @ W1_0 /8           (N,64)
__device__ float4 d_g_v  [NN * 24];   // v   = v_in . W1_1 /sqrt32      (N,32,3) [u*3+c]
__device__ float4 d_g_scs[NN * 16];   // sc_s                           (N,64)
__device__ float4 d_g_scv[NN * 24];   // sc_v                           (N,96)  [u*3+c]
__device__ float4 d_g_ns [NN * 24];   // scatter accum s-part           (N,96)
__device__ float4 d_g_nv [NN * 96];   // scatter accum v-part           (N,3,128) [c][u]
__device__ float  d_W1T[64 * 8];      // Wfc1^T [k][m], prescaled 1/sqrt(8)
__device__ float  d_W2K[64 * 64];     // Wfc2 k-major [k][j], prescaled 1/8
__device__ float  d_W3T[224 * 64];    // Wfc3^T [j][k], prescaled WS (+INV_SQRT3/2)

// ---------------- f32x2 helpers ----------------
#define FMA2(d, a, b) \
    asm("fma.rn.f32x2 %0, %1, %2, %0;" : "+l"(d) : "l"(a), "l"(b))
#define ADD2(d, a, b) \
    asm("add.rn.f32x2 %0, %1, %2;" : "=l"(d) : "l"(a), "l"(b))
#define PACK2(d, lo, hi) \
    asm("mov.b64 %0, {%1, %2};" : "=l"(d) : "f"(lo), "f"(hi))
#define UNPACK2(lo, hi, s) \
    asm("mov.b64 {%0, %1}, %2;" : "=f"(lo), "=f"(hi) : "l"(s))

__device__ __forceinline__ float silu_f(float x) {
    return x / (1.0f + __expf(-x));
}

// dot of 64 floats: h packed as 32 f32x2 pairs, w = 16B-aligned smem row
__device__ __forceinline__ float dot64x2(const unsigned long long* h,
                                         const float* w) {
    unsigned long long a0 = 0ull, a1 = 0ull, a2 = 0ull, a3 = 0ull;
    const ulonglong2* q = reinterpret_cast<const ulonglong2*>(w);
#pragma unroll
    for (int k = 0; k < 8; ++k) {
        ulonglong2 w0 = q[2 * k];
        ulonglong2 w1 = q[2 * k + 1];
        FMA2(a0, h[4 * k + 0], w0.x);
        FMA2(a1, h[4 * k + 1], w0.y);
        FMA2(a2, h[4 * k + 2], w1.x);
        FMA2(a3, h[4 * k + 3], w1.y);
    }
    ADD2(a0, a0, a1);
    ADD2(a2, a2, a3);
    ADD2(a0, a0, a2);
    float lo, hi;
    UNPACK2(lo, hi, a0);
    return lo + hi;
}

__device__ __forceinline__ void red4(float* p, float a, float b, float c, float d) {
    asm volatile("red.global.add.v4.f32 [%0], {%1,%2,%3,%4};"
                 :: "l"(p), "f"(a), "f"(b), "f"(c), "f"(d) : "memory");
}

// ---------------- kernel 0: zero accumulators + transpose/prescale weights ---
__global__ void k_pre(const float* __restrict__ Wfc1,
                      const float* __restrict__ Wfc2,
                      const float* __restrict__ Wfc3) {
    int i = blockIdx.x * 256 + threadIdx.x;
    const int NZ = NN * 120;   // float4 count of (ns + nv)
    if (i < NZ) {
        float4 z = make_float4(0.f, 0.f, 0.f, 0.f);
        if (i < NN * 24) d_g_ns[i] = z;
        else             d_g_nv[i - NN * 24] = z;
    } else {
        int j = i - NZ;
        if (j < 512) {
            d_W1T[j] = Wfc1[(j & 7) * 64 + (j >> 3)] * 0.3535533906f;
        } else if (j < 512 + 4096) {
            int k = j - 512;
            d_W2K[k] = Wfc2[k] * 0.125f;     // already k-major
        } else if (j < 512 + 4096 + 14336) {
            int k = j - 4608;
            int row = k >> 6;
            float s = 0.03125f;  // (1/sqrt(64)) * (1/sqrt(16))
            if (row >= 192)      s *= INV_SQRT2;
            else if (row >= 160) s *= INV_SQRT3;
            d_W3T[k] = Wfc3[(k & 63) * 224 + row] * s;
        }
    }
}

// ---------------- kernel 2: node prep, persistent warp-per-node -------------
__global__ void __launch_bounds__(256) k_prep(const float* __restrict__ nh,
                                              const float* __restrict__ W1_0,
                                              const float* __restrict__ W1_1,
                                              const float* __restrict__ Wsc0,
                                              const float* __restrict__ Wsc1) {
    __shared__ float sW10[4096], sWsc0[4096], sW11[1024], sWsc1[1024], sIn[1280];
    int t = threadIdx.x;
    for (int i = t; i < 4096; i += 256) { sW10[i] = W1_0[i]; sWsc0[i] = Wsc0[i]; }
    for (int i = t; i < 1024; i += 256) { sW11[i] = W1_1[i]; sWsc1[i] = Wsc1[i]; }
    __syncthreads();

    int wid = t >> 5, l = t & 31;
    float* gs  = (float*)d_g_s;
    float* gv  = (float*)d_g_v;
    float* gss = (float*)d_g_scs;
    float* gsv = (float*)d_g_scv;
    float* row = sIn + wid * 160;

    for (int it = 0; it < 8; ++it) {
        int n = blockIdx.x * 64 + it * 8 + wid;
        if (n >= NN) break;
        {
            const float4* src = reinterpret_cast<const float4*>(nh + (size_t)n * 160);
            float4* dst = reinterpret_cast<float4*>(row);
            for (int i = l; i < 40; i += 32) dst[i] = __ldg(src + i);
        }
        __syncwarp();
#pragma unroll
        for (int r = 0; r < 2; ++r) {
            int o = l + r * 32;
            float a = 0.f, b = 0.f;
#pragma unroll 8
            for (int u = 0; u < 64; ++u) {
                float x = row[u];
                a += x * sW10[u * 64 + o];
                b += x * sWsc0[u * 64 + o];
            }
            gs [(size_t)n * 64 + o] = a * 0.125f;
            gss[(size_t)n * 64 + o] = b * 0.125f;
        }
#pragma unroll
        for (int r = 0; r < 3; ++r) {
            int o = l + r * 32;
            int up = o / 3, c = o - up * 3;
            float a = 0.f, b = 0.f;
#pragma unroll 8
            for (int u = 0; u < 32; ++u) {
                float x = row[64 + u * 3 + c];
                a += x * sW11[u * 32 + up];
                b += x * sWsc1[u * 32 + up];
            }
            gv [(size_t)n * 96 + o] = a * 0.1767766953f;
            gsv[(size_t)n * 96 + o] = b * 0.1767766953f;
        }
        __syncwarp();
    }
}

// ---------------- kernel 3: edge MLP + messages + scatter (R5 version) ------
// Phased smem: [sW2K | sW1] live only during the MLP phase, then the same
// region is overwritten with sW3 for the w-phase. 57344 B total.
__global__ void __launch_bounds__(128, 4) k_edge(const int* __restrict__ ei,
                                                 const float* __restrict__ esh,
                                                 const float* __restrict__ eattr) {
    extern __shared__ float sm[];
    float* sW2K = sm;          // 4096 floats  [k][j] (phase 1)
    float* sW1  = sm + 4096;   // 512 floats   [k][m] (phase 1)
    float* sW3  = sm;          // 14336 floats [j][k] (phase 2)
    int t = threadIdx.x;
    for (int i = t; i < 4096; i += 128) sW2K[i] = d_W2K[i];
    for (int i = t; i < 512;  i += 128) sW1[i]  = d_W1T[i];
    __syncthreads();

    int e = blockIdx.x * 128 + t;   // NE = 3125*128 exactly

    // ---- edge MLP, k-outer: h1[k] computed just-in-time, h1 never stored ----
    float att0, att1, att2, att3, att4, att5, att6, att7;
    {
        const float4* ap = reinterpret_cast<const float4*>(eattr + (size_t)e * 8);
        float4 a0 = __ldg(ap), a1 = __ldg(ap + 1);
        att0 = a0.x; att1 = a0.y; att2 = a0.z; att3 = a0.w;
        att4 = a1.x; att5 = a1.y; att6 = a1.z; att7 = a1.w;
    }
    unsigned long long h2p[32];
#pragma unroll
    for (int p = 0; p < 32; ++p) h2p[p] = 0ull;
#pragma unroll 4
    for (int k = 0; k < 64; ++k) {
        float4 q0 = *reinterpret_cast<const float4*>(sW1 + k * 8);
        float4 q1 = *reinterpret_cast<const float4*>(sW1 + k * 8 + 4);
        float a = att0 * q0.x + att1 * q0.y + att2 * q0.z + att3 * q0.w
                + att4 * q1.x + att5 * q1.y + att6 * q1.z + att7 * q1.w;
        float h = silu_f(a);
        unsigned long long hkk;
        PACK2(hkk, h, h);
        const ulonglong2* q = reinterpret_cast<const ulonglong2*>(sW2K + k * 64);
#pragma unroll
        for (int i = 0; i < 16; ++i) {
            ulonglong2 ww = q[i];
            FMA2(h2p[2 * i],     hkk, ww.x);
            FMA2(h2p[2 * i + 1], hkk, ww.y);
        }
    }
#pragma unroll
    for (int p = 0; p < 32; ++p) {
        float lo, hi;
        UNPACK2(lo, hi, h2p[p]);
        PACK2(h2p[p], silu_f(lo), silu_f(hi));
    }

    __syncthreads();   // done reading sW1/sW2K
    for (int i = t; i < 14336; i += 128) sW3[i] = d_W3T[i];
    __syncthreads();

    int src = __ldg(ei + e);
    int dst = __ldg(ei + NE + e);
    float4 sh = __ldg(reinterpret_cast<const float4*>(esh + (size_t)e * 4));
    float sh0 = sh.x, shx = sh.y, shy = sh.z, shz = sh.w;

    const float* sd  = (const float*)d_g_s + (size_t)dst * 64;
    const float* vd  = (const float*)d_g_v + (size_t)dst * 96;
    float*       nsp = (float*)d_g_ns + (size_t)src * 96;
    float*       nvp = (float*)d_g_nv + (size_t)src * 384;

    // ---- m0 (ns[0:64]) and mv0 (nv[c][0:64]) ----
#pragma unroll 1
    for (int g = 0; g < 16; ++g) {
        float4 s4 = __ldg(reinterpret_cast<const float4*>(sd) + g);
        float sdl[4]  = {s4.x, s4.y, s4.z, s4.w};
        float sdl0[4] = {s4.x * sh0, s4.y * sh0, s4.z * sh0, s4.w * sh0};
        float m0[4], w1s[4];
#pragma unroll
        for (int i = 0; i < 4; ++i) {
            int j = g * 4 + i;
            float w0 = dot64x2(h2p, sW3 + j * 64);
            float w1 = dot64x2(h2p, sW3 + (64 + j) * 64);
            m0[i]  = w0 * sdl0[i];
            w1s[i] = w1 * sdl[i];
        }
        red4(nsp + g * 4, m0[0], m0[1], m0[2], m0[3]);
        red4(nvp +       g * 4, w1s[0] * shx, w1s[1] * shx, w1s[2] * shx, w1s[3] * shx);
        red4(nvp + 128 + g * 4, w1s[0] * shy, w1s[1] * shy, w1s[2] * shy, w1s[3] * shy);
        red4(nvp + 256 + g * 4, w1s[0] * shz, w1s[1] * shz, w1s[2] * shz, w1s[3] * shz);
    }

    // ---- m1 (ns[64:96]), mv1 (nv[c][64:96]), mv2 (nv[c][96:128]) ----
#pragma unroll 1
    for (int g = 0; g < 8; ++g) {
        const float4* vb = reinterpret_cast<const float4*>(vd + g * 12);
        float4 b0 = __ldg(vb), b1 = __ldg(vb + 1), b2 = __ldg(vb + 2);
        float vv[12] = {b0.x, b0.y, b0.z, b0.w, b1.x, b1.y, b1.z, b1.w,
                        b2.x, b2.y, b2.z, b2.w};
        float m1[4], mv1[3][4], mv2[3][4];
#pragma unroll
        for (int i = 0; i < 4; ++i) {
            int u = g * 4 + i;
            float w2 = dot64x2(h2p, sW3 + (128 + u) * 64);
            float w3 = dot64x2(h2p, sW3 + (160 + u) * 64);  // incl INV_SQRT3
            float w4 = dot64x2(h2p, sW3 + (192 + u) * 64);  // incl INV_SQRT2
            float vx = vv[i * 3], vy = vv[i * 3 + 1], vz = vv[i * 3 + 2];
            m1[i] = w3 * (vx * shx + vy * shy + vz * shz);
            mv1[0][i] = w2 * vx * sh0;
            mv1[1][i] = w2 * vy * sh0;
            mv1[2][i] = w2 * vz * sh0;
            mv2[0][i] = w4 * (vy * shz - vz * shy);
            mv2[1][i] = w4 * (vz * shx - vx * shz);
            mv2[2][i] = w4 * (vx * shy - vy * shx);
        }
        red4(nsp + 64 + g * 4, m1[0], m1[1], m1[2], m1[3]);
#pragma unroll
        for (int c = 0; c < 3; ++c) {
            red4(nvp + c * 128 + 64 + g * 4, mv1[c][0], mv1[c][1], mv1[c][2], mv1[c][3]);
            red4(nvp + c * 128 + 96 + g * 4, mv2[c][0], mv2[c][1], mv2[c][2], mv2[c][3]);
        }
    }
}

// ---------------- kernel 4: output projection + skip + RMS, 4 nodes/warp ----
// Warp handles 4 nodes; acc staged per-warp in stride-5 smem (conflict-free
// STS, scalar broadcast reads). Weight LDS slots shared across the 4 nodes.
// smem: 6144 + 4096 + 128 + 8*640 = 15488 floats = 61952 B -> 3 blocks/SM.
__global__ void __launch_bounds__(256) k_out(float* __restrict__ out,
                                             const float* __restrict__ W2_0,
                                             const float* __restrict__ W2_1,
                                             const float* __restrict__ g0,
                                             const float* __restrict__ g1) {
    extern __shared__ float smo[];
    float* sW20 = smo;           // 6144  [k][o], natural layout
    float* sW21 = smo + 6144;    // 4096  [u][u'], natural layout
    float* sG   = smo + 10240;   // 96 (+32 pad)
    float* sBuf = smo + 10368;   // 8 warps * 640
    int t = threadIdx.x;
    for (int i = t; i < 6144; i += 256) sW20[i] = W2_0[i];
    for (int i = t; i < 4096; i += 256) sW21[i] = W2_1[i];
    if (t < 64) sG[t] = g0[t];
    else if (t < 96) sG[t] = g1[t - 64];
    __syncthreads();

    const float* gnsF = (const float*)d_g_ns;
    const float* gnvF = (const float*)d_g_nv;
    const float* gssF = (const float*)d_g_scs;
    const float* gsvF = (const float*)d_g_scv;

    int wid = t >> 5, l = t & 31;
    float* buf = sBuf + wid * 640;     // buf[k*5 + j]

    for (int it = 0; it < 2; ++it) {
        int nb = blockIdx.x * 64 + it * 32 + wid * 4;

        // ======== s section: out_s[o] = sum_k ns[k] * W20[k][o] ========
#pragma unroll
        for (int j = 0; j < 4; ++j) {
            int nj = min(nb + j, NN - 1);
#pragma unroll
            for (int m = 0; m < 3; ++m) {
                int k = l + 32 * m;
                buf[k * 5 + j] = __ldg(gnsF + (size_t)nj * 96 + k);
            }
        }
        __syncwarp();

        float as0[4] = {0.f, 0.f, 0.f, 0.f};
        float as1[4] = {0.f, 0.f, 0.f, 0.f};
#pragma unroll 4
        for (int k = 0; k < 96; ++k) {
            float w0 = sW20[k * 64 + l];
            float w1 = sW20[k * 64 + l + 32];
            float a0 = buf[k * 5 + 0], a1 = buf[k * 5 + 1];
            float a2 = buf[k * 5 + 2], a3 = buf[k * 5 + 3];
            as0[0] += a0 * w0; as0[1] += a1 * w0; as0[2] += a2 * w0; as0[3] += a3 * w0;
            as1[0] += a0 * w1; as1[1] += a1 * w1; as1[2] += a2 * w1; as1[3] += a3 * w1;
        }
        __syncwarp();

        float vs0[4], vs1[4], ssq_s[4];
#pragma unroll
        for (int j = 0; j < 4; ++j) {
            int nj = min(nb + j, NN - 1);
            float v0 = as0[j] * 0.1020620726f + __ldg(gssF + (size_t)nj * 64 + l);
            float v1 = as1[j] * 0.1020620726f + __ldg(gssF + (size_t)nj * 64 + l + 32);
            vs0[j] = v0; vs1[j] = v1;
            ssq_s[j] = v0 * v0 + v1 * v1;
        }

        // ======== v sections: lane l = output column u', section c ========
        float vvs[3][4];
        float ssq_v[4] = {0.f, 0.f, 0.f, 0.f};
#pragma unroll 1
        for (int c = 0; c < 3; ++c) {
#pragma unroll
            for (int j = 0; j < 4; ++j) {
                int nj = min(nb + j, NN - 1);
#pragma unroll
                for (int m = 0; m < 4; ++m) {
                    int u = l + 32 * m;
                    buf[u * 5 + j] = __ldg(gnvF + (size_t)nj * 384 + c * 128 + u);
                }
            }
            __syncwarp();

            float av[4] = {0.f, 0.f, 0.f, 0.f};
#pragma unroll 4
            for (int u = 0; u < 128; ++u) {
                float w = sW21[u * 32 + l];
                av[0] += buf[u * 5 + 0] * w;
                av[1] += buf[u * 5 + 1] * w;
                av[2] += buf[u * 5 + 2] * w;
                av[3] += buf[u * 5 + 3] * w;
            }
            __syncwarp();

            int o = l * 3 + c;    // output channel in [0,96)
#pragma unroll
            for (int j = 0; j < 4; ++j) {
                int nj = min(nb + j, NN - 1);
                float val = av[j] * 0.0883883476f + __ldg(gsvF + (size_t)nj * 96 + o);
                vvs[c][j] = val;
                ssq_v[j] += val * val;
            }
        }

        // ======== warp reductions + writes ========
#pragma unroll
        for (int d = 16; d; d >>= 1) {
#pragma unroll
            for (int j = 0; j < 4; ++j) {
                ssq_s[j] += __shfl_xor_sync(0xffffffffu, ssq_s[j], d);
                ssq_v[j] += __shfl_xor_sync(0xffffffffu, ssq_v[j], d);
            }
        }
#pragma unroll
        for (int j = 0; j < 4; ++j) {
            int n = nb + j;
            if (n < NN) {
                float rs = rsqrtf(ssq_s[j] * (1.0f / 64.0f) + 1e-5f);
                float rv = rsqrtf(ssq_v[j] * (1.0f / 32.0f) + 1e-5f);
                out[(size_t)n * 160 + l]      = vs0[j] * rs * sG[l];
                out[(size_t)n * 160 + l + 32] = vs1[j] * rs * sG[l + 32];
                float gv = rv * sG[64 + l];
#pragma unroll
                for (int c = 0; c < 3; ++c)
                    out[(size_t)n * 160 + 64 + l * 3 + c] = vvs[c][j] * gv;
            }
        }
        __syncwarp();
    }
}

// ---------------- launch ----------------
extern "C" void kernel_launch(void* const* d_in, const int* in_sizes, int n_in,
                              void* d_out, int out_size) {
    const float* nh    = (const float*)d_in[0];
    const int*   ei    = (const int*)  d_in[1];
    const float* esh   = (const float*)d_in[2];
    const float* eattr = (const float*)d_in[3];
    const float* W1_0  = (const float*)d_in[4];
    const float* W1_1  = (const float*)d_in[5];
    const float* Wfc1  = (const float*)d_in[6];
    const float* Wfc2  = (const float*)d_in[7];
    const float* Wfc3  = (const float*)d_in[8];
    const float* W2_0  = (const float*)d_in[9];
    const float* W2_1  = (const float*)d_in[10];
    const float* Wsc0  = (const float*)d_in[11];
    const float* Wsc1  = (const float*)d_in[12];
    const float* g0    = (const float*)d_in[13];
    const float* g1    = (const float*)d_in[14];
    float* out = (float*)d_out;

    cudaFuncSetAttribute(k_edge, cudaFuncAttributeMaxDynamicSharedMemorySize, 57344);
    cudaFuncSetAttribute(k_out, cudaFuncAttributeMaxDynamicSharedMemorySize, 61952);

    k_pre<<<11793, 256>>>(Wfc1, Wfc2, Wfc3);              // zero + transpose
    k_prep<<<391, 256>>>(nh, W1_0, W1_1, Wsc0, Wsc1);     // 64 nodes/block
    k_edge<<<3125, 128, 57344>>>(ei, esh, eattr);
    k_out<<<391, 256, 61952>>>(out, W2_0, W2_1, g0, g1);  // 64 nodes/block
}

// round 11
// speedup vs baseline: 1.5959x; 1.1498x over previous
#include <cuda_runtime.h>

#define NN 25000
#define NE 400000

#define INV_SQRT3 0.57735026919f
#define INV_SQRT2 0.70710678119f

// ---------------- scratch (device globals; allocation-free) ----------------
__device__ float4 d_g_s  [NN * 16];   // s   = s_in @ W1_0 /8           (N,64)
__device__ float4 d_g_v  [NN * 24];   // v   = v_in . W1_1 /sqrt32      (N,32,3) [u*3+c]
__device__ float4 d_g_scs[NN * 16];   // sc_s                           (N,64)
__device__ float4 d_g_scv[NN * 24];   // sc_v                           (N,96)  [u*3+c]
__device__ float4 d_g_ns [NN * 24];   // scatter accum s-part           (N,96)
__device__ float4 d_g_nv [NN * 96];   // scatter accum v-part           (N,3,128) [c][u]
__device__ float  d_W1T[64 * 8];      // Wfc1^T [k][m], prescaled 1/sqrt(8)
__device__ float  d_W2K[64 * 64];     // Wfc2 k-major [k][j], prescaled 1/8
__device__ float  d_W3T[224 * 64];    // Wfc3^T [j][k], prescaled WS (+INV_SQRT3/2)

// ---------------- f32x2 helpers ----------------
#define FMA2(d, a, b) \
    asm("fma.rn.f32x2 %0, %1, %2, %0;" : "+l"(d) : "l"(a), "l"(b))
#define ADD2(d, a, b) \
    asm("add.rn.f32x2 %0, %1, %2;" : "=l"(d) : "l"(a), "l"(b))
#define PACK2(d, lo, hi) \
    asm("mov.b64 %0, {%1, %2};" : "=l"(d) : "f"(lo), "f"(hi))
#define UNPACK2(lo, hi, s) \
    asm("mov.b64 {%0, %1}, %2;" : "=f"(lo), "=f"(hi) : "l"(s))

__device__ __forceinline__ float silu_f(float x) {
    return x / (1.0f + __expf(-x));
}

// dual-edge dot of 64: one weight load feeds both edges (halves LDS traffic)
__device__ __forceinline__ void dot64x2_dual(const unsigned long long* hA,
                                             const unsigned long long* hB,
                                             const float* w,
                                             float& ra, float& rb) {
    unsigned long long a0 = 0ull, a1 = 0ull, b0 = 0ull, b1 = 0ull;
    const ulonglong2* q = reinterpret_cast<const ulonglong2*>(w);
#pragma unroll
    for (int k = 0; k < 16; ++k) {
        ulonglong2 ww = q[k];
        FMA2(a0, hA[2 * k + 0], ww.x);
        FMA2(a1, hA[2 * k + 1], ww.y);
        FMA2(b0, hB[2 * k + 0], ww.x);
        FMA2(b1, hB[2 * k + 1], ww.y);
    }
    ADD2(a0, a0, a1);
    ADD2(b0, b0, b1);
    float lo, hi;
    UNPACK2(lo, hi, a0); ra = lo + hi;
    UNPACK2(lo, hi, b0); rb = lo + hi;
}

__device__ __forceinline__ void red4(float* p, float a, float b, float c, float d) {
    asm volatile("red.global.add.v4.f32 [%0], {%1,%2,%3,%4};"
                 :: "l"(p), "f"(a), "f"(b), "f"(c), "f"(d) : "memory");
}

// ---------------- kernel 0: zero accumulators + transpose/prescale weights ---
__global__ void k_pre(const float* __restrict__ Wfc1,
                      const float* __restrict__ Wfc2,
                      const float* __restrict__ Wfc3) {
    int i = blockIdx.x * 256 + threadIdx.x;
    const int NZ = NN * 120;   // float4 count of (ns + nv)
    if (i < NZ) {
        float4 z = make_float4(0.f, 0.f, 0.f, 0.f);
        if (i < NN * 24) d_g_ns[i] = z;
        else             d_g_nv[i - NN * 24] = z;
    } else {
        int j = i - NZ;
        if (j < 512) {
            d_W1T[j] = Wfc1[(j & 7) * 64 + (j >> 3)] * 0.3535533906f;
        } else if (j < 512 + 4096) {
            int k = j - 512;
            d_W2K[k] = Wfc2[k] * 0.125f;     // already k-major
        } else if (j < 512 + 4096 + 14336) {
            int k = j - 4608;
            int row = k >> 6;
            float s = 0.03125f;  // (1/sqrt(64)) * (1/sqrt(16))
            if (row >= 192)      s *= INV_SQRT2;
            else if (row >= 160) s *= INV_SQRT3;
            d_W3T[k] = Wfc3[(k & 63) * 224 + row] * s;
        }
    }
}

// ---------------- kernel 2: node prep, persistent warp-per-node -------------
__global__ void __launch_bounds__(256) k_prep(const float* __restrict__ nh,
                                              const float* __restrict__ W1_0,
                                              const float* __restrict__ W1_1,
                                              const float* __restrict__ Wsc0,
                                              const float* __restrict__ Wsc1) {
    __shared__ float sW10[4096], sWsc0[4096], sW11[1024], sWsc1[1024], sIn[1280];
    int t = threadIdx.x;
    for (int i = t; i < 4096; i += 256) { sW10[i] = W1_0[i]; sWsc0[i] = Wsc0[i]; }
    for (int i = t; i < 1024; i += 256) { sW11[i] = W1_1[i]; sWsc1[i] = Wsc1[i]; }
    __syncthreads();

    int wid = t >> 5, l = t & 31;
    float* gs  = (float*)d_g_s;
    float* gv  = (float*)d_g_v;
    float* gss = (float*)d_g_scs;
    float* gsv = (float*)d_g_scv;
    float* row = sIn + wid * 160;

    for (int it = 0; it < 8; ++it) {
        int n = blockIdx.x * 64 + it * 8 + wid;
        if (n >= NN) break;
        {
            const float4* src = reinterpret_cast<const float4*>(nh + (size_t)n * 160);
            float4* dst = reinterpret_cast<float4*>(row);
            for (int i = l; i < 40; i += 32) dst[i] = __ldg(src + i);
        }
        __syncwarp();
#pragma unroll
        for (int r = 0; r < 2; ++r) {
            int o = l + r * 32;
            float a = 0.f, b = 0.f;
#pragma unroll 8
            for (int u = 0; u < 64; ++u) {
                float x = row[u];
                a += x * sW10[u * 64 + o];
                b += x * sWsc0[u * 64 + o];
            }
            gs [(size_t)n * 64 + o] = a * 0.125f;
            gss[(size_t)n * 64 + o] = b * 0.125f;
        }
#pragma unroll
        for (int r = 0; r < 3; ++r) {
            int o = l + r * 32;
            int up = o / 3, c = o - up * 3;
            float a = 0.f, b = 0.f;
#pragma unroll 8
            for (int u = 0; u < 32; ++u) {
                float x = row[64 + u * 3 + c];
                a += x * sW11[u * 32 + up];
                b += x * sWsc1[u * 32 + up];
            }
            gv [(size_t)n * 96 + o] = a * 0.1767766953f;
            gsv[(size_t)n * 96 + o] = b * 0.1767766953f;
        }
        __syncwarp();
    }
}

// ---------------- kernel 3: dual-edge MLP + messages + scatter --------------
// 2 edges/thread. k-outer MLP (h1 never materialized) keeps regs ~210.
// Phased smem: [sW2K | sW1] then sW3 overwrites. 57344 B, 2 blocks/SM.
__global__ void __launch_bounds__(128, 2) k_edge(const int* __restrict__ ei,
                                                 const float* __restrict__ esh,
                                                 const float* __restrict__ eattr) {
    extern __shared__ float sm[];
    float* sW2K = sm;          // 4096 floats  [k][j] (phase 1)
    float* sW1  = sm + 4096;   // 512 floats   [k][m] (phase 1)
    float* sW3  = sm;          // 14336 floats [j][k] (phase 2)
    int t = threadIdx.x;
    for (int i = t; i < 4096; i += 128) sW2K[i] = d_W2K[i];
    for (int i = t; i < 512;  i += 128) sW1[i]  = d_W1T[i];
    __syncthreads();

    int eA = blockIdx.x * 256 + t;     // < NE always (1563*256-129 < NE)
    int eB = eA + 128;
    bool hasB = (eB < NE);
    int eBc = hasB ? eB : eA;

    // ---- dual k-outer MLP: one sW1/sW2K row load feeds both edges ----
    float aA0, aA1, aA2, aA3, aA4, aA5, aA6, aA7;
    float aB0, aB1, aB2, aB3, aB4, aB5, aB6, aB7;
    {
        const float4* ap = reinterpret_cast<const float4*>(eattr + (size_t)eA * 8);
        float4 x0 = __ldg(ap), x1 = __ldg(ap + 1);
        aA0 = x0.x; aA1 = x0.y; aA2 = x0.z; aA3 = x0.w;
        aA4 = x1.x; aA5 = x1.y; aA6 = x1.z; aA7 = x1.w;
        const float4* bp = reinterpret_cast<const float4*>(eattr + (size_t)eBc * 8);
        float4 y0 = __ldg(bp), y1 = __ldg(bp + 1);
        aB0 = y0.x; aB1 = y0.y; aB2 = y0.z; aB3 = y0.w;
        aB4 = y1.x; aB5 = y1.y; aB6 = y1.z; aB7 = y1.w;
    }
    unsigned long long h2pA[32], h2pB[32];
#pragma unroll
    for (int p = 0; p < 32; ++p) { h2pA[p] = 0ull; h2pB[p] = 0ull; }
#pragma unroll 2
    for (int k = 0; k < 64; ++k) {
        float4 q0 = *reinterpret_cast<const float4*>(sW1 + k * 8);
        float4 q1 = *reinterpret_cast<const float4*>(sW1 + k * 8 + 4);
        float sa = aA0 * q0.x + aA1 * q0.y + aA2 * q0.z + aA3 * q0.w
                 + aA4 * q1.x + aA5 * q1.y + aA6 * q1.z + aA7 * q1.w;
        float sb = aB0 * q0.x + aB1 * q0.y + aB2 * q0.z + aB3 * q0.w
                 + aB4 * q1.x + aB5 * q1.y + aB6 * q1.z + aB7 * q1.w;
        float hA = silu_f(sa);
        float hB = silu_f(sb);
        unsigned long long hkA, hkB;
        PACK2(hkA, hA, hA);
        PACK2(hkB, hB, hB);
        const ulonglong2* q = reinterpret_cast<const ulonglong2*>(sW2K + k * 64);
#pragma unroll
        for (int i = 0; i < 16; ++i) {
            ulonglong2 ww = q[i];
            FMA2(h2pA[2 * i],     hkA, ww.x);
            FMA2(h2pA[2 * i + 1], hkA, ww.y);
            FMA2(h2pB[2 * i],     hkB, ww.x);
            FMA2(h2pB[2 * i + 1], hkB, ww.y);
        }
    }
#pragma unroll
    for (int p = 0; p < 32; ++p) {
        float lo, hi;
        UNPACK2(lo, hi, h2pA[p]);
        PACK2(h2pA[p], silu_f(lo), silu_f(hi));
        UNPACK2(lo, hi, h2pB[p]);
        PACK2(h2pB[p], silu_f(lo), silu_f(hi));
    }

    __syncthreads();   // done reading sW1/sW2K
    for (int i = t; i < 14336; i += 128) sW3[i] = d_W3T[i];
    __syncthreads();

    int srcA = __ldg(ei + eA),  dstA = __ldg(ei + NE + eA);
    int srcB = __ldg(ei + eBc), dstB = __ldg(ei + NE + eBc);
    float4 shA = __ldg(reinterpret_cast<const float4*>(esh + (size_t)eA * 4));
    float4 shB = __ldg(reinterpret_cast<const float4*>(esh + (size_t)eBc * 4));

    const float* sdA = (const float*)d_g_s + (size_t)dstA * 64;
    const float* sdB = (const float*)d_g_s + (size_t)dstB * 64;
    const float* vdA = (const float*)d_g_v + (size_t)dstA * 96;
    const float* vdB = (const float*)d_g_v + (size_t)dstB * 96;
    float* nspA = (float*)d_g_ns + (size_t)srcA * 96;
    float* nspB = (float*)d_g_ns + (size_t)srcB * 96;
    float* nvpA = (float*)d_g_nv + (size_t)srcA * 384;
    float* nvpB = (float*)d_g_nv + (size_t)srcB * 384;

    // ---- m0 (ns[0:64]) and mv0 (nv[c][0:64]) ----
#pragma unroll 1
    for (int g = 0; g < 16; ++g) {
        float4 s4A = __ldg(reinterpret_cast<const float4*>(sdA) + g);
        float4 s4B = __ldg(reinterpret_cast<const float4*>(sdB) + g);
        float sA[4] = {s4A.x, s4A.y, s4A.z, s4A.w};
        float sB[4] = {s4B.x, s4B.y, s4B.z, s4B.w};
        float m0A[4], w1A[4], m0B[4], w1B[4];
#pragma unroll
        for (int i = 0; i < 4; ++i) {
            int j = g * 4 + i;
            float w0a, w0b, w1a, w1b;
            dot64x2_dual(h2pA, h2pB, sW3 + j * 64,        w0a, w0b);
            dot64x2_dual(h2pA, h2pB, sW3 + (64 + j) * 64, w1a, w1b);
            m0A[i] = w0a * sA[i] * shA.x;
            m0B[i] = w0b * sB[i] * shB.x;
            w1A[i] = w1a * sA[i];
            w1B[i] = w1b * sB[i];
        }
        red4(nspA + g * 4, m0A[0], m0A[1], m0A[2], m0A[3]);
        red4(nvpA +       g * 4, w1A[0] * shA.y, w1A[1] * shA.y, w1A[2] * shA.y, w1A[3] * shA.y);
        red4(nvpA + 128 + g * 4, w1A[0] * shA.z, w1A[1] * shA.z, w1A[2] * shA.z, w1A[3] * shA.z);
        red4(nvpA + 256 + g * 4, w1A[0] * shA.w, w1A[1] * shA.w, w1A[2] * shA.w, w1A[3] * shA.w);
        if (hasB) {
            red4(nspB + g * 4, m0B[0], m0B[1], m0B[2], m0B[3]);
            red4(nvpB +       g * 4, w1B[0] * shB.y, w1B[1] * shB.y, w1B[2] * shB.y, w1B[3] * shB.y);
            red4(nvpB + 128 + g * 4, w1B[0] * shB.z, w1B[1] * shB.z, w1B[2] * shB.z, w1B[3] * shB.z);
            red4(nvpB + 256 + g * 4, w1B[0] * shB.w, w1B[1] * shB.w, w1B[2] * shB.w, w1B[3] * shB.w);
        }
    }

    // ---- m1 (ns[64:96]), mv1 (nv[c][64:96]), mv2 (nv[c][96:128]) ----
#pragma unroll 1
    for (int g = 0; g < 8; ++g) {
        const float4* vbA = reinterpret_cast<const float4*>(vdA + g * 12);
        const float4* vbB = reinterpret_cast<const float4*>(vdB + g * 12);
        float4 x0 = __ldg(vbA), x1 = __ldg(vbA + 1), x2 = __ldg(vbA + 2);
        float4 y0 = __ldg(vbB), y1 = __ldg(vbB + 1), y2 = __ldg(vbB + 2);
        float vvA[12] = {x0.x, x0.y, x0.z, x0.w, x1.x, x1.y, x1.z, x1.w,
                         x2.x, x2.y, x2.z, x2.w};
        float vvB[12] = {y0.x, y0.y, y0.z, y0.w, y1.x, y1.y, y1.z, y1.w,
                         y2.x, y2.y, y2.z, y2.w};
        float m1A[4], mv1A[3][4], mv2A[3][4];
        float m1B[4], mv1B[3][4], mv2B[3][4];
#pragma unroll
        for (int i = 0; i < 4; ++i) {
            int u = g * 4 + i;
            float w2a, w2b, w3a, w3b, w4a, w4b;
            dot64x2_dual(h2pA, h2pB, sW3 + (128 + u) * 64, w2a, w2b);
            dot64x2_dual(h2pA, h2pB, sW3 + (160 + u) * 64, w3a, w3b);  // incl INV_SQRT3
            dot64x2_dual(h2pA, h2pB, sW3 + (192 + u) * 64, w4a, w4b);  // incl INV_SQRT2
            {
                float vx = vvA[i * 3], vy = vvA[i * 3 + 1], vz = vvA[i * 3 + 2];
                m1A[i] = w3a * (vx * shA.y + vy * shA.z + vz * shA.w);
                mv1A[0][i] = w2a * vx * shA.x;
                mv1A[1][i] = w2a * vy * shA.x;
                mv1A[2][i] = w2a * vz * shA.x;
                mv2A[0][i] = w4a * (vy * shA.w - vz * shA.z);
                mv2A[1][i] = w4a * (vz * shA.y - vx * shA.w);
                mv2A[2][i] = w4a * (vx * shA.z - vy * shA.y);
            }
            {
                float vx = vvB[i * 3], vy = vvB[i * 3 + 1], vz = vvB[i * 3 + 2];
                m1B[i] = w3b * (vx * shB.y + vy * shB.z + vz * shB.w);
                mv1B[0][i] = w2b * vx * shB.x;
                mv1B[1][i] = w2b * vy * shB.x;
                mv1B[2][i] = w2b * vz * shB.x;
                mv2B[0][i] = w4b * (vy * shB.w - vz * shB.z);
                mv2B[1][i] = w4b * (vz * shB.y - vx * shB.w);
                mv2B[2][i] = w4b * (vx * shB.z - vy * shB.y);
            }
        }
        red4(nspA + 64 + g * 4, m1A[0], m1A[1], m1A[2], m1A[3]);
#pragma unroll
        for (int c = 0; c < 3; ++c) {
            red4(nvpA + c * 128 + 64 + g * 4, mv1A[c][0], mv1A[c][1], mv1A[c][2], mv1A[c][3]);
            red4(nvpA + c * 128 + 96 + g * 4, mv2A[c][0], mv2A[c][1], mv2A[c][2], mv2A[c][3]);
        }
        if (hasB) {
            red4(nspB + 64 + g * 4, m1B[0], m1B[1], m1B[2], m1B[3]);
#pragma unroll
            for (int c = 0; c < 3; ++c) {
                red4(nvpB + c * 128 + 64 + g * 4, mv1B[c][0], mv1B[c][1], mv1B[c][2], mv1B[c][3]);
                red4(nvpB + c * 128 + 96 + g * 4, mv2B[c][0], mv2B[c][1], mv2B[c][2], mv2B[c][3]);
            }
        }
    }
}

// ---------------- kernel 4: output projection + skip + RMS, 4 nodes/warp ----
// (unchanged from R10 — proven 64us)
__global__ void __launch_bounds__(256) k_out(float* __restrict__ out,
                                             const float* __restrict__ W2_0,
                                             const float* __restrict__ W2_1,
                                             const float* __restrict__ g0,
                                             const float* __restrict__ g1) {
    extern __shared__ float smo[];
    float* sW20 = smo;           // 6144  [k][o], natural layout
    float* sW21 = smo + 6144;    // 4096  [u][u'], natural layout
    float* sG   = smo + 10240;   // 96 (+32 pad)
    float* sBuf = smo + 10368;   // 8 warps * 640
    int t = threadIdx.x;
    for (int i = t; i < 6144; i += 256) sW20[i] = W2_0[i];
    for (int i = t; i < 4096; i += 256) sW21[i] = W2_1[i];
    if (t < 64) sG[t] = g0[t];
    else if (t < 96) sG[t] = g1[t - 64];
    __syncthreads();

    const float* gnsF = (const float*)d_g_ns;
    const float* gnvF = (const float*)d_g_nv;
    const float* gssF = (const float*)d_g_scs;
    const float* gsvF = (const float*)d_g_scv;

    int wid = t >> 5, l = t & 31;
    float* buf = sBuf + wid * 640;     // buf[k*5 + j]

    for (int it = 0; it < 2; ++it) {
        int nb = blockIdx.x * 64 + it * 32 + wid * 4;

        // ======== s section ========
#pragma unroll
        for (int j = 0; j < 4; ++j) {
            int nj = min(nb + j, NN - 1);
#pragma unroll
            for (int m = 0; m < 3; ++m) {
                int k = l + 32 * m;
                buf[k * 5 + j] = __ldg(gnsF + (size_t)nj * 96 + k);
            }
        }
        __syncwarp();

        float as0[4] = {0.f, 0.f, 0.f, 0.f};
        float as1[4] = {0.f, 0.f, 0.f, 0.f};
#pragma unroll 4
        for (int k = 0; k < 96; ++k) {
            float w0 = sW20[k * 64 + l];
            float w1 = sW20[k * 64 + l + 32];
            float a0 = buf[k * 5 + 0], a1 = buf[k * 5 + 1];
            float a2 = buf[k * 5 + 2], a3 = buf[k * 5 + 3];
            as0[0] += a0 * w0; as0[1] += a1 * w0; as0[2] += a2 * w0; as0[3] += a3 * w0;
            as1[0] += a0 * w1; as1[1] += a1 * w1; as1[2] += a2 * w1; as1[3] += a3 * w1;
        }
        __syncwarp();

        float vs0[4], vs1[4], ssq_s[4];
#pragma unroll
        for (int j = 0; j < 4; ++j) {
            int nj = min(nb + j, NN - 1);
            float v0 = as0[j] * 0.1020620726f + __ldg(gssF + (size_t)nj * 64 + l);
            float v1 = as1[j] * 0.1020620726f + __ldg(gssF + (size_t)nj * 64 + l + 32);
            vs0[j] = v0; vs1[j] = v1;
            ssq_s[j] = v0 * v0 + v1 * v1;
        }

        // ======== v sections ========
        float vvs[3][4];
        float ssq_v[4] = {0.f, 0.f, 0.f, 0.f};
#pragma unroll 1
        for (int c = 0; c < 3; ++c) {
#pragma unroll
            for (int j = 0; j < 4; ++j) {
                int nj = min(nb + j, NN - 1);
#pragma unroll
                for (int m = 0; m < 4; ++m) {
                    int u = l + 32 * m;
                    buf[u * 5 + j] = __ldg(gnvF + (size_t)nj * 384 + c * 128 + u);
                }
            }
            __syncwarp();

            float av[4] = {0.f, 0.f, 0.f, 0.f};
#pragma unroll 4
            for (int u = 0; u < 128; ++u) {
                float w = sW21[u * 32 + l];
                av[0] += buf[u * 5 + 0] * w;
                av[1] += buf[u * 5 + 1] * w;
                av[2] += buf[u * 5 + 2] * w;
                av[3] += buf[u * 5 + 3] * w;
            }
            __syncwarp();

            int o = l * 3 + c;
#pragma unroll
            for (int j = 0; j < 4; ++j) {
                int nj = min(nb + j, NN - 1);
                float val = av[j] * 0.0883883476f + __ldg(gsvF + (size_t)nj * 96 + o);
                vvs[c][j] = val;
                ssq_v[j] += val * val;
            }
        }

        // ======== warp reductions + writes ========
#pragma unroll
        for (int d = 16; d; d >>= 1) {
#pragma unroll
            for (int j = 0; j < 4; ++j) {
                ssq_s[j] += __shfl_xor_sync(0xffffffffu, ssq_s[j], d);
                ssq_v[j] += __shfl_xor_sync(0xffffffffu, ssq_v[j], d);
            }
        }
#pragma unroll
        for (int j = 0; j < 4; ++j) {
            int n = nb + j;
            if (n < NN) {
                float rs = rsqrtf(ssq_s[j] * (1.0f / 64.0f) + 1e-5f);
                float rv = rsqrtf(ssq_v[j] * (1.0f / 32.0f) + 1e-5f);
                out[(size_t)n * 160 + l]      = vs0[j] * rs * sG[l];
                out[(size_t)n * 160 + l + 32] = vs1[j] * rs * sG[l + 32];
                float gv = rv * sG[64 + l];
#pragma unroll
                for (int c = 0; c < 3; ++c)
                    out[(size_t)n * 160 + 64 + l * 3 + c] = vvs[c][j] * gv;
            }
        }
        __syncwarp();
    }
}

// ---------------- launch ----------------
extern "C" void kernel_launch(void* const* d_in, const int* in_sizes, int n_in,
                              void* d_out, int out_size) {
    const float* nh    = (const float*)d_in[0];
    const int*   ei    = (const int*)  d_in[1];
    const float* esh   = (const float*)d_in[2];
    const float* eattr = (const float*)d_in[3];
    const float* W1_0  = (const float*)d_in[4];
    const float* W1_1  = (const float*)d_in[5];
    const float* Wfc1  = (const float*)d_in[6];
    const float* Wfc2  = (const float*)d_in[7];
    const float* Wfc3  = (const float*)d_in[8];
    const float* W2_0  = (const float*)d_in[9];
    const float* W2_1  = (const float*)d_in[10];
    const float* Wsc0  = (const float*)d_in[11];
    const float* Wsc1  = (const float*)d_in[12];
    const float* g0    = (const float*)d_in[13];
    const float* g1    = (const float*)d_in[14];
    float* out = (float*)d_out;

    cudaFuncSetAttribute(k_edge, cudaFuncAttributeMaxDynamicSharedMemorySize, 57344);
    cudaFuncSetAttribute(k_out, cudaFuncAttributeMaxDynamicSharedMemorySize, 61952);

    k_pre<<<11793, 256>>>(Wfc1, Wfc2, Wfc3);              // zero + transpose
    k_prep<<<391, 256>>>(nh, W1_0, W1_1, Wsc0, Wsc1);     // 64 nodes/block
    k_edge<<<1563, 128, 57344>>>(ei, esh, eattr);         // 2 edges/thread
    k_out<<<391, 256, 61952>>>(out, W2_0, W2_1, g0, g1);  // 64 nodes/block
}

// round 12
// speedup vs baseline: 1.6137x; 1.0112x over previous
#include <cuda_runtime.h>

#define NN 25000
#define NE 400000

#define INV_SQRT3 0.57735026919f
#define INV_SQRT2 0.70710678119f

// ---------------- scratch (device globals; allocation-free) ----------------
__device__ float4 d_g_s  [NN * 16];   // s   = s_in @ W1_0 /8           (N,64)
__device__ float4 d_g_v  [NN * 24];   // v   = v_in . W1_1 /sqrt32      (N,32,3) [u*3+c]
__device__ float4 d_g_scs[NN * 16];   // sc_s                           (N,64)
__device__ float4 d_g_scv[NN * 24];   // sc_v                           (N,96)  [u*3+c]
__device__ float4 d_g_ns [NN * 24];   // scatter accum s-part           (N,96)
__device__ float4 d_g_nv [NN * 96];   // scatter accum v-part           (N,3,128) [c][u]
__device__ float  d_W1K[8 * 64];      // Wfc1 natural [k][j], prescaled 1/sqrt(8)
__device__ float  d_W2K[64 * 64];     // Wfc2 natural [k][j], prescaled 1/8
__device__ float  d_W3K[64 * 256];    // Wfc3 natural [k][j], prescaled, zero-pad j>=224

// ---------------- f32x2 helpers ----------------
#define FMA2(d, a, b) \
    asm("fma.rn.f32x2 %0, %1, %2, %0;" : "+l"(d) : "l"(a), "l"(b))
#define PACK2(d, lo, hi) \
    asm("mov.b64 %0, {%1, %2};" : "=l"(d) : "f"(lo), "f"(hi))
#define UNPACK2(lo, hi, s) \
    asm("mov.b64 {%0, %1}, %2;" : "=f"(lo), "=f"(hi) : "l"(s))

__device__ __forceinline__ float silu_f(float x) {
    return x / (1.0f + __expf(-x));
}

__device__ __forceinline__ void red4(float* p, float a, float b, float c, float d) {
    asm volatile("red.global.add.v4.f32 [%0], {%1,%2,%3,%4};"
                 :: "l"(p), "f"(a), "f"(b), "f"(c), "f"(d) : "memory");
}

// ---------------- 8x8 register-tiled GEMM (acc stays in registers) ---------
// acc[j*4+i] += sum_k A[k][jt*8+j] * B[k][et*8+2i .. 2i+1]
// A stride 64, B stride 128.
template <int KLEN>
__device__ __forceinline__ void gemm_acc(const float* __restrict__ sAm,
                                         const float* __restrict__ sBm,
                                         unsigned long long* acc,
                                         int jt, int et) {
    const float* Ap = sAm + jt * 8;
    const float* Bp = sBm + et * 8;
#pragma unroll
    for (int i = 0; i < 32; ++i) acc[i] = 0ull;
#pragma unroll 4
    for (int k = 0; k < KLEN; ++k) {
        float4 a0 = *reinterpret_cast<const float4*>(Ap + k * 64);
        float4 a1 = *reinterpret_cast<const float4*>(Ap + k * 64 + 4);
        ulonglong2 b01 = *reinterpret_cast<const ulonglong2*>(Bp + k * 128);
        ulonglong2 b23 = *reinterpret_cast<const ulonglong2*>(Bp + k * 128 + 4);
        unsigned long long ap;
        PACK2(ap, a0.x, a0.x);
        FMA2(acc[0],  ap, b01.x); FMA2(acc[1],  ap, b01.y);
        FMA2(acc[2],  ap, b23.x); FMA2(acc[3],  ap, b23.y);
        PACK2(ap, a0.y, a0.y);
        FMA2(acc[4],  ap, b01.x); FMA2(acc[5],  ap, b01.y);
        FMA2(acc[6],  ap, b23.x); FMA2(acc[7],  ap, b23.y);
        PACK2(ap, a0.z, a0.z);
        FMA2(acc[8],  ap, b01.x); FMA2(acc[9],  ap, b01.y);
        FMA2(acc[10], ap, b23.x); FMA2(acc[11], ap, b23.y);
        PACK2(ap, a0.w, a0.w);
        FMA2(acc[12], ap, b01.x); FMA2(acc[13], ap, b01.y);
        FMA2(acc[14], ap, b23.x); FMA2(acc[15], ap, b23.y);
        PACK2(ap, a1.x, a1.x);
        FMA2(acc[16], ap, b01.x); FMA2(acc[17], ap, b01.y);
        FMA2(acc[18], ap, b23.x); FMA2(acc[19], ap, b23.y);
        PACK2(ap, a1.y, a1.y);
        FMA2(acc[20], ap, b01.x); FMA2(acc[21], ap, b01.y);
        FMA2(acc[22], ap, b23.x); FMA2(acc[23], ap, b23.y);
        PACK2(ap, a1.z, a1.z);
        FMA2(acc[24], ap, b01.x); FMA2(acc[25], ap, b01.y);
        FMA2(acc[26], ap, b23.x); FMA2(acc[27], ap, b23.y);
        PACK2(ap, a1.w, a1.w);
        FMA2(acc[28], ap, b01.x); FMA2(acc[29], ap, b01.y);
        FMA2(acc[30], ap, b23.x); FMA2(acc[31], ap, b23.y);
    }
}

// store acc with silu into sD (stride 128)
__device__ __forceinline__ void store_silu(const unsigned long long* acc,
                                           float* __restrict__ sD,
                                           int jt, int et) {
    float* D = sD + (size_t)(jt * 8) * 128 + et * 8;
#pragma unroll
    for (int j = 0; j < 8; ++j) {
#pragma unroll
        for (int i = 0; i < 4; ++i) {
            float lo, hi;
            UNPACK2(lo, hi, acc[j * 4 + i]);
            unsigned long long p;
            PACK2(p, silu_f(lo), silu_f(hi));
            *reinterpret_cast<unsigned long long*>(D + j * 128 + 2 * i) = p;
        }
    }
}

// ---------------- consume helpers (read acc-derived w, scatter) ------------
__device__ __forceinline__ void cons_c0(const float* w, int e, int j0,
                                        const int* __restrict__ ei,
                                        const float* __restrict__ esh) {
    int src = __ldg(ei + e), dst = __ldg(ei + NE + e);
    float sh0 = __ldg(esh + (size_t)e * 4);
    const float4* sd = reinterpret_cast<const float4*>(
        (const float*)d_g_s + (size_t)dst * 64 + j0);
    float4 s0 = __ldg(sd), s1 = __ldg(sd + 1);
    float* nsp = (float*)d_g_ns + (size_t)src * 96 + j0;
    red4(nsp,     w[0]*s0.x*sh0, w[1]*s0.y*sh0, w[2]*s0.z*sh0, w[3]*s0.w*sh0);
    red4(nsp + 4, w[4]*s1.x*sh0, w[5]*s1.y*sh0, w[6]*s1.z*sh0, w[7]*s1.w*sh0);
}

__device__ __forceinline__ void cons_c1(const float* w, int e, int j0,
                                        const int* __restrict__ ei,
                                        const float* __restrict__ esh) {
    int src = __ldg(ei + e), dst = __ldg(ei + NE + e);
    float4 sh = __ldg(reinterpret_cast<const float4*>(esh + (size_t)e * 4));
    const float4* sd = reinterpret_cast<const float4*>(
        (const float*)d_g_s + (size_t)dst * 64 + j0);
    float4 s0 = __ldg(sd), s1 = __ldg(sd + 1);
    float a0 = w[0]*s0.x, a1 = w[1]*s0.y, a2 = w[2]*s0.z, a3 = w[3]*s0.w;
    float a4 = w[4]*s1.x, a5 = w[5]*s1.y, a6 = w[6]*s1.z, a7 = w[7]*s1.w;
    float* nvp = (float*)d_g_nv + (size_t)src * 384 + j0;
    red4(nvp,           a0*sh.y, a1*sh.y, a2*sh.y, a3*sh.y);
    red4(nvp + 4,       a4*sh.y, a5*sh.y, a6*sh.y, a7*sh.y);
    red4(nvp + 128,     a0*sh.z, a1*sh.z, a2*sh.z, a3*sh.z);
    red4(nvp + 132,     a4*sh.z, a5*sh.z, a6*sh.z, a7*sh.z);
    red4(nvp + 256,     a0*sh.w, a1*sh.w, a2*sh.w, a3*sh.w);
    red4(nvp + 260,     a4*sh.w, a5*sh.w, a6*sh.w, a7*sh.w);
}

// w2 (mv1): u0 = row group within [0,32)
__device__ __forceinline__ void cons_c2a(const float* w, int e, int u0,
                                         const int* __restrict__ ei,
                                         const float* __restrict__ esh) {
    int src = __ldg(ei + e), dst = __ldg(ei + NE + e);
    float sh0 = __ldg(esh + (size_t)e * 4);
    const float4* vp = reinterpret_cast<const float4*>(
        (const float*)d_g_v + (size_t)dst * 96 + u0 * 3);
    float4 v0 = __ldg(vp),     v1 = __ldg(vp + 1), v2 = __ldg(vp + 2);
    float4 v3 = __ldg(vp + 3), v4 = __ldg(vp + 4), v5 = __ldg(vp + 5);
    float vv[24] = {v0.x,v0.y,v0.z,v0.w, v1.x,v1.y,v1.z,v1.w,
                    v2.x,v2.y,v2.z,v2.w, v3.x,v3.y,v3.z,v3.w,
                    v4.x,v4.y,v4.z,v4.w, v5.x,v5.y,v5.z,v5.w};
    float* nvp = (float*)d_g_nv + (size_t)src * 384;
#pragma unroll
    for (int c = 0; c < 3; ++c) {
        red4(nvp + c*128 + 64 + u0,
             w[0]*vv[0+c]*sh0,  w[1]*vv[3+c]*sh0,
             w[2]*vv[6+c]*sh0,  w[3]*vv[9+c]*sh0);
        red4(nvp + c*128 + 64 + u0 + 4,
             w[4]*vv[12+c]*sh0, w[5]*vv[15+c]*sh0,
             w[6]*vv[18+c]*sh0, w[7]*vv[21+c]*sh0);
    }
}

// w3 (m1): u0 in [0,32)
__device__ __forceinline__ void cons_c2b(const float* w, int e, int u0,
                                         const int* __restrict__ ei,
                                         const float* __restrict__ esh) {
    int src = __ldg(ei + e), dst = __ldg(ei + NE + e);
    float4 sh = __ldg(reinterpret_cast<const float4*>(esh + (size_t)e * 4));
    const float4* vp = reinterpret_cast<const float4*>(
        (const float*)d_g_v + (size_t)dst * 96 + u0 * 3);
    float4 v0 = __ldg(vp),     v1 = __ldg(vp + 1), v2 = __ldg(vp + 2);
    float4 v3 = __ldg(vp + 3), v4 = __ldg(vp + 4), v5 = __ldg(vp + 5);
    float vv[24] = {v0.x,v0.y,v0.z,v0.w, v1.x,v1.y,v1.z,v1.w,
                    v2.x,v2.y,v2.z,v2.w, v3.x,v3.y,v3.z,v3.w,
                    v4.x,v4.y,v4.z,v4.w, v5.x,v5.y,v5.z,v5.w};
    float m[8];
#pragma unroll
    for (int q = 0; q < 8; ++q)
        m[q] = w[q] * (vv[q*3]*sh.y + vv[q*3+1]*sh.z + vv[q*3+2]*sh.w);
    float* nsp = (float*)d_g_ns + (size_t)src * 96 + 64 + u0;
    red4(nsp,     m[0], m[1], m[2], m[3]);
    red4(nsp + 4, m[4], m[5], m[6], m[7]);
}

// w4 (mv2 cross): u0 in [0,32)
__device__ __forceinline__ void cons_c3(const float* w, int e, int u0,
                                        const int* __restrict__ ei,
                                        const float* __restrict__ esh) {
    int src = __ldg(ei + e), dst = __ldg(ei + NE + e);
    float4 sh = __ldg(reinterpret_cast<const float4*>(esh + (size_t)e * 4));
    const float4* vp = reinterpret_cast<const float4*>(
        (const float*)d_g_v + (size_t)dst * 96 + u0 * 3);
    float4 v0 = __ldg(vp),     v1 = __ldg(vp + 1), v2 = __ldg(vp + 2);
    float4 v3 = __ldg(vp + 3), v4 = __ldg(vp + 4), v5 = __ldg(vp + 5);
    float vv[24] = {v0.x,v0.y,v0.z,v0.w, v1.x,v1.y,v1.z,v1.w,
                    v2.x,v2.y,v2.z,v2.w, v3.x,v3.y,v3.z,v3.w,
                    v4.x,v4.y,v4.z,v4.w, v5.x,v5.y,v5.z,v5.w};
    float mx[8], my[8], mz[8];
#pragma unroll
    for (int q = 0; q < 8; ++q) {
        float vx = vv[q*3], vy = vv[q*3+1], vz = vv[q*3+2];
        mx[q] = w[q] * (vy*sh.w - vz*sh.z);
        my[q] = w[q] * (vz*sh.y - vx*sh.w);
        mz[q] = w[q] * (vx*sh.z - vy*sh.y);
    }
    float* nvp = (float*)d_g_nv + (size_t)src * 384;
    red4(nvp +          96 + u0,     mx[0], mx[1], mx[2], mx[3]);
    red4(nvp +          96 + u0 + 4, mx[4], mx[5], mx[6], mx[7]);
    red4(nvp + 128 +    96 + u0,     my[0], my[1], my[2], my[3]);
    red4(nvp + 128 +    96 + u0 + 4, my[4], my[5], my[6], my[7]);
    red4(nvp + 256 +    96 + u0,     mz[0], mz[1], mz[2], mz[3]);
    red4(nvp + 256 +    96 + u0 + 4, mz[4], mz[5], mz[6], mz[7]);
}

// ---------------- kernel 0: zero accumulators + prescale weights ------------
__global__ void k_pre(const float* __restrict__ Wfc1,
                      const float* __restrict__ Wfc2,
                      const float* __restrict__ Wfc3) {
    int i = blockIdx.x * 256 + threadIdx.x;
    const int NZ = NN * 120;   // float4 count of (ns + nv)
    if (i < NZ) {
        float4 z = make_float4(0.f, 0.f, 0.f, 0.f);
        if (i < NN * 24) d_g_ns[i] = z;
        else             d_g_nv[i - NN * 24] = z;
    } else {
        int j = i - NZ;
        if (j < 512) {
            d_W1K[j] = Wfc1[j] * 0.3535533906f;
        } else if (j < 4608) {
            d_W2K[j - 512] = Wfc2[j - 512] * 0.125f;
        } else if (j < 4608 + 16384) {
            int m = j - 4608;
            int k = m >> 8, col = m & 255;
            float v = 0.f;
            if (col < 224) {
                float s = 0.03125f;  // (1/sqrt(64)) * (1/sqrt(16))
                if (col >= 192)      s *= INV_SQRT2;
                else if (col >= 160) s *= INV_SQRT3;
                v = Wfc3[k * 224 + col] * s;
            }
            d_W3K[m] = v;
        }
    }
}

// ---------------- kernel 2: node prep, persistent warp-per-node -------------
__global__ void __launch_bounds__(256) k_prep(const float* __restrict__ nh,
                                              const float* __restrict__ W1_0,
                                              const float* __restrict__ W1_1,
                                              const float* __restrict__ Wsc0,
                                              const float* __restrict__ Wsc1) {
    __shared__ float sW10[4096], sWsc0[4096], sW11[1024], sWsc1[1024], sIn[1280];
    int t = threadIdx.x;
    for (int i = t; i < 4096; i += 256) { sW10[i] = W1_0[i]; sWsc0[i] = Wsc0[i]; }
    for (int i = t; i < 1024; i += 256) { sW11[i] = W1_1[i]; sWsc1[i] = Wsc1[i]; }
    __syncthreads();

    int wid = t >> 5, l = t & 31;
    float* gs  = (float*)d_g_s;
    float* gv  = (float*)d_g_v;
    float* gss = (float*)d_g_scs;
    float* gsv = (float*)d_g_scv;
    float* row = sIn + wid * 160;

    for (int it = 0; it < 8; ++it) {
        int n = blockIdx.x * 64 + it * 8 + wid;
        if (n >= NN) break;
        {
            const float4* src = reinterpret_cast<const float4*>(nh + (size_t)n * 160);
            float4* dst = reinterpret_cast<float4*>(row);
            for (int i = l; i < 40; i += 32) dst[i] = __ldg(src + i);
        }
        __syncwarp();
#pragma unroll
        for (int r = 0; r < 2; ++r) {
            int o = l + r * 32;
            float a = 0.f, b = 0.f;
#pragma unroll 8
            for (int u = 0; u < 64; ++u) {
                float x = row[u];
                a += x * sW10[u * 64 + o];
                b += x * sWsc0[u * 64 + o];
            }
            gs [(size_t)n * 64 + o] = a * 0.125f;
            gss[(size_t)n * 64 + o] = b * 0.125f;
        }
#pragma unroll
        for (int r = 0; r < 3; ++r) {
            int o = l + r * 32;
            int up = o / 3, c = o - up * 3;
            float a = 0.f, b = 0.f;
#pragma unroll 8
            for (int u = 0; u < 32; ++u) {
                float x = row[64 + u * 3 + c];
                a += x * sW11[u * 32 + up];
                b += x * sWsc1[u * 32 + up];
            }
            gv [(size_t)n * 96 + o] = a * 0.1767766953f;
            gsv[(size_t)n * 96 + o] = b * 0.1767766953f;
        }
        __syncwarp();
    }
}

// ---------------- kernel 3: fused GEMM + register consume -------------------
// 128 threads / 128 edges. smem: sA 4096 + sB 8192 = 12288 fl = 49152 B.
// h1 and h2 ping-pong inside sB (gemm2 accumulates in regs before overwrite).
// w-chunks never touch smem: consumed straight from accumulators.
__global__ void __launch_bounds__(128, 3) k_edge(const int* __restrict__ ei,
                                                 const float* __restrict__ esh,
                                                 const float* __restrict__ eattr) {
    extern __shared__ float sm[];
    float* sA = sm;          // 4096: W1K -> W2K -> Wc
    float* sB = sm + 4096;   // 8192: att(partial) -> h1 -> h2
    int t = threadIdx.x;
    int jt = t & 7, et = t >> 3;
    int ebase = blockIdx.x * 128;   // NE = 3125*128 exactly

    // stage att transposed [k][e] into sB, W1K into sA
    {
        int e = ebase + t;
        const float4* ap = reinterpret_cast<const float4*>(eattr + (size_t)e * 8);
        float4 a0 = __ldg(ap), a1 = __ldg(ap + 1);
        sB[0*128+t] = a0.x; sB[1*128+t] = a0.y;
        sB[2*128+t] = a0.z; sB[3*128+t] = a0.w;
        sB[4*128+t] = a1.x; sB[5*128+t] = a1.y;
        sB[6*128+t] = a1.z; sB[7*128+t] = a1.w;
        for (int i = t; i < 512; i += 128) sA[i] = d_W1K[i];
    }
    __syncthreads();

    unsigned long long acc[32];

    // ---- MLP1: h1 = silu(W1K @ att) ----
    gemm_acc<8>(sA, sB, acc, jt, et);
    __syncthreads();                 // all att reads done
    store_silu(acc, sB, jt, et);     // h1 -> sB
    for (int i = t; i < 4096; i += 128) sA[i] = d_W2K[i];
    __syncthreads();                 // h1 + W2K visible

    // ---- MLP2: h2 = silu(W2K @ h1) ----
    gemm_acc<64>(sA, sB, acc, jt, et);
    __syncthreads();                 // all h1 reads done
    store_silu(acc, sB, jt, et);     // h2 -> sB (in place)

    // ---- 4 chunks of 64 w-rows: GEMM then consume from registers ----
    int e0 = ebase + et * 8;
#pragma unroll 1
    for (int c = 0; c < 4; ++c) {
        // load Wc[64][64] = d_W3K[:, 64c:64c+64]
#pragma unroll
        for (int r = 0; r < 8; ++r) {
            int idx4 = t + 128 * r;
            int k = idx4 >> 4;
            int jj = (idx4 & 15) * 4;
            *reinterpret_cast<float4*>(sA + k * 64 + jj) =
                *reinterpret_cast<const float4*>(d_W3K + k * 256 + 64 * c + jj);
        }
        __syncthreads();             // Wc ready (also guards h2 store on c=0)
        gemm_acc<64>(sA, sB, acc, jt, et);

        // consume: thread owns rows jt*8..jt*8+7, edges e0..e0+7
#pragma unroll 1
        for (int i = 0; i < 4; ++i) {
            float wa[8], wb[8];
#pragma unroll
            for (int j = 0; j < 8; ++j) UNPACK2(wa[j], wb[j], acc[j * 4 + i]);
            int ea = e0 + 2 * i, eb = ea + 1;
            if (c == 0) {
                int j0 = jt * 8;
                cons_c0(wa, ea, j0, ei, esh);
                cons_c0(wb, eb, j0, ei, esh);
            } else if (c == 1) {
                int j0 = jt * 8;
                cons_c1(wa, ea, j0, ei, esh);
                cons_c1(wb, eb, j0, ei, esh);
            } else if (c == 2) {
                if (jt < 4) {
                    int u0 = jt * 8;
                    cons_c2a(wa, ea, u0, ei, esh);
                    cons_c2a(wb, eb, u0, ei, esh);
                } else {
                    int u0 = (jt - 4) * 8;
                    cons_c2b(wa, ea, u0, ei, esh);
                    cons_c2b(wb, eb, u0, ei, esh);
                }
            } else {
                if (jt < 4) {
                    int u0 = jt * 8;
                    cons_c3(wa, ea, u0, ei, esh);
                    cons_c3(wb, eb, u0, ei, esh);
                }
            }
        }
        __syncthreads();             // all Wc reads done before next overwrite
    }
}

// ---------------- kernel 4: output projection + skip + RMS, 4 nodes/warp ----
// (unchanged — proven 64us)
__global__ void __launch_bounds__(256) k_out(float* __restrict__ out,
                                             const float* __restrict__ W2_0,
                                             const float* __restrict__ W2_1,
                                             const float* __restrict__ g0,
                                             const float* __restrict__ g1) {
    extern __shared__ float smo[];
    float* sW20 = smo;           // 6144  [k][o], natural layout
    float* sW21 = smo + 6144;    // 4096  [u][u'], natural layout
    float* sG   = smo + 10240;   // 96 (+32 pad)
    float* sBuf = smo + 10368;   // 8 warps * 640
    int t = threadIdx.x;
    for (int i = t; i < 6144; i += 256) sW20[i] = W2_0[i];
    for (int i = t; i < 4096; i += 256) sW21[i] = W2_1[i];
    if (t < 64) sG[t] = g0[t];
    else if (t < 96) sG[t] = g1[t - 64];
    __syncthreads();

    const float* gnsF = (const float*)d_g_ns;
    const float* gnvF = (const float*)d_g_nv;
    const float* gssF = (const float*)d_g_scs;
    const float* gsvF = (const float*)d_g_scv;

    int wid = t >> 5, l = t & 31;
    float* buf = sBuf + wid * 640;     // buf[k*5 + j]

    for (int it = 0; it < 2; ++it) {
        int nb = blockIdx.x * 64 + it * 32 + wid * 4;

        // ======== s section ========
#pragma unroll
        for (int j = 0; j < 4; ++j) {
            int nj = min(nb + j, NN - 1);
#pragma unroll
            for (int m = 0; m < 3; ++m) {
                int k = l + 32 * m;
                buf[k * 5 + j] = __ldg(gnsF + (size_t)nj * 96 + k);
            }
        }
        __syncwarp();

        float as0[4] = {0.f, 0.f, 0.f, 0.f};
        float as1[4] = {0.f, 0.f, 0.f, 0.f};
#pragma unroll 4
        for (int k = 0; k < 96; ++k) {
            float w0 = sW20[k * 64 + l];
            float w1 = sW20[k * 64 + l + 32];
            float a0 = buf[k * 5 + 0], a1 = buf[k * 5 + 1];
            float a2 = buf[k * 5 + 2], a3 = buf[k * 5 + 3];
            as0[0] += a0 * w0; as0[1] += a1 * w0; as0[2] += a2 * w0; as0[3] += a3 * w0;
            as1[0] += a0 * w1; as1[1] += a1 * w1; as1[2] += a2 * w1; as1[3] += a3 * w1;
        }
        __syncwarp();

        float vs0[4], vs1[4], ssq_s[4];
#pragma unroll
        for (int j = 0; j < 4; ++j) {
            int nj = min(nb + j, NN - 1);
            float v0 = as0[j] * 0.1020620726f + __ldg(gssF + (size_t)nj * 64 + l);
            float v1 = as1[j] * 0.1020620726f + __ldg(gssF + (size_t)nj * 64 + l + 32);
            vs0[j] = v0; vs1[j] = v1;
            ssq_s[j] = v0 * v0 + v1 * v1;
        }

        // ======== v sections ========
        float vvs[3][4];
        float ssq_v[4] = {0.f, 0.f, 0.f, 0.f};
#pragma unroll 1
        for (int c = 0; c < 3; ++c) {
#pragma unroll
            for (int j = 0; j < 4; ++j) {
                int nj = min(nb + j, NN - 1);
#pragma unroll
                for (int m = 0; m < 4; ++m) {
                    int u = l + 32 * m;
                    buf[u * 5 + j] = __ldg(gnvF + (size_t)nj * 384 + c * 128 + u);
                }
            }
            __syncwarp();

            float av[4] = {0.f, 0.f, 0.f, 0.f};
#pragma unroll 4
            for (int u = 0; u < 128; ++u) {
                float w = sW21[u * 32 + l];
                av[0] += buf[u * 5 + 0] * w;
                av[1] += buf[u * 5 + 1] * w;
                av[2] += buf[u * 5 + 2] * w;
                av[3] += buf[u * 5 + 3] * w;
            }
            __syncwarp();

            int o = l * 3 + c;
#pragma unroll
            for (int j = 0; j < 4; ++j) {
                int nj = min(nb + j, NN - 1);
                float val = av[j] * 0.0883883476f + __ldg(gsvF + (size_t)nj * 96 + o);
                vvs[c][j] = val;
                ssq_v[j] += val * val;
            }
        }

        // ======== warp reductions + writes ========
#pragma unroll
        for (int d = 16; d; d >>= 1) {
#pragma unroll
            for (int j = 0; j < 4; ++j) {
                ssq_s[j] += __shfl_xor_sync(0xffffffffu, ssq_s[j], d);
                ssq_v[j] += __shfl_xor_sync(0xffffffffu, ssq_v[j], d);
            }
        }
#pragma unroll
        for (int j = 0; j < 4; ++j) {
            int n = nb + j;
            if (n < NN) {
                float rs = rsqrtf(ssq_s[j] * (1.0f / 64.0f) + 1e-5f);
                float rv = rsqrtf(ssq_v[j] * (1.0f / 32.0f) + 1e-5f);
                out[(size_t)n * 160 + l]      = vs0[j] * rs * sG[l];
                out[(size_t)n * 160 + l + 32] = vs1[j] * rs * sG[l + 32];
                float gv = rv * sG[64 + l];
#pragma unroll
                for (int c = 0; c < 3; ++c)
                    out[(size_t)n * 160 + 64 + l * 3 + c] = vvs[c][j] * gv;
            }
        }
        __syncwarp();
    }
}

// ---------------- launch ----------------
extern "C" void kernel_launch(void* const* d_in, const int* in_sizes, int n_in,
                              void* d_out, int out_size) {
    const float* nh    = (const float*)d_in[0];
    const int*   ei    = (const int*)  d_in[1];
    const float* esh   = (const float*)d_in[2];
    const float* eattr = (const float*)d_in[3];
    const float* W1_0  = (const float*)d_in[4];
    const float* W1_1  = (const float*)d_in[5];
    const float* Wfc1  = (const float*)d_in[6];
    const float* Wfc2  = (const float*)d_in[7];
    const float* Wfc3  = (const float*)d_in[8];
    const float* W2_0  = (const float*)d_in[9];
    const float* W2_1  = (const float*)d_in[10];
    const float* Wsc0  = (const float*)d_in[11];
    const float* Wsc1  = (const float*)d_in[12];
    const float* g0    = (const float*)d_in[13];
    const float* g1    = (const float*)d_in[14];
    float* out = (float*)d_out;

    cudaFuncSetAttribute(k_edge, cudaFuncAttributeMaxDynamicSharedMemorySize, 49152);
    cudaFuncSetAttribute(k_out, cudaFuncAttributeMaxDynamicSharedMemorySize, 61952);

    k_pre<<<11802, 256>>>(Wfc1, Wfc2, Wfc3);              // zero + prescale
    k_prep<<<391, 256>>>(nh, W1_0, W1_1, Wsc0, Wsc1);     // 64 nodes/block
    k_edge<<<3125, 128, 49152>>>(ei, esh, eattr);
    k_out<<<391, 256, 61952>>>(out, W2_0, W2_1, g0, g1);  // 64 nodes/block
}

// round 13
// speedup vs baseline: 1.8246x; 1.1307x over previous
#include <cuda_runtime.h>

#define NN 25000
#define NE 400000

#define INV_SQRT3 0.57735026919f
#define INV_SQRT2 0.70710678119f

// ---------------- scratch (device globals; allocation-free) ----------------
__device__ float4 d_g_s  [NN * 16];   // s   = s_in @ W1_0 /8           (N,64)
__device__ float4 d_g_v  [NN * 24];   // v   = v_in . W1_1 /sqrt32      (N,32,3) [u*3+c]
__device__ float4 d_g_scs[NN * 16];   // sc_s                           (N,64)
__device__ float4 d_g_scv[NN * 24];   // sc_v                           (N,96)  [u*3+c]
__device__ float4 d_g_ns [NN * 24];   // scatter accum s-part           (N,96)
__device__ float4 d_g_nv [NN * 96];   // scatter accum v-part           (N,3,128) [c][u]
__device__ float  d_W1K[8 * 64];      // Wfc1 natural [k][j], prescaled 1/sqrt(8)
__device__ float  d_W2K[64 * 64];     // Wfc2 natural [k][j], prescaled 1/8
__device__ float  d_W3K[64 * 256];    // Wfc3 natural [k][j], prescaled, zero-pad j>=224

// ---------------- f32x2 / async helpers ----------------
#define FMA2(d, a, b) \
    asm("fma.rn.f32x2 %0, %1, %2, %0;" : "+l"(d) : "l"(a), "l"(b))
#define PACK2(d, lo, hi) \
    asm("mov.b64 %0, {%1, %2};" : "=l"(d) : "f"(lo), "f"(hi))
#define UNPACK2(lo, hi, s) \
    asm("mov.b64 {%0, %1}, %2;" : "=f"(lo), "=f"(hi) : "l"(s))

__device__ __forceinline__ void cpa16(unsigned int saddr, const float* g) {
    asm volatile("cp.async.ca.shared.global [%0], [%1], 16;"
                 :: "r"(saddr), "l"(g) : "memory");
}
#define CP_COMMIT() asm volatile("cp.async.commit_group;" ::: "memory")
#define CP_WAIT(n)  asm volatile("cp.async.wait_group %0;" :: "n"(n) : "memory")

__device__ __forceinline__ float silu_f(float x) {
    return x / (1.0f + __expf(-x));
}

__device__ __forceinline__ void red4(float* p, float a, float b, float c, float d) {
    asm volatile("red.global.add.v4.f32 [%0], {%1,%2,%3,%4};"
                 :: "l"(p), "f"(a), "f"(b), "f"(c), "f"(d) : "memory");
}

// ---------------- 8x8 register-tiled GEMM (acc stays in registers) ---------
template <int KLEN>
__device__ __forceinline__ void gemm_acc(const float* __restrict__ sAm,
                                         const float* __restrict__ sBm,
                                         unsigned long long* acc,
                                         int jt, int et) {
    const float* Ap = sAm + jt * 8;
    const float* Bp = sBm + et * 8;
#pragma unroll
    for (int i = 0; i < 32; ++i) acc[i] = 0ull;
#pragma unroll 4
    for (int k = 0; k < KLEN; ++k) {
        float4 a0 = *reinterpret_cast<const float4*>(Ap + k * 64);
        float4 a1 = *reinterpret_cast<const float4*>(Ap + k * 64 + 4);
        ulonglong2 b01 = *reinterpret_cast<const ulonglong2*>(Bp + k * 128);
        ulonglong2 b23 = *reinterpret_cast<const ulonglong2*>(Bp + k * 128 + 4);
        unsigned long long ap;
        PACK2(ap, a0.x, a0.x);
        FMA2(acc[0],  ap, b01.x); FMA2(acc[1],  ap, b01.y);
        FMA2(acc[2],  ap, b23.x); FMA2(acc[3],  ap, b23.y);
        PACK2(ap, a0.y, a0.y);
        FMA2(acc[4],  ap, b01.x); FMA2(acc[5],  ap, b01.y);
        FMA2(acc[6],  ap, b23.x); FMA2(acc[7],  ap, b23.y);
        PACK2(ap, a0.z, a0.z);
        FMA2(acc[8],  ap, b01.x); FMA2(acc[9],  ap, b01.y);
        FMA2(acc[10], ap, b23.x); FMA2(acc[11], ap, b23.y);
        PACK2(ap, a0.w, a0.w);
        FMA2(acc[12], ap, b01.x); FMA2(acc[13], ap, b01.y);
        FMA2(acc[14], ap, b23.x); FMA2(acc[15], ap, b23.y);
        PACK2(ap, a1.x, a1.x);
        FMA2(acc[16], ap, b01.x); FMA2(acc[17], ap, b01.y);
        FMA2(acc[18], ap, b23.x); FMA2(acc[19], ap, b23.y);
        PACK2(ap, a1.y, a1.y);
        FMA2(acc[20], ap, b01.x); FMA2(acc[21], ap, b01.y);
        FMA2(acc[22], ap, b23.x); FMA2(acc[23], ap, b23.y);
        PACK2(ap, a1.z, a1.z);
        FMA2(acc[24], ap, b01.x); FMA2(acc[25], ap, b01.y);
        FMA2(acc[26], ap, b23.x); FMA2(acc[27], ap, b23.y);
        PACK2(ap, a1.w, a1.w);
        FMA2(acc[28], ap, b01.x); FMA2(acc[29], ap, b01.y);
        FMA2(acc[30], ap, b23.x); FMA2(acc[31], ap, b23.y);
    }
}

// store acc with silu into sD (stride 128)
__device__ __forceinline__ void store_silu(const unsigned long long* acc,
                                           float* __restrict__ sD,
                                           int jt, int et) {
    float* D = sD + (size_t)(jt * 8) * 128 + et * 8;
#pragma unroll
    for (int j = 0; j < 8; ++j) {
#pragma unroll
        for (int i = 0; i < 4; ++i) {
            float lo, hi;
            UNPACK2(lo, hi, acc[j * 4 + i]);
            unsigned long long p;
            PACK2(p, silu_f(lo), silu_f(hi));
            *reinterpret_cast<unsigned long long*>(D + j * 128 + 2 * i) = p;
        }
    }
}

// ---------------- consume helpers (identical math to R12) ------------------
__device__ __forceinline__ void cons_c0(const float* w, int e, int j0,
                                        const int* __restrict__ ei,
                                        const float* __restrict__ esh) {
    int src = __ldg(ei + e), dst = __ldg(ei + NE + e);
    float sh0 = __ldg(esh + (size_t)e * 4);
    const float4* sd = reinterpret_cast<const float4*>(
        (const float*)d_g_s + (size_t)dst * 64 + j0);
    float4 s0 = __ldg(sd), s1 = __ldg(sd + 1);
    float* nsp = (float*)d_g_ns + (size_t)src * 96 + j0;
    red4(nsp,     w[0]*s0.x*sh0, w[1]*s0.y*sh0, w[2]*s0.z*sh0, w[3]*s0.w*sh0);
    red4(nsp + 4, w[4]*s1.x*sh0, w[5]*s1.y*sh0, w[6]*s1.z*sh0, w[7]*s1.w*sh0);
}

__device__ __forceinline__ void cons_c1(const float* w, int e, int j0,
                                        const int* __restrict__ ei,
                                        const float* __restrict__ esh) {
    int src = __ldg(ei + e), dst = __ldg(ei + NE + e);
    float4 sh = __ldg(reinterpret_cast<const float4*>(esh + (size_t)e * 4));
    const float4* sd = reinterpret_cast<const float4*>(
        (const float*)d_g_s + (size_t)dst * 64 + j0);
    float4 s0 = __ldg(sd), s1 = __ldg(sd + 1);
    float a0 = w[0]*s0.x, a1 = w[1]*s0.y, a2 = w[2]*s0.z, a3 = w[3]*s0.w;
    float a4 = w[4]*s1.x, a5 = w[5]*s1.y, a6 = w[6]*s1.z, a7 = w[7]*s1.w;
    float* nvp = (float*)d_g_nv + (size_t)src * 384 + j0;
    red4(nvp,           a0*sh.y, a1*sh.y, a2*sh.y, a3*sh.y);
    red4(nvp + 4,       a4*sh.y, a5*sh.y, a6*sh.y, a7*sh.y);
    red4(nvp + 128,     a0*sh.z, a1*sh.z, a2*sh.z, a3*sh.z);
    red4(nvp + 132,     a4*sh.z, a5*sh.z, a6*sh.z, a7*sh.z);
    red4(nvp + 256,     a0*sh.w, a1*sh.w, a2*sh.w, a3*sh.w);
    red4(nvp + 260,     a4*sh.w, a5*sh.w, a6*sh.w, a7*sh.w);
}

__device__ __forceinline__ void cons_c2a(const float* w, int e, int u0,
                                         const int* __restrict__ ei,
                                         const float* __restrict__ esh) {
    int src = __ldg(ei + e), dst = __ldg(ei + NE + e);
    float sh0 = __ldg(esh + (size_t)e * 4);
    const float4* vp = reinterpret_cast<const float4*>(
        (const float*)d_g_v + (size_t)dst * 96 + u0 * 3);
    float4 v0 = __ldg(vp),     v1 = __ldg(vp + 1), v2 = __ldg(vp + 2);
    float4 v3 = __ldg(vp + 3), v4 = __ldg(vp + 4), v5 = __ldg(vp + 5);
    float vv[24] = {v0.x,v0.y,v0.z,v0.w, v1.x,v1.y,v1.z,v1.w,
                    v2.x,v2.y,v2.z,v2.w, v3.x,v3.y,v3.z,v3.w,
                    v4.x,v4.y,v4.z,v4.w, v5.x,v5.y,v5.z,v5.w};
    float* nvp = (float*)d_g_nv + (size_t)src * 384;
#pragma unroll
    for (int c = 0; c < 3; ++c) {
        red4(nvp + c*128 + 64 + u0,
             w[0]*vv[0+c]*sh0,  w[1]*vv[3+c]*sh0,
             w[2]*vv[6+c]*sh0,  w[3]*vv[9+c]*sh0);
        red4(nvp + c*128 + 64 + u0 + 4,
             w[4]*vv[12+c]*sh0, w[5]*vv[15+c]*sh0,
             w[6]*vv[18+c]*sh0, w[7]*vv[21+c]*sh0);
    }
}

__device__ __forceinline__ void cons_c2b(const float* w, int e, int u0,
                                         const int* __restrict__ ei,
                                         const float* __restrict__ esh) {
    int src = __ldg(ei + e), dst = __ldg(ei + NE + e);
    float4 sh = __ldg(reinterpret_cast<const float4*>(esh + (size_t)e * 4));
    const float4* vp = reinterpret_cast<const float4*>(
        (const float*)d_g_v + (size_t)dst * 96 + u0 * 3);
    float4 v0 = __ldg(vp),     v1 = __ldg(vp + 1), v2 = __ldg(vp + 2);
    float4 v3 = __ldg(vp + 3), v4 = __ldg(vp + 4), v5 = __ldg(vp + 5);
    float vv[24] = {v0.x,v0.y,v0.z,v0.w, v1.x,v1.y,v1.z,v1.w,
                    v2.x,v2.y,v2.z,v2.w, v3.x,v3.y,v3.z,v3.w,
                    v4.x,v4.y,v4.z,v4.w, v5.x,v5.y,v5.z,v5.w};
    float m[8];
#pragma unroll
    for (int q = 0; q < 8; ++q)
        m[q] = w[q] * (vv[q*3]*sh.y + vv[q*3+1]*sh.z + vv[q*3+2]*sh.w);
    float* nsp = (float*)d_g_ns + (size_t)src * 96 + 64 + u0;
    red4(nsp,     m[0], m[1], m[2], m[3]);
    red4(nsp + 4, m[4], m[5], m[6], m[7]);
}

__device__ __forceinline__ void cons_c3(const float* w, int e, int u0,
                                        const int* __restrict__ ei,
                                        const float* __restrict__ esh) {
    int src = __ldg(ei + e), dst = __ldg(ei + NE + e);
    float4 sh = __ldg(reinterpret_cast<const float4*>(esh + (size_t)e * 4));
    const float4* vp = reinterpret_cast<const float4*>(
        (const float*)d_g_v + (size_t)dst * 96 + u0 * 3);
    float4 v0 = __ldg(vp),     v1 = __ldg(vp + 1), v2 = __ldg(vp + 2);
    float4 v3 = __ldg(vp + 3), v4 = __ldg(vp + 4), v5 = __ldg(vp + 5);
    float vv[24] = {v0.x,v0.y,v0.z,v0.w, v1.x,v1.y,v1.z,v1.w,
                    v2.x,v2.y,v2.z,v2.w, v3.x,v3.y,v3.z,v3.w,
                    v4.x,v4.y,v4.z,v4.w, v5.x,v5.y,v5.z,v5.w};
    float mx[8], my[8], mz[8];
#pragma unroll
    for (int q = 0; q < 8; ++q) {
        float vx = vv[q*3], vy = vv[q*3+1], vz = vv[q*3+2];
        mx[q] = w[q] * (vy*sh.w - vz*sh.z);
        my[q] = w[q] * (vz*sh.y - vx*sh.w);
        mz[q] = w[q] * (vx*sh.z - vy*sh.y);
    }
    float* nvp = (float*)d_g_nv + (size_t)src * 384;
    red4(nvp +          96 + u0,     mx[0], mx[1], mx[2], mx[3]);
    red4(nvp +          96 + u0 + 4, mx[4], mx[5], mx[6], mx[7]);
    red4(nvp + 128 +    96 + u0,     my[0], my[1], my[2], my[3]);
    red4(nvp + 128 +    96 + u0 + 4, my[4], my[5], my[6], my[7]);
    red4(nvp + 256 +    96 + u0,     mz[0], mz[1], mz[2], mz[3]);
    red4(nvp + 256 +    96 + u0 + 4, mz[4], mz[5], mz[6], mz[7]);
}

// ---------------- kernel 0: zero accumulators + prescale weights ------------
__global__ void k_pre(const float* __restrict__ Wfc1,
                      const float* __restrict__ Wfc2,
                      const float* __restrict__ Wfc3) {
    int i = blockIdx.x * 256 + threadIdx.x;
    const int NZ = NN * 120;   // float4 count of (ns + nv)
    if (i < NZ) {
        float4 z = make_float4(0.f, 0.f, 0.f, 0.f);
        if (i < NN * 24) d_g_ns[i] = z;
        else             d_g_nv[i - NN * 24] = z;
    } else {
        int j = i - NZ;
        if (j < 512) {
            d_W1K[j] = Wfc1[j] * 0.3535533906f;
        } else if (j < 4608) {
            d_W2K[j - 512] = Wfc2[j - 512] * 0.125f;
        } else if (j < 4608 + 16384) {
            int m = j - 4608;
            int k = m >> 8, col = m & 255;
            float v = 0.f;
            if (col < 224) {
                float s = 0.03125f;  // (1/sqrt(64)) * (1/sqrt(16))
                if (col >= 192)      s *= INV_SQRT2;
                else if (col >= 160) s *= INV_SQRT3;
                v = Wfc3[k * 224 + col] * s;
            }
            d_W3K[m] = v;
        }
    }
}

// ---------------- kernel 2: node prep, persistent warp-per-node -------------
__global__ void __launch_bounds__(256) k_prep(const float* __restrict__ nh,
                                              const float* __restrict__ W1_0,
                                              const float* __restrict__ W1_1,
                                              const float* __restrict__ Wsc0,
                                              const float* __restrict__ Wsc1) {
    __shared__ float sW10[4096], sWsc0[4096], sW11[1024], sWsc1[1024], sIn[1280];
    int t = threadIdx.x;
    for (int i = t; i < 4096; i += 256) { sW10[i] = W1_0[i]; sWsc0[i] = Wsc0[i]; }
    for (int i = t; i < 1024; i += 256) { sW11[i] = W1_1[i]; sWsc1[i] = Wsc1[i]; }
    __syncthreads();

    int wid = t >> 5, l = t & 31;
    float* gs  = (float*)d_g_s;
    float* gv  = (float*)d_g_v;
    float* gss = (float*)d_g_scs;
    float* gsv = (float*)d_g_scv;
    float* row = sIn + wid * 160;

    for (int it = 0; it < 8; ++it) {
        int n = blockIdx.x * 64 + it * 8 + wid;
        if (n >= NN) break;
        {
            const float4* src = reinterpret_cast<const float4*>(nh + (size_t)n * 160);
            float4* dst = reinterpret_cast<float4*>(row);
            for (int i = l; i < 40; i += 32) dst[i] = __ldg(src + i);
        }
        __syncwarp();
#pragma unroll
        for (int r = 0; r < 2; ++r) {
            int o = l + r * 32;
            float a = 0.f, b = 0.f;
#pragma unroll 8
            for (int u = 0; u < 64; ++u) {
                float x = row[u];
                a += x * sW10[u * 64 + o];
                b += x * sWsc0[u * 64 + o];
            }
            gs [(size_t)n * 64 + o] = a * 0.125f;
            gss[(size_t)n * 64 + o] = b * 0.125f;
        }
#pragma unroll
        for (int r = 0; r < 3; ++r) {
            int o = l + r * 32;
            int up = o / 3, c = o - up * 3;
            float a = 0.f, b = 0.f;
#pragma unroll 8
            for (int u = 0; u < 32; ++u) {
                float x = row[64 + u * 3 + c];
                a += x * sW11[u * 32 + up];
                b += x * sWsc1[u * 32 + up];
            }
            gv [(size_t)n * 96 + o] = a * 0.1767766953f;
            gsv[(size_t)n * 96 + o] = b * 0.1767766953f;
        }
        __syncwarp();
    }
}

// ---------------- kernel 3: fused GEMM + register consume, cp.async --------
// smem: buf0 4096 | buf1 4096 | sB 8192 = 16384 fl = 65536 B -> 3 blocks/SM.
// Wc chunks double-buffered via cp.async; consume loops fully unrolled.
__global__ void __launch_bounds__(128, 3) k_edge(const int* __restrict__ ei,
                                                 const float* __restrict__ esh,
                                                 const float* __restrict__ eattr) {
    extern __shared__ float sm[];
    float* sB = sm + 8192;   // 8192: att -> h1 -> h2
    int t = threadIdx.x;
    int jt = t & 7, et = t >> 3;
    int ebase = blockIdx.x * 128;   // NE = 3125*128 exactly
    unsigned int sA0 = (unsigned int)__cvta_generic_to_shared(sm);

    // stage att transposed [k][e] into sB; W1K into buf1 (direct)
    {
        int e = ebase + t;
        const float4* ap = reinterpret_cast<const float4*>(eattr + (size_t)e * 8);
        float4 a0 = __ldg(ap), a1 = __ldg(ap + 1);
        sB[0*128+t] = a0.x; sB[1*128+t] = a0.y;
        sB[2*128+t] = a0.z; sB[3*128+t] = a0.w;
        sB[4*128+t] = a1.x; sB[5*128+t] = a1.y;
        sB[6*128+t] = a1.z; sB[7*128+t] = a1.w;
        for (int i = t; i < 512; i += 128) sm[4096 + i] = d_W1K[i];
    }
    // prefetch W2K -> buf0 (async, hidden under MLP1)
#pragma unroll
    for (int r = 0; r < 8; ++r) {
        int idx = t + 128 * r;           // 1024 x 16B = 16KB
        cpa16(sA0 + idx * 16, d_W2K + idx * 4);
    }
    CP_COMMIT();
    __syncthreads();

    unsigned long long acc[32];

    // ---- MLP1: h1 = silu(W1K @ att), W1K @ buf1 ----
    gemm_acc<8>(sm + 4096, sB, acc, jt, et);
    __syncthreads();                 // att + W1K reads done
    store_silu(acc, sB, jt, et);     // h1 -> sB
    // prefetch chunk0 -> buf1 (W1K dead)
#pragma unroll
    for (int r = 0; r < 8; ++r) {
        int idx4 = t + 128 * r;
        int k = idx4 >> 4;
        int jj = (idx4 & 15) * 4;
        cpa16(sA0 + 16384 + (k * 64 + jj) * 4, d_W3K + k * 256 + jj);
    }
    CP_COMMIT();
    CP_WAIT(1);                      // W2K ready; chunk0 in flight
    __syncthreads();                 // h1 + W2K visible

    // ---- MLP2: h2 = silu(W2K @ h1), W2K @ buf0 ----
    gemm_acc<64>(sm, sB, acc, jt, et);
    __syncthreads();                 // h1 reads done
    store_silu(acc, sB, jt, et);     // h2 -> sB (in place)

    // ---- 4 chunks: gemm on buf[(c&1)^1], prefetch c+1 -> buf[c&1] ----
    int e0 = ebase + et * 8;
#pragma unroll 1
    for (int c = 0; c < 4; ++c) {
        CP_WAIT(0);                  // chunk c data landed (this thread)
        __syncthreads();             // visible block-wide (+ h2 on c==0)
        const float* bufc = sm + (((c & 1) ^ 1) ? 4096 : 0);
        gemm_acc<64>(bufc, sB, acc, jt, et);

        if (c < 3) {                 // prefetch chunk c+1 -> buf[c&1]
            unsigned int dstoff = (c & 1) ? 16384u : 0u;
#pragma unroll
            for (int r = 0; r < 8; ++r) {
                int idx4 = t + 128 * r;
                int k = idx4 >> 4;
                int jj = (idx4 & 15) * 4;
                cpa16(sA0 + dstoff + (k * 64 + jj) * 4,
                      d_W3K + k * 256 + 64 * (c + 1) + jj);
            }
            CP_COMMIT();
        }

        // consume: thread owns rows jt*8..jt*8+7, edges e0..e0+7 (unrolled)
#pragma unroll
        for (int i = 0; i < 4; ++i) {
            float wa[8], wb[8];
#pragma unroll
            for (int j = 0; j < 8; ++j) UNPACK2(wa[j], wb[j], acc[j * 4 + i]);
            int ea = e0 + 2 * i, eb = ea + 1;
            if (c == 0) {
                int j0 = jt * 8;
                cons_c0(wa, ea, j0, ei, esh);
                cons_c0(wb, eb, j0, ei, esh);
            } else if (c == 1) {
                int j0 = jt * 8;
                cons_c1(wa, ea, j0, ei, esh);
                cons_c1(wb, eb, j0, ei, esh);
            } else if (c == 2) {
                if (jt < 4) {
                    int u0 = jt * 8;
                    cons_c2a(wa, ea, u0, ei, esh);
                    cons_c2a(wb, eb, u0, ei, esh);
                } else {
                    int u0 = (jt - 4) * 8;
                    cons_c2b(wa, ea, u0, ei, esh);
                    cons_c2b(wb, eb, u0, ei, esh);
                }
            } else {
                if (jt < 4) {
                    int u0 = jt * 8;
                    cons_c3(wa, ea, u0, ei, esh);
                    cons_c3(wb, eb, u0, ei, esh);
                }
            }
        }
        // next iteration's top barrier protects buf reuse; none needed here
    }
}

// ---------------- kernel 4: output projection + skip + RMS, 4 nodes/warp ----
// (unchanged — proven 64us)
__global__ void __launch_bounds__(256) k_out(float* __restrict__ out,
                                             const float* __restrict__ W2_0,
                                             const float* __restrict__ W2_1,
                                             const float* __restrict__ g0,
                                             const float* __restrict__ g1) {
    extern __shared__ float smo[];
    float* sW20 = smo;           // 6144  [k][o], natural layout
    float* sW21 = smo + 6144;    // 4096  [u][u'], natural layout
    float* sG   = smo + 10240;   // 96 (+32 pad)
    float* sBuf = smo + 10368;   // 8 warps * 640
    int t = threadIdx.x;
    for (int i = t; i < 6144; i += 256) sW20[i] = W2_0[i];
    for (int i = t; i < 4096; i += 256) sW21[i] = W2_1[i];
    if (t < 64) sG[t] = g0[t];
    else if (t < 96) sG[t] = g1[t - 64];
    __syncthreads();

    const float* gnsF = (const float*)d_g_ns;
    const float* gnvF = (const float*)d_g_nv;
    const float* gssF = (const float*)d_g_scs;
    const float* gsvF = (const float*)d_g_scv;

    int wid = t >> 5, l = t & 31;
    float* buf = sBuf + wid * 640;     // buf[k*5 + j]

    for (int it = 0; it < 2; ++it) {
        int nb = blockIdx.x * 64 + it * 32 + wid * 4;

        // ======== s section ========
#pragma unroll
        for (int j = 0; j < 4; ++j) {
            int nj = min(nb + j, NN - 1);
#pragma unroll
            for (int m = 0; m < 3; ++m) {
                int k = l + 32 * m;
                buf[k * 5 + j] = __ldg(gnsF + (size_t)nj * 96 + k);
            }
        }
        __syncwarp();

        float as0[4] = {0.f, 0.f, 0.f, 0.f};
        float as1[4] = {0.f, 0.f, 0.f, 0.f};
#pragma unroll 4
        for (int k = 0; k < 96; ++k) {
            float w0 = sW20[k * 64 + l];
            float w1 = sW20[k * 64 + l + 32];
            float a0 = buf[k * 5 + 0], a1 = buf[k * 5 + 1];
            float a2 = buf[k * 5 + 2], a3 = buf[k * 5 + 3];
            as0[0] += a0 * w0; as0[1] += a1 * w0; as0[2] += a2 * w0; as0[3] += a3 * w0;
            as1[0] += a0 * w1; as1[1] += a1 * w1; as1[2] += a2 * w1; as1[3] += a3 * w1;
        }
        __syncwarp();

        float vs0[4], vs1[4], ssq_s[4];
#pragma unroll
        for (int j = 0; j < 4; ++j) {
            int nj = min(nb + j, NN - 1);
            float v0 = as0[j] * 0.1020620726f + __ldg(gssF + (size_t)nj * 64 + l);
            float v1 = as1[j] * 0.1020620726f + __ldg(gssF + (size_t)nj * 64 + l + 32);
            vs0[j] = v0; vs1[j] = v1;
            ssq_s[j] = v0 * v0 + v1 * v1;
        }

        // ======== v sections ========
        float vvs[3][4];
        float ssq_v[4] = {0.f, 0.f, 0.f, 0.f};
#pragma unroll 1
        for (int c = 0; c < 3; ++c) {
#pragma unroll
            for (int j = 0; j < 4; ++j) {
                int nj = min(nb + j, NN - 1);
#pragma unroll
                for (int m = 0; m < 4; ++m) {
                    int u = l + 32 * m;
                    buf[u * 5 + j] = __ldg(gnvF + (size_t)nj * 384 + c * 128 + u);
                }
            }
            __syncwarp();

            float av[4] = {0.f, 0.f, 0.f, 0.f};
#pragma unroll 4
            for (int u = 0; u < 128; ++u) {
                float w = sW21[u * 32 + l];
                av[0] += buf[u * 5 + 0] * w;
                av[1] += buf[u * 5 + 1] * w;
                av[2] += buf[u * 5 + 2] * w;
                av[3] += buf[u * 5 + 3] * w;
            }
            __syncwarp();

            int o = l * 3 + c;
#pragma unroll
            for (int j = 0; j < 4; ++j) {
                int nj = min(nb + j, NN - 1);
                float val = av[j] * 0.0883883476f + __ldg(gsvF + (size_t)nj * 96 + o);
                vvs[c][j] = val;
                ssq_v[j] += val * val;
            }
        }

        // ======== warp reductions + writes ========
#pragma unroll
        for (int d = 16; d; d >>= 1) {
#pragma unroll
            for (int j = 0; j < 4; ++j) {
                ssq_s[j] += __shfl_xor_sync(0xffffffffu, ssq_s[j], d);
                ssq_v[j] += __shfl_xor_sync(0xffffffffu, ssq_v[j], d);
            }
        }
#pragma unroll
        for (int j = 0; j < 4; ++j) {
            int n = nb + j;
            if (n < NN) {
                float rs = rsqrtf(ssq_s[j] * (1.0f / 64.0f) + 1e-5f);
                float rv = rsqrtf(ssq_v[j] * (1.0f / 32.0f) + 1e-5f);
                out[(size_t)n * 160 + l]      = vs0[j] * rs * sG[l];
                out[(size_t)n * 160 + l + 32] = vs1[j] * rs * sG[l + 32];
                float gv = rv * sG[64 + l];
#pragma unroll
                for (int c = 0; c < 3; ++c)
                    out[(size_t)n * 160 + 64 + l * 3 + c] = vvs[c][j] * gv;
            }
        }
        __syncwarp();
    }
}

// ---------------- launch ----------------
extern "C" void kernel_launch(void* const* d_in, const int* in_sizes, int n_in,
                              void* d_out, int out_size) {
    const float* nh    = (const float*)d_in[0];
    const int*   ei    = (const int*)  d_in[1];
    const float* esh   = (const float*)d_in[2];
    const float* eattr = (const float*)d_in[3];
    const float* W1_0  = (const float*)d_in[4];
    const float* W1_1  = (const float*)d_in[5];
    const float* Wfc1  = (const float*)d_in[6];
    const float* Wfc2  = (const float*)d_in[7];
    const float* Wfc3  = (const float*)d_in[8];
    const float* W2_0  = (const float*)d_in[9];
    const float* W2_1  = (const float*)d_in[10];
    const float* Wsc0  = (const float*)d_in[11];
    const float* Wsc1  = (const float*)d_in[12];
    const float* g0    = (const float*)d_in[13];
    const float* g1    = (const float*)d_in[14];
    float* out = (float*)d_out;

    cudaFuncSetAttribute(k_edge, cudaFuncAttributeMaxDynamicSharedMemorySize, 65536);
    cudaFuncSetAttribute(k_out, cudaFuncAttributeMaxDynamicSharedMemorySize, 61952);

    k_pre<<<11802, 256>>>(Wfc1, Wfc2, Wfc3);              // zero + prescale
    k_prep<<<391, 256>>>(nh, W1_0, W1_1, Wsc0, Wsc1);     // 64 nodes/block
    k_edge<<<3125, 128, 65536>>>(ei, esh, eattr);
    k_out<<<391, 256, 61952>>>(out, W2_0, W2_1, g0, g1);  // 64 nodes/block
}

// round 14
// speedup vs baseline: 2.1062x; 1.1544x over previous
#include <cuda_runtime.h>

#define NN 25000
#define NE 400000

#define INV_SQRT3 0.57735026919f
#define INV_SQRT2 0.70710678119f

// ---------------- scratch (device globals; allocation-free) ----------------
__device__ float4 d_g_s  [NN * 16];   // s   = s_in @ W1_0 /8           (N,64)
__device__ float4 d_g_v  [NN * 24];   // v   = v_in . W1_1 /sqrt32      (N,32,3) [u*3+c]
__device__ float4 d_g_scs[NN * 16];   // sc_s                           (N,64)
__device__ float4 d_g_scv[NN * 24];   // sc_v                           (N,96)  [u*3+c]
__device__ float4 d_g_ns [NN * 24];   // scatter accum s-part           (N,96)
__device__ float4 d_g_nv [NN * 96];   // scatter accum v-part           (N,3,128) [c][u]
__device__ float  d_W1K[8 * 64];      // Wfc1 natural [k][j], prescaled 1/sqrt(8)
__device__ float  d_W2K[64 * 64];     // Wfc2 natural [k][j], prescaled 1/8
// Wfc3 PERMUTED layout [k][R], prescaled. R mapping (jtp=R/8 in chunk, q=R%8):
//  chunk0 (R 0:64):    q<4 -> w0[jtp*4+q],      q>=4 -> w1[jtp*4+q-4]
//  chunk1 (R 64:128):  q<4 -> w0[32+jtp*4+q],   q>=4 -> w1[32+jtp*4+q-4]
//  chunk2 (R 128:192): q<4 -> w2[jtp*4+q],      q>=4 -> w3[jtp*4+q-4]
//  chunk3 (R 192:224): identity w4 rows; R>=224 zero (unused)
__device__ float  d_W3K[64 * 256];

// ---------------- f32x2 / async helpers ----------------
#define FMA2(d, a, b) \
    asm("fma.rn.f32x2 %0, %1, %2, %0;" : "+l"(d) : "l"(a), "l"(b))
#define PACK2(d, lo, hi) \
    asm("mov.b64 %0, {%1, %2};" : "=l"(d) : "f"(lo), "f"(hi))
#define UNPACK2(lo, hi, s) \
    asm("mov.b64 {%0, %1}, %2;" : "=f"(lo), "=f"(hi) : "l"(s))

__device__ __forceinline__ void cpa16(unsigned int saddr, const float* g) {
    asm volatile("cp.async.ca.shared.global [%0], [%1], 16;"
                 :: "r"(saddr), "l"(g) : "memory");
}
#define CP_COMMIT() asm volatile("cp.async.commit_group;" ::: "memory")
#define CP_WAIT(n)  asm volatile("cp.async.wait_group %0;" :: "n"(n) : "memory")

__device__ __forceinline__ float silu_f(float x) {
    return x / (1.0f + __expf(-x));
}

__device__ __forceinline__ void red4(float* p, float a, float b, float c, float d) {
    asm volatile("red.global.add.v4.f32 [%0], {%1,%2,%3,%4};"
                 :: "l"(p), "f"(a), "f"(b), "f"(c), "f"(d) : "memory");
}

// ---------------- 8x8 register-tiled GEMM (acc stays in registers) ---------
template <int KLEN>
__device__ __forceinline__ void gemm_acc(const float* __restrict__ sAm,
                                         const float* __restrict__ sBm,
                                         unsigned long long* acc,
                                         int jt, int et) {
    const float* Ap = sAm + jt * 8;
    const float* Bp = sBm + et * 8;
#pragma unroll
    for (int i = 0; i < 32; ++i) acc[i] = 0ull;
#pragma unroll 4
    for (int k = 0; k < KLEN; ++k) {
        float4 a0 = *reinterpret_cast<const float4*>(Ap + k * 64);
        float4 a1 = *reinterpret_cast<const float4*>(Ap + k * 64 + 4);
        ulonglong2 b01 = *reinterpret_cast<const ulonglong2*>(Bp + k * 128);
        ulonglong2 b23 = *reinterpret_cast<const ulonglong2*>(Bp + k * 128 + 4);
        unsigned long long ap;
        PACK2(ap, a0.x, a0.x);
        FMA2(acc[0],  ap, b01.x); FMA2(acc[1],  ap, b01.y);
        FMA2(acc[2],  ap, b23.x); FMA2(acc[3],  ap, b23.y);
        PACK2(ap, a0.y, a0.y);
        FMA2(acc[4],  ap, b01.x); FMA2(acc[5],  ap, b01.y);
        FMA2(acc[6],  ap, b23.x); FMA2(acc[7],  ap, b23.y);
        PACK2(ap, a0.z, a0.z);
        FMA2(acc[8],  ap, b01.x); FMA2(acc[9],  ap, b01.y);
        FMA2(acc[10], ap, b23.x); FMA2(acc[11], ap, b23.y);
        PACK2(ap, a0.w, a0.w);
        FMA2(acc[12], ap, b01.x); FMA2(acc[13], ap, b01.y);
        FMA2(acc[14], ap, b23.x); FMA2(acc[15], ap, b23.y);
        PACK2(ap, a1.x, a1.x);
        FMA2(acc[16], ap, b01.x); FMA2(acc[17], ap, b01.y);
        FMA2(acc[18], ap, b23.x); FMA2(acc[19], ap, b23.y);
        PACK2(ap, a1.y, a1.y);
        FMA2(acc[20], ap, b01.x); FMA2(acc[21], ap, b01.y);
        FMA2(acc[22], ap, b23.x); FMA2(acc[23], ap, b23.y);
        PACK2(ap, a1.z, a1.z);
        FMA2(acc[24], ap, b01.x); FMA2(acc[25], ap, b01.y);
        FMA2(acc[26], ap, b23.x); FMA2(acc[27], ap, b23.y);
        PACK2(ap, a1.w, a1.w);
        FMA2(acc[28], ap, b01.x); FMA2(acc[29], ap, b01.y);
        FMA2(acc[30], ap, b23.x); FMA2(acc[31], ap, b23.y);
    }
}

// 4x8 tile for the 32-row chunk3 (A stride 32)
template <int KLEN>
__device__ __forceinline__ void gemm_acc4(const float* __restrict__ sAm,
                                          const float* __restrict__ sBm,
                                          unsigned long long* acc,
                                          int jt, int et) {
    const float* Ap = sAm + jt * 4;
    const float* Bp = sBm + et * 8;
#pragma unroll
    for (int i = 0; i < 16; ++i) acc[i] = 0ull;
#pragma unroll 4
    for (int k = 0; k < KLEN; ++k) {
        float4 a0 = *reinterpret_cast<const float4*>(Ap + k * 32);
        ulonglong2 b01 = *reinterpret_cast<const ulonglong2*>(Bp + k * 128);
        ulonglong2 b23 = *reinterpret_cast<const ulonglong2*>(Bp + k * 128 + 4);
        unsigned long long ap;
        PACK2(ap, a0.x, a0.x);
        FMA2(acc[0],  ap, b01.x); FMA2(acc[1],  ap, b01.y);
        FMA2(acc[2],  ap, b23.x); FMA2(acc[3],  ap, b23.y);
        PACK2(ap, a0.y, a0.y);
        FMA2(acc[4],  ap, b01.x); FMA2(acc[5],  ap, b01.y);
        FMA2(acc[6],  ap, b23.x); FMA2(acc[7],  ap, b23.y);
        PACK2(ap, a0.z, a0.z);
        FMA2(acc[8],  ap, b01.x); FMA2(acc[9],  ap, b01.y);
        FMA2(acc[10], ap, b23.x); FMA2(acc[11], ap, b23.y);
        PACK2(ap, a0.w, a0.w);
        FMA2(acc[12], ap, b01.x); FMA2(acc[13], ap, b01.y);
        FMA2(acc[14], ap, b23.x); FMA2(acc[15], ap, b23.y);
    }
}

// store acc with silu into sD (stride 128)
__device__ __forceinline__ void store_silu(const unsigned long long* acc,
                                           float* __restrict__ sD,
                                           int jt, int et) {
    float* D = sD + (size_t)(jt * 8) * 128 + et * 8;
#pragma unroll
    for (int j = 0; j < 8; ++j) {
#pragma unroll
        for (int i = 0; i < 4; ++i) {
            float lo, hi;
            UNPACK2(lo, hi, acc[j * 4 + i]);
            unsigned long long p;
            PACK2(p, silu_f(lo), silu_f(hi));
            *reinterpret_cast<unsigned long long*>(D + j * 128 + 2 * i) = p;
        }
    }
}

// ---------------- consume helpers (paired-row layout) ----------------------
// w[0..3] = w0[j0..j0+3], w[4..7] = w1[j0..j0+3]; one sd float4 serves both.
__device__ __forceinline__ void cons_A(const float* w, int e, int j0,
                                       const int* __restrict__ ei,
                                       const float* __restrict__ esh) {
    int src = __ldg(ei + e), dst = __ldg(ei + NE + e);
    float4 sh = __ldg(reinterpret_cast<const float4*>(esh + (size_t)e * 4));
    float4 s = __ldg(reinterpret_cast<const float4*>(
        (const float*)d_g_s + (size_t)dst * 64 + j0));
    float* nsp = (float*)d_g_ns + (size_t)src * 96 + j0;
    red4(nsp, w[0]*s.x*sh.x, w[1]*s.y*sh.x, w[2]*s.z*sh.x, w[3]*s.w*sh.x);
    float a0 = w[4]*s.x, a1 = w[5]*s.y, a2 = w[6]*s.z, a3 = w[7]*s.w;
    float* nvp = (float*)d_g_nv + (size_t)src * 384 + j0;
    red4(nvp,       a0*sh.y, a1*sh.y, a2*sh.y, a3*sh.y);
    red4(nvp + 128, a0*sh.z, a1*sh.z, a2*sh.z, a3*sh.z);
    red4(nvp + 256, a0*sh.w, a1*sh.w, a2*sh.w, a3*sh.w);
}

// w[0..3] = w2[u0..u0+3] (mv1), w[4..7] = w3[u0..u0+3] (m1); one vd gather.
__device__ __forceinline__ void cons_B(const float* w, int e, int u0,
                                       const int* __restrict__ ei,
                                       const float* __restrict__ esh) {
    int src = __ldg(ei + e), dst = __ldg(ei + NE + e);
    float4 sh = __ldg(reinterpret_cast<const float4*>(esh + (size_t)e * 4));
    const float4* vp = reinterpret_cast<const float4*>(
        (const float*)d_g_v + (size_t)dst * 96 + u0 * 3);
    float4 v0 = __ldg(vp), v1 = __ldg(vp + 1), v2 = __ldg(vp + 2);
    float vv[12] = {v0.x,v0.y,v0.z,v0.w, v1.x,v1.y,v1.z,v1.w,
                    v2.x,v2.y,v2.z,v2.w};
    float* nvp = (float*)d_g_nv + (size_t)src * 384;
#pragma unroll
    for (int c = 0; c < 3; ++c) {
        red4(nvp + c*128 + 64 + u0,
             w[0]*vv[0+c]*sh.x, w[1]*vv[3+c]*sh.x,
             w[2]*vv[6+c]*sh.x, w[3]*vv[9+c]*sh.x);
    }
    float m[4];
#pragma unroll
    for (int q = 0; q < 4; ++q)
        m[q] = w[4+q] * (vv[q*3]*sh.y + vv[q*3+1]*sh.z + vv[q*3+2]*sh.w);
    red4((float*)d_g_ns + (size_t)src * 96 + 64 + u0, m[0], m[1], m[2], m[3]);
}

// w[0..3] = w4[u0..u0+3] (mv2 cross)
__device__ __forceinline__ void cons_C(const float* w, int e, int u0,
                                       const int* __restrict__ ei,
                                       const float* __restrict__ esh) {
    int src = __ldg(ei + e), dst = __ldg(ei + NE + e);
    float4 sh = __ldg(reinterpret_cast<const float4*>(esh + (size_t)e * 4));
    const float4* vp = reinterpret_cast<const float4*>(
        (const float*)d_g_v + (size_t)dst * 96 + u0 * 3);
    float4 v0 = __ldg(vp), v1 = __ldg(vp + 1), v2 = __ldg(vp + 2);
    float vv[12] = {v0.x,v0.y,v0.z,v0.w, v1.x,v1.y,v1.z,v1.w,
                    v2.x,v2.y,v2.z,v2.w};
    float mx[4], my[4], mz[4];
#pragma unroll
    for (int q = 0; q < 4; ++q) {
        float vx = vv[q*3], vy = vv[q*3+1], vz = vv[q*3+2];
        mx[q] = w[q] * (vy*sh.w - vz*sh.z);
        my[q] = w[q] * (vz*sh.y - vx*sh.w);
        mz[q] = w[q] * (vx*sh.z - vy*sh.y);
    }
    float* nvp = (float*)d_g_nv + (size_t)src * 384;
    red4(nvp +       96 + u0, mx[0], mx[1], mx[2], mx[3]);
    red4(nvp + 128 + 96 + u0, my[0], my[1], my[2], my[3]);
    red4(nvp + 256 + 96 + u0, mz[0], mz[1], mz[2], mz[3]);
}

// ---------------- kernel 0: zero accumulators + prescale/permute weights ----
__global__ void k_pre(const float* __restrict__ Wfc1,
                      const float* __restrict__ Wfc2,
                      const float* __restrict__ Wfc3) {
    int i = blockIdx.x * 256 + threadIdx.x;
    const int NZ = NN * 120;   // float4 count of (ns + nv)
    if (i < NZ) {
        float4 z = make_float4(0.f, 0.f, 0.f, 0.f);
        if (i < NN * 24) d_g_ns[i] = z;
        else             d_g_nv[i - NN * 24] = z;
    } else {
        int j = i - NZ;
        if (j < 512) {
            d_W1K[j] = Wfc1[j] * 0.3535533906f;
        } else if (j < 4608) {
            d_W2K[j - 512] = Wfc2[j - 512] * 0.125f;
        } else if (j < 4608 + 16384) {
            int m = j - 4608;
            int k = m >> 8, R = m & 255;
            int orig = -1;
            if (R < 192) {
                int chunk = R >> 6, r = R & 63, jtp = r >> 3, q = r & 7;
                int fh, sh2;
                if (chunk == 0)      { fh = 0;   sh2 = 64;  }
                else if (chunk == 1) { fh = 32;  sh2 = 96;  }
                else                 { fh = 128; sh2 = 160; }
                orig = (q < 4) ? (fh + jtp * 4 + q) : (sh2 + jtp * 4 + q - 4);
            } else if (R < 224) {
                orig = R;   // w4 rows, identity
            }
            float v = 0.f;
            if (orig >= 0) {
                float s = 0.03125f;  // (1/sqrt(64)) * (1/sqrt(16))
                if (orig >= 192)      s *= INV_SQRT2;
                else if (orig >= 160) s *= INV_SQRT3;
                v = Wfc3[k * 224 + orig] * s;
            }
            d_W3K[m] = v;
        }
    }
}

// ---------------- kernel 2: node prep, persistent warp-per-node -------------
__global__ void __launch_bounds__(256) k_prep(const float* __restrict__ nh,
                                              const float* __restrict__ W1_0,
                                              const float* __restrict__ W1_1,
                                              const float* __restrict__ Wsc0,
                                              const float* __restrict__ Wsc1) {
    __shared__ float sW10[4096], sWsc0[4096], sW11[1024], sWsc1[1024], sIn[1280];
    int t = threadIdx.x;
    for (int i = t; i < 4096; i += 256) { sW10[i] = W1_0[i]; sWsc0[i] = Wsc0[i]; }
    for (int i = t; i < 1024; i += 256) { sW11[i] = W1_1[i]; sWsc1[i] = Wsc1[i]; }
    __syncthreads();

    int wid = t >> 5, l = t & 31;
    float* gs  = (float*)d_g_s;
    float* gv  = (float*)d_g_v;
    float* gss = (float*)d_g_scs;
    float* gsv = (float*)d_g_scv;
    float* row = sIn + wid * 160;

    for (int it = 0; it < 8; ++it) {
        int n = blockIdx.x * 64 + it * 8 + wid;
        if (n >= NN) break;
        {
            const float4* src = reinterpret_cast<const float4*>(nh + (size_t)n * 160);
            float4* dst = reinterpret_cast<float4*>(row);
            for (int i = l; i < 40; i += 32) dst[i] = __ldg(src + i);
        }
        __syncwarp();
#pragma unroll
        for (int r = 0; r < 2; ++r) {
            int o = l + r * 32;
            float a = 0.f, b = 0.f;
#pragma unroll 8
            for (int u = 0; u < 64; ++u) {
                float x = row[u];
                a += x * sW10[u * 64 + o];
                b += x * sWsc0[u * 64 + o];
            }
            gs [(size_t)n * 64 + o] = a * 0.125f;
            gss[(size_t)n * 64 + o] = b * 0.125f;
        }
#pragma unroll
        for (int r = 0; r < 3; ++r) {
            int o = l + r * 32;
            int up = o / 3, c = o - up * 3;
            float a = 0.f, b = 0.f;
#pragma unroll 8
            for (int u = 0; u < 32; ++u) {
                float x = row[64 + u * 3 + c];
                a += x * sW11[u * 32 + up];
                b += x * sWsc1[u * 32 + up];
            }
            gv [(size_t)n * 96 + o] = a * 0.1767766953f;
            gsv[(size_t)n * 96 + o] = b * 0.1767766953f;
        }
        __syncwarp();
    }
}

// ---------------- kernel 3: fused GEMM + register consume, cp.async --------
// smem: buf0 4096 | buf1 4096 | sB 8192 = 16384 fl = 65536 B -> 3 blocks/SM.
__global__ void __launch_bounds__(128, 3) k_edge(const int* __restrict__ ei,
                                                 const float* __restrict__ esh,
                                                 const float* __restrict__ eattr) {
    extern __shared__ float sm[];
    float* sB = sm + 8192;   // 8192: att -> h1 -> h2
    int t = threadIdx.x;
    int jt = t & 7, et = t >> 3;
    int ebase = blockIdx.x * 128;   // NE = 3125*128 exactly
    unsigned int sA0 = (unsigned int)__cvta_generic_to_shared(sm);

    // stage att transposed [k][e] into sB; W1K into buf1 (direct)
    {
        int e = ebase + t;
        const float4* ap = reinterpret_cast<const float4*>(eattr + (size_t)e * 8);
        float4 a0 = __ldg(ap), a1 = __ldg(ap + 1);
        sB[0*128+t] = a0.x; sB[1*128+t] = a0.y;
        sB[2*128+t] = a0.z; sB[3*128+t] = a0.w;
        sB[4*128+t] = a1.x; sB[5*128+t] = a1.y;
        sB[6*128+t] = a1.z; sB[7*128+t] = a1.w;
        for (int i = t; i < 512; i += 128) sm[4096 + i] = d_W1K[i];
    }
    // prefetch W2K -> buf0 (async, hidden under MLP1)
#pragma unroll
    for (int r = 0; r < 8; ++r) {
        int idx = t + 128 * r;           // 1024 x 16B = 16KB
        cpa16(sA0 + idx * 16, d_W2K + idx * 4);
    }
    CP_COMMIT();
    __syncthreads();

    unsigned long long acc[32];

    // ---- MLP1: h1 = silu(W1K @ att) ----
    gemm_acc<8>(sm + 4096, sB, acc, jt, et);
    __syncthreads();                 // att + W1K reads done
    store_silu(acc, sB, jt, et);     // h1 -> sB
    // prefetch chunk0 -> buf1 (W1K dead)
#pragma unroll
    for (int r = 0; r < 8; ++r) {
        int idx4 = t + 128 * r;
        int k = idx4 >> 4;
        int jj = (idx4 & 15) * 4;
        cpa16(sA0 + 16384 + (k * 64 + jj) * 4, d_W3K + k * 256 + jj);
    }
    CP_COMMIT();
    CP_WAIT(1);                      // W2K ready; chunk0 in flight
    __syncthreads();                 // h1 + W2K visible

    // ---- MLP2: h2 = silu(W2K @ h1) ----
    gemm_acc<64>(sm, sB, acc, jt, et);
    __syncthreads();                 // h1 reads done
    store_silu(acc, sB, jt, et);     // h2 -> sB (in place)

    // ---- 4 chunks: gemm on alternating buf, prefetch c+1, consume regs ----
    int e0 = ebase + et * 8;
    int j0 = jt * 4;
#pragma unroll 1
    for (int c = 0; c < 4; ++c) {
        CP_WAIT(0);                  // chunk c data landed (this thread)
        __syncthreads();             // visible block-wide (+ h2 on c==0)
        const float* bufc = sm + ((c & 1) ? 0 : 4096);
        if (c < 3) gemm_acc<64>(bufc, sB, acc, jt, et);
        else       gemm_acc4<64>(bufc, sB, acc, jt, et);

        if (c < 2) {                 // prefetch full chunk c+1 (64x64)
            unsigned int dstoff = (c & 1) ? 16384u : 0u;
#pragma unroll
            for (int r = 0; r < 8; ++r) {
                int idx4 = t + 128 * r;
                int k = idx4 >> 4;
                int jj = (idx4 & 15) * 4;
                cpa16(sA0 + dstoff + (k * 64 + jj) * 4,
                      d_W3K + k * 256 + 64 * (c + 1) + jj);
            }
            CP_COMMIT();
        } else if (c == 2) {         // prefetch chunk3 (64x32, stride 32)
#pragma unroll
            for (int r = 0; r < 4; ++r) {
                int idx4 = t + 128 * r;
                int k = idx4 >> 3;
                int jj = (idx4 & 7) * 4;
                cpa16(sA0 + (k * 32 + jj) * 4, d_W3K + k * 256 + 192 + jj);
            }
            CP_COMMIT();
        }

        // consume: thread owns paired rows (j0 / j0+32 etc.), edges e0..e0+7
#pragma unroll
        for (int i = 0; i < 4; ++i) {
            float wa[8], wb[8];
            if (c < 3) {
#pragma unroll
                for (int j = 0; j < 8; ++j) UNPACK2(wa[j], wb[j], acc[j * 4 + i]);
            } else {
#pragma unroll
                for (int j = 0; j < 4; ++j) UNPACK2(wa[j], wb[j], acc[j * 4 + i]);
            }
            int ea = e0 + 2 * i, eb = ea + 1;
            if (c == 0) {
                cons_A(wa, ea, j0, ei, esh);
                cons_A(wb, eb, j0, ei, esh);
            } else if (c == 1) {
                cons_A(wa, ea, j0 + 32, ei, esh);
                cons_A(wb, eb, j0 + 32, ei, esh);
            } else if (c == 2) {
                cons_B(wa, ea, j0, ei, esh);
                cons_B(wb, eb, j0, ei, esh);
            } else {
                cons_C(wa, ea, j0, ei, esh);
                cons_C(wb, eb, j0, ei, esh);
            }
        }
    }
}

// ---------------- kernel 4: output projection + skip + RMS, 4 nodes/warp ----
// (unchanged — proven 64us)
__global__ void __launch_bounds__(256) k_out(float* __restrict__ out,
                                             const float* __restrict__ W2_0,
                                             const float* __restrict__ W2_1,
                                             const float* __restrict__ g0,
                                             const float* __restrict__ g1) {
    extern __shared__ float smo[];
    float* sW20 = smo;           // 6144  [k][o], natural layout
    float* sW21 = smo + 6144;    // 4096  [u][u'], natural layout
    float* sG   = smo + 10240;   // 96 (+32 pad)
    float* sBuf = smo + 10368;   // 8 warps * 640
    int t = threadIdx.x;
    for (int i = t; i < 6144; i += 256) sW20[i] = W2_0[i];
    for (int i = t; i < 4096; i += 256) sW21[i] = W2_1[i];
    if (t < 64) sG[t] = g0[t];
    else if (t < 96) sG[t] = g1[t - 64];
    __syncthreads();

    const float* gnsF = (const float*)d_g_ns;
    const float* gnvF = (const float*)d_g_nv;
    const float* gssF = (const float*)d_g_scs;
    const float* gsvF = (const float*)d_g_scv;

    int wid = t >> 5, l = t & 31;
    float* buf = sBuf + wid * 640;     // buf[k*5 + j]

    for (int it = 0; it < 2; ++it) {
        int nb = blockIdx.x * 64 + it * 32 + wid * 4;

        // ======== s section ========
#pragma unroll
        for (int j = 0; j < 4; ++j) {
            int nj = min(nb + j, NN - 1);
#pragma unroll
            for (int m = 0; m < 3; ++m) {
                int k = l + 32 * m;
                buf[k * 5 + j] = __ldg(gnsF + (size_t)nj * 96 + k);
            }
        }
        __syncwarp();

        float as0[4] = {0.f, 0.f, 0.f, 0.f};
        float as1[4] = {0.f, 0.f, 0.f, 0.f};
#pragma unroll 4
        for (int k = 0; k < 96; ++k) {
            float w0 = sW20[k * 64 + l];
            float w1 = sW20[k * 64 + l + 32];
            float a0 = buf[k * 5 + 0], a1 = buf[k * 5 + 1];
            float a2 = buf[k * 5 + 2], a3 = buf[k * 5 + 3];
            as0[0] += a0 * w0; as0[1] += a1 * w0; as0[2] += a2 * w0; as0[3] += a3 * w0;
            as1[0] += a0 * w1; as1[1] += a1 * w1; as1[2] += a2 * w1; as1[3] += a3 * w1;
        }
        __syncwarp();

        float vs0[4], vs1[4], ssq_s[4];
#pragma unroll
        for (int j = 0; j < 4; ++j) {
            int nj = min(nb + j, NN - 1);
            float v0 = as0[j] * 0.1020620726f + __ldg(gssF + (size_t)nj * 64 + l);
            float v1 = as1[j] * 0.1020620726f + __ldg(gssF + (size_t)nj * 64 + l + 32);
            vs0[j] = v0; vs1[j] = v1;
            ssq_s[j] = v0 * v0 + v1 * v1;
        }

        // ======== v sections ========
        float vvs[3][4];
        float ssq_v[4] = {0.f, 0.f, 0.f, 0.f};
#pragma unroll 1
        for (int c = 0; c < 3; ++c) {
#pragma unroll
            for (int j = 0; j < 4; ++j) {
                int nj = min(nb + j, NN - 1);
#pragma unroll
                for (int m = 0; m < 4; ++m) {
                    int u = l + 32 * m;
                    buf[u * 5 + j] = __ldg(gnvF + (size_t)nj * 384 + c * 128 + u);
                }
            }
            __syncwarp();

            float av[4] = {0.f, 0.f, 0.f, 0.f};
#pragma unroll 4
            for (int u = 0; u < 128; ++u) {
                float w = sW21[u * 32 + l];
                av[0] += buf[u * 5 + 0] * w;
                av[1] += buf[u * 5 + 1] * w;
                av[2] += buf[u * 5 + 2] * w;
                av[3] += buf[u * 5 + 3] * w;
            }
            __syncwarp();

            int o = l * 3 + c;
#pragma unroll
            for (int j = 0; j < 4; ++j) {
                int nj = min(nb + j, NN - 1);
                float val = av[j] * 0.0883883476f + __ldg(gsvF + (size_t)nj * 96 + o);
                vvs[c][j] = val;
                ssq_v[j] += val * val;
            }
        }

        // ======== warp reductions + writes ========
#pragma unroll
        for (int d = 16; d; d >>= 1) {
#pragma unroll
            for (int j = 0; j < 4; ++j) {
                ssq_s[j] += __shfl_xor_sync(0xffffffffu, ssq_s[j], d);
                ssq_v[j] += __shfl_xor_sync(0xffffffffu, ssq_v[j], d);
            }
        }
#pragma unroll
        for (int j = 0; j < 4; ++j) {
            int n = nb + j;
            if (n < NN) {
                float rs = rsqrtf(ssq_s[j] * (1.0f / 64.0f) + 1e-5f);
                float rv = rsqrtf(ssq_v[j] * (1.0f / 32.0f) + 1e-5f);
                out[(size_t)n * 160 + l]      = vs0[j] * rs * sG[l];
                out[(size_t)n * 160 + l + 32] = vs1[j] * rs * sG[l + 32];
                float gv = rv * sG[64 + l];
#pragma unroll
                for (int c = 0; c < 3; ++c)
                    out[(size_t)n * 160 + 64 + l * 3 + c] = vvs[c][j] * gv;
            }
        }
        __syncwarp();
    }
}

// ---------------- launch ----------------
extern "C" void kernel_launch(void* const* d_in, const int* in_sizes, int n_in,
                              void* d_out, int out_size) {
    const float* nh    = (const float*)d_in[0];
    const int*   ei    = (const int*)  d_in[1];
    const float* esh   = (const float*)d_in[2];
    const float* eattr = (const float*)d_in[3];
    const float* W1_0  = (const float*)d_in[4];
    const float* W1_1  = (const float*)d_in[5];
    const float* Wfc1  = (const float*)d_in[6];
    const float* Wfc2  = (const float*)d_in[7];
    const float* Wfc3  = (const float*)d_in[8];
    const float* W2_0  = (const float*)d_in[9];
    const float* W2_1  = (const float*)d_in[10];
    const float* Wsc0  = (const float*)d_in[11];
    const float* Wsc1  = (const float*)d_in[12];
    const float* g0    = (const float*)d_in[13];
    const float* g1    = (const float*)d_in[14];
    float* out = (float*)d_out;

    cudaFuncSetAttribute(k_edge, cudaFuncAttributeMaxDynamicSharedMemorySize, 65536);
    cudaFuncSetAttribute(k_out, cudaFuncAttributeMaxDynamicSharedMemorySize, 61952);

    k_pre<<<11802, 256>>>(Wfc1, Wfc2, Wfc3);              // zero + prescale/permute
    k_prep<<<391, 256>>>(nh, W1_0, W1_1, Wsc0, Wsc1);     // 64 nodes/block
    k_edge<<<3125, 128, 65536>>>(ei, esh, eattr);
    k_out<<<391, 256, 61952>>>(out, W2_0, W2_1, g0, g1);  // 64 nodes/block
}

// round 15
// speedup vs baseline: 2.1177x; 1.0055x over previous
#include <cuda_runtime.h>

#define NN 25000
#define NE 400000

#define INV_SQRT3 0.57735026919f
#define INV_SQRT2 0.70710678119f

// ---------------- scratch (device globals; allocation-free) ----------------
__device__ float4 d_g_s  [NN * 16];   // s   = s_in @ W1_0 /8           (N,64)
__device__ float4 d_g_v  [NN * 24];   // v   = v_in . W1_1 /sqrt32      (N,32,3) [u*3+c]
__device__ float4 d_g_scs[NN * 16];   // sc_s                           (N,64)
__device__ float4 d_g_scv[NN * 24];   // sc_v                           (N,96)  [u*3+c]
__device__ float4 d_g_ns [NN * 24];   // scatter accum s-part           (N,96)
__device__ float4 d_g_nv [NN * 96];   // scatter accum v-part           (N,3,128) [c][u]
__device__ float  d_W1K[8 * 64];      // Wfc1 natural [k][j], prescaled 1/sqrt(8)
__device__ float  d_W2K[64 * 64];     // Wfc2 natural [k][j], prescaled 1/8
// Wfc3 PERMUTED layout [k][R], prescaled (see R14 mapping).
__device__ float  d_W3K[64 * 256];

// ---------------- f32x2 / async helpers ----------------
#define FMA2(d, a, b) \
    asm("fma.rn.f32x2 %0, %1, %2, %0;" : "+l"(d) : "l"(a), "l"(b))
#define PACK2(d, lo, hi) \
    asm("mov.b64 %0, {%1, %2};" : "=l"(d) : "f"(lo), "f"(hi))
#define UNPACK2(lo, hi, s) \
    asm("mov.b64 {%0, %1}, %2;" : "=f"(lo), "=f"(hi) : "l"(s))

__device__ __forceinline__ void cpa16(unsigned int saddr, const float* g) {
    asm volatile("cp.async.ca.shared.global [%0], [%1], 16;"
                 :: "r"(saddr), "l"(g) : "memory");
}
#define CP_COMMIT() asm volatile("cp.async.commit_group;" ::: "memory")
#define CP_WAIT(n)  asm volatile("cp.async.wait_group %0;" :: "n"(n) : "memory")

__device__ __forceinline__ float silu_f(float x) {
    return x / (1.0f + __expf(-x));
}

__device__ __forceinline__ void red4(float* p, float a, float b, float c, float d) {
    asm volatile("red.global.add.v4.f32 [%0], {%1,%2,%3,%4};"
                 :: "l"(p), "f"(a), "f"(b), "f"(c), "f"(d) : "memory");
}

// ---------------- 8x8 register-tiled GEMM (acc stays in registers) ---------
template <int KLEN>
__device__ __forceinline__ void gemm_acc(const float* __restrict__ sAm,
                                         const float* __restrict__ sBm,
                                         unsigned long long* acc,
                                         int jt, int et) {
    const float* Ap = sAm + jt * 8;
    const float* Bp = sBm + et * 8;
#pragma unroll
    for (int i = 0; i < 32; ++i) acc[i] = 0ull;
#pragma unroll 4
    for (int k = 0; k < KLEN; ++k) {
        float4 a0 = *reinterpret_cast<const float4*>(Ap + k * 64);
        float4 a1 = *reinterpret_cast<const float4*>(Ap + k * 64 + 4);
        ulonglong2 b01 = *reinterpret_cast<const ulonglong2*>(Bp + k * 128);
        ulonglong2 b23 = *reinterpret_cast<const ulonglong2*>(Bp + k * 128 + 4);
        unsigned long long ap;
        PACK2(ap, a0.x, a0.x);
        FMA2(acc[0],  ap, b01.x); FMA2(acc[1],  ap, b01.y);
        FMA2(acc[2],  ap, b23.x); FMA2(acc[3],  ap, b23.y);
        PACK2(ap, a0.y, a0.y);
        FMA2(acc[4],  ap, b01.x); FMA2(acc[5],  ap, b01.y);
        FMA2(acc[6],  ap, b23.x); FMA2(acc[7],  ap, b23.y);
        PACK2(ap, a0.z, a0.z);
        FMA2(acc[8],  ap, b01.x); FMA2(acc[9],  ap, b01.y);
        FMA2(acc[10], ap, b23.x); FMA2(acc[11], ap, b23.y);
        PACK2(ap, a0.w, a0.w);
        FMA2(acc[12], ap, b01.x); FMA2(acc[13], ap, b01.y);
        FMA2(acc[14], ap, b23.x); FMA2(acc[15], ap, b23.y);
        PACK2(ap, a1.x, a1.x);
        FMA2(acc[16], ap, b01.x); FMA2(acc[17], ap, b01.y);
        FMA2(acc[18], ap, b23.x); FMA2(acc[19], ap, b23.y);
        PACK2(ap, a1.y, a1.y);
        FMA2(acc[20], ap, b01.x); FMA2(acc[21], ap, b01.y);
        FMA2(acc[22], ap, b23.x); FMA2(acc[23], ap, b23.y);
        PACK2(ap, a1.z, a1.z);
        FMA2(acc[24], ap, b01.x); FMA2(acc[25], ap, b01.y);
        FMA2(acc[26], ap, b23.x); FMA2(acc[27], ap, b23.y);
        PACK2(ap, a1.w, a1.w);
        FMA2(acc[28], ap, b01.x); FMA2(acc[29], ap, b01.y);
        FMA2(acc[30], ap, b23.x); FMA2(acc[31], ap, b23.y);
    }
}

// 4x8 tile for the 32-row chunk3 (A stride 32)
template <int KLEN>
__device__ __forceinline__ void gemm_acc4(const float* __restrict__ sAm,
                                          const float* __restrict__ sBm,
                                          unsigned long long* acc,
                                          int jt, int et) {
    const float* Ap = sAm + jt * 4;
    const float* Bp = sBm + et * 8;
#pragma unroll
    for (int i = 0; i < 16; ++i) acc[i] = 0ull;
#pragma unroll 4
    for (int k = 0; k < KLEN; ++k) {
        float4 a0 = *reinterpret_cast<const float4*>(Ap + k * 32);
        ulonglong2 b01 = *reinterpret_cast<const ulonglong2*>(Bp + k * 128);
        ulonglong2 b23 = *reinterpret_cast<const ulonglong2*>(Bp + k * 128 + 4);
        unsigned long long ap;
        PACK2(ap, a0.x, a0.x);
        FMA2(acc[0],  ap, b01.x); FMA2(acc[1],  ap, b01.y);
        FMA2(acc[2],  ap, b23.x); FMA2(acc[3],  ap, b23.y);
        PACK2(ap, a0.y, a0.y);
        FMA2(acc[4],  ap, b01.x); FMA2(acc[5],  ap, b01.y);
        FMA2(acc[6],  ap, b23.x); FMA2(acc[7],  ap, b23.y);
        PACK2(ap, a0.z, a0.z);
        FMA2(acc[8],  ap, b01.x); FMA2(acc[9],  ap, b01.y);
        FMA2(acc[10], ap, b23.x); FMA2(acc[11], ap, b23.y);
        PACK2(ap, a0.w, a0.w);
        FMA2(acc[12], ap, b01.x); FMA2(acc[13], ap, b01.y);
        FMA2(acc[14], ap, b23.x); FMA2(acc[15], ap, b23.y);
    }
}

// store acc with silu into sD (stride 128)
__device__ __forceinline__ void store_silu(const unsigned long long* acc,
                                           float* __restrict__ sD,
                                           int jt, int et) {
    float* D = sD + (size_t)(jt * 8) * 128 + et * 8;
#pragma unroll
    for (int j = 0; j < 8; ++j) {
#pragma unroll
        for (int i = 0; i < 4; ++i) {
            float lo, hi;
            UNPACK2(lo, hi, acc[j * 4 + i]);
            unsigned long long p;
            PACK2(p, silu_f(lo), silu_f(hi));
            *reinterpret_cast<unsigned long long*>(D + j * 128 + 2 * i) = p;
        }
    }
}

// ---------------- consume helpers (edge data from smem cache) --------------
// w[0..3] = w0[j0..j0+3], w[4..7] = w1[j0..j0+3]; one sd float4 serves both.
__device__ __forceinline__ void cons_A(const float* w, int el, int j0,
                                       const int* sSrc, const int* sDst,
                                       const float4* sSh) {
    int src = sSrc[el], dst = sDst[el];
    float4 sh = sSh[el];
    float4 s = __ldg(reinterpret_cast<const float4*>(
        (const float*)d_g_s + (size_t)dst * 64 + j0));
    float* nsp = (float*)d_g_ns + (size_t)src * 96 + j0;
    red4(nsp, w[0]*s.x*sh.x, w[1]*s.y*sh.x, w[2]*s.z*sh.x, w[3]*s.w*sh.x);
    float a0 = w[4]*s.x, a1 = w[5]*s.y, a2 = w[6]*s.z, a3 = w[7]*s.w;
    float* nvp = (float*)d_g_nv + (size_t)src * 384 + j0;
    red4(nvp,       a0*sh.y, a1*sh.y, a2*sh.y, a3*sh.y);
    red4(nvp + 128, a0*sh.z, a1*sh.z, a2*sh.z, a3*sh.z);
    red4(nvp + 256, a0*sh.w, a1*sh.w, a2*sh.w, a3*sh.w);
}

// w[0..3] = w2[u0..u0+3] (mv1), w[4..7] = w3[u0..u0+3] (m1); one vd gather.
__device__ __forceinline__ void cons_B(const float* w, int el, int u0,
                                       const int* sSrc, const int* sDst,
                                       const float4* sSh) {
    int src = sSrc[el], dst = sDst[el];
    float4 sh = sSh[el];
    const float4* vp = reinterpret_cast<const float4*>(
        (const float*)d_g_v + (size_t)dst * 96 + u0 * 3);
    float4 v0 = __ldg(vp), v1 = __ldg(vp + 1), v2 = __ldg(vp + 2);
    float vv[12] = {v0.x,v0.y,v0.z,v0.w, v1.x,v1.y,v1.z,v1.w,
                    v2.x,v2.y,v2.z,v2.w};
    float* nvp = (float*)d_g_nv + (size_t)src * 384;
#pragma unroll
    for (int c = 0; c < 3; ++c) {
        red4(nvp + c*128 + 64 + u0,
             w[0]*vv[0+c]*sh.x, w[1]*vv[3+c]*sh.x,
             w[2]*vv[6+c]*sh.x, w[3]*vv[9+c]*sh.x);
    }
    float m[4];
#pragma unroll
    for (int q = 0; q < 4; ++q)
        m[q] = w[4+q] * (vv[q*3]*sh.y + vv[q*3+1]*sh.z + vv[q*3+2]*sh.w);
    red4((float*)d_g_ns + (size_t)src * 96 + 64 + u0, m[0], m[1], m[2], m[3]);
}

// w[0..3] = w4[u0..u0+3] (mv2 cross)
__device__ __forceinline__ void cons_C(const float* w, int el, int u0,
                                       const int* sSrc, const int* sDst,
                                       const float4* sSh) {
    int src = sSrc[el], dst = sDst[el];
    float4 sh = sSh[el];
    const float4* vp = reinterpret_cast<const float4*>(
        (const float*)d_g_v + (size_t)dst * 96 + u0 * 3);
    float4 v0 = __ldg(vp), v1 = __ldg(vp + 1), v2 = __ldg(vp + 2);
    float vv[12] = {v0.x,v0.y,v0.z,v0.w, v1.x,v1.y,v1.z,v1.w,
                    v2.x,v2.y,v2.z,v2.w};
    float mx[4], my[4], mz[4];
#pragma unroll
    for (int q = 0; q < 4; ++q) {
        float vx = vv[q*3], vy = vv[q*3+1], vz = vv[q*3+2];
        mx[q] = w[q] * (vy*sh.w - vz*sh.z);
        my[q] = w[q] * (vz*sh.y - vx*sh.w);
        mz[q] = w[q] * (vx*sh.z - vy*sh.y);
    }
    float* nvp = (float*)d_g_nv + (size_t)src * 384;
    red4(nvp +       96 + u0, mx[0], mx[1], mx[2], mx[3]);
    red4(nvp + 128 + 96 + u0, my[0], my[1], my[2], my[3]);
    red4(nvp + 256 + 96 + u0, mz[0], mz[1], mz[2], mz[3]);
}

// ---------------- kernel 1: init (zero + prescale/permute + node prep) ------
// One 391-block launch replaces k_pre + k_prep.
__global__ void __launch_bounds__(256) k_init(const float* __restrict__ nh,
                                              const float* __restrict__ W1_0,
                                              const float* __restrict__ W1_1,
                                              const float* __restrict__ Wsc0,
                                              const float* __restrict__ Wsc1,
                                              const float* __restrict__ Wfc1,
                                              const float* __restrict__ Wfc2,
                                              const float* __restrict__ Wfc3) {
    __shared__ float sW10[4096], sWsc0[4096], sW11[1024], sWsc1[1024], sIn[1280];
    int t = threadIdx.x;
    int gid = blockIdx.x * 256 + t;
    const int GSTRIDE = 391 * 256;

    // --- grid-strided: zero accumulators (3M float4) ---
    {
        float4 z = make_float4(0.f, 0.f, 0.f, 0.f);
        for (int i = gid; i < NN * 120; i += GSTRIDE) {
            if (i < NN * 24) d_g_ns[i] = z;
            else             d_g_nv[i - NN * 24] = z;
        }
    }
    // --- grid-strided: weight prescale + W3 permute (20992 entries) ---
    for (int j = gid; j < 20992; j += GSTRIDE) {
        if (j < 512) {
            d_W1K[j] = Wfc1[j] * 0.3535533906f;
        } else if (j < 4608) {
            d_W2K[j - 512] = Wfc2[j - 512] * 0.125f;
        } else {
            int m = j - 4608;
            int k = m >> 8, R = m & 255;
            int orig = -1;
            if (R < 192) {
                int chunk = R >> 6, r = R & 63, jtp = r >> 3, q = r & 7;
                int fh, sh2;
                if (chunk == 0)      { fh = 0;   sh2 = 64;  }
                else if (chunk == 1) { fh = 32;  sh2 = 96;  }
                else                 { fh = 128; sh2 = 160; }
                orig = (q < 4) ? (fh + jtp * 4 + q) : (sh2 + jtp * 4 + q - 4);
            } else if (R < 224) {
                orig = R;   // w4 rows, identity
            }
            float v = 0.f;
            if (orig >= 0) {
                float s = 0.03125f;  // (1/sqrt(64)) * (1/sqrt(16))
                if (orig >= 192)      s *= INV_SQRT2;
                else if (orig >= 160) s *= INV_SQRT3;
                v = Wfc3[k * 224 + orig] * s;
            }
            d_W3K[m] = v;
        }
    }

    // --- node prep (unchanged from k_prep) ---
    for (int i = t; i < 4096; i += 256) { sW10[i] = W1_0[i]; sWsc0[i] = Wsc0[i]; }
    for (int i = t; i < 1024; i += 256) { sW11[i] = W1_1[i]; sWsc1[i] = Wsc1[i]; }
    __syncthreads();

    int wid = t >> 5, l = t & 31;
    float* gs  = (float*)d_g_s;
    float* gv  = (float*)d_g_v;
    float* gss = (float*)d_g_scs;
    float* gsv = (float*)d_g_scv;
    float* row = sIn + wid * 160;

    for (int it = 0; it < 8; ++it) {
        int n = blockIdx.x * 64 + it * 8 + wid;
        if (n >= NN) break;
        {
            const float4* src = reinterpret_cast<const float4*>(nh + (size_t)n * 160);
            float4* dst = reinterpret_cast<float4*>(row);
            for (int i = l; i < 40; i += 32) dst[i] = __ldg(src + i);
        }
        __syncwarp();
#pragma unroll
        for (int r = 0; r < 2; ++r) {
            int o = l + r * 32;
            float a = 0.f, b = 0.f;
#pragma unroll 8
            for (int u = 0; u < 64; ++u) {
                float x = row[u];
                a += x * sW10[u * 64 + o];
                b += x * sWsc0[u * 64 + o];
            }
            gs [(size_t)n * 64 + o] = a * 0.125f;
            gss[(size_t)n * 64 + o] = b * 0.125f;
        }
#pragma unroll
        for (int r = 0; r < 3; ++r) {
            int o = l + r * 32;
            int up = o / 3, c = o - up * 3;
            float a = 0.f, b = 0.f;
#pragma unroll 8
            for (int u = 0; u < 32; ++u) {
                float x = row[64 + u * 3 + c];
                a += x * sW11[u * 32 + up];
                b += x * sWsc1[u * 32 + up];
            }
            gv [(size_t)n * 96 + o] = a * 0.1767766953f;
            gsv[(size_t)n * 96 + o] = b * 0.1767766953f;
        }
        __syncwarp();
    }
}

// ---------------- kernel 3: fused GEMM + register consume, cp.async --------
// smem floats: buf0 [0,4096) | buf1 [4096,8192) | sB [8192,16384)
//              | sSrc [16384,16512) | sDst [16512,16640) | sSh [16640,17152)
// = 67.0 KB -> 3 blocks/SM.
__global__ void __launch_bounds__(128, 3) k_edge(const int* __restrict__ ei,
                                                 const float* __restrict__ esh,
                                                 const float* __restrict__ eattr) {
    extern __shared__ float sm[];
    float* sB = sm + 8192;
    int* sSrc = (int*)(sm + 16384);
    int* sDst = (int*)(sm + 16512);
    float4* sSh = (float4*)(sm + 16640);
    int t = threadIdx.x;
    int jt = t & 7, et = t >> 3;
    int ebase = blockIdx.x * 128;   // NE = 3125*128 exactly
    unsigned int sA0 = (unsigned int)__cvta_generic_to_shared(sm);

    // stage att transposed [k][e] into sB; edge data into cache; W1K into buf1
    {
        int e = ebase + t;
        const float4* ap = reinterpret_cast<const float4*>(eattr + (size_t)e * 8);
        float4 a0 = __ldg(ap), a1 = __ldg(ap + 1);
        sB[0*128+t] = a0.x; sB[1*128+t] = a0.y;
        sB[2*128+t] = a0.z; sB[3*128+t] = a0.w;
        sB[4*128+t] = a1.x; sB[5*128+t] = a1.y;
        sB[6*128+t] = a1.z; sB[7*128+t] = a1.w;
        sSrc[t] = __ldg(ei + e);
        sDst[t] = __ldg(ei + NE + e);
        sSh[t]  = __ldg(reinterpret_cast<const float4*>(esh + (size_t)e * 4));
        for (int i = t; i < 512; i += 128) sm[4096 + i] = d_W1K[i];
    }
    // prefetch W2K -> buf0 (async, hidden under MLP1)
#pragma unroll
    for (int r = 0; r < 8; ++r) {
        int idx = t + 128 * r;           // 1024 x 16B = 16KB
        cpa16(sA0 + idx * 16, d_W2K + idx * 4);
    }
    CP_COMMIT();
    __syncthreads();

    unsigned long long acc[32];

    // ---- MLP1: h1 = silu(W1K @ att) ----
    gemm_acc<8>(sm + 4096, sB, acc, jt, et);
    __syncthreads();                 // att + W1K reads done
    store_silu(acc, sB, jt, et);     // h1 -> sB
    // prefetch chunk0 -> buf1 (W1K dead)
#pragma unroll
    for (int r = 0; r < 8; ++r) {
        int idx4 = t + 128 * r;
        int k = idx4 >> 4;
        int jj = (idx4 & 15) * 4;
        cpa16(sA0 + 16384 + (k * 64 + jj) * 4, d_W3K + k * 256 + jj);
    }
    CP_COMMIT();
    CP_WAIT(1);                      // W2K ready; chunk0 in flight
    __syncthreads();                 // h1 + W2K visible

    // ---- MLP2: h2 = silu(W2K @ h1) ----
    gemm_acc<64>(sm, sB, acc, jt, et);
    __syncthreads();                 // h1 reads done
    store_silu(acc, sB, jt, et);     // h2 -> sB (in place)

    // ---- 4 chunks: gemm on alternating buf, prefetch c+1, consume regs ----
    int el0 = et * 8;
    int j0 = jt * 4;
#pragma unroll 1
    for (int c = 0; c < 4; ++c) {
        CP_WAIT(0);                  // chunk c data landed (this thread)
        __syncthreads();             // visible block-wide (+ h2 on c==0)
        const float* bufc = sm + ((c & 1) ? 0 : 4096);
        if (c < 3) gemm_acc<64>(bufc, sB, acc, jt, et);
        else       gemm_acc4<64>(bufc, sB, acc, jt, et);

        if (c < 2) {                 // prefetch full chunk c+1 (64x64)
            unsigned int dstoff = (c & 1) ? 16384u : 0u;
#pragma unroll
            for (int r = 0; r < 8; ++r) {
                int idx4 = t + 128 * r;
                int k = idx4 >> 4;
                int jj = (idx4 & 15) * 4;
                cpa16(sA0 + dstoff + (k * 64 + jj) * 4,
                      d_W3K + k * 256 + 64 * (c + 1) + jj);
            }
            CP_COMMIT();
        } else if (c == 2) {         // prefetch chunk3 (64x32, stride 32)
#pragma unroll
            for (int r = 0; r < 4; ++r) {
                int idx4 = t + 128 * r;
                int k = idx4 >> 3;
                int jj = (idx4 & 7) * 4;
                cpa16(sA0 + (k * 32 + jj) * 4, d_W3K + k * 256 + 192 + jj);
            }
            CP_COMMIT();
        }

        // consume: thread owns paired rows, edges el0..el0+7 (unrolled)
#pragma unroll
        for (int i = 0; i < 4; ++i) {
            float wa[8], wb[8];
            if (c < 3) {
#pragma unroll
                for (int j = 0; j < 8; ++j) UNPACK2(wa[j], wb[j], acc[j * 4 + i]);
            } else {
#pragma unroll
                for (int j = 0; j < 4; ++j) UNPACK2(wa[j], wb[j], acc[j * 4 + i]);
            }
            int ea = el0 + 2 * i, eb = ea + 1;
            if (c == 0) {
                cons_A(wa, ea, j0, sSrc, sDst, sSh);
                cons_A(wb, eb, j0, sSrc, sDst, sSh);
            } else if (c == 1) {
                cons_A(wa, ea, j0 + 32, sSrc, sDst, sSh);
                cons_A(wb, eb, j0 + 32, sSrc, sDst, sSh);
            } else if (c == 2) {
                cons_B(wa, ea, j0, sSrc, sDst, sSh);
                cons_B(wb, eb, j0, sSrc, sDst, sSh);
            } else {
                cons_C(wa, ea, j0, sSrc, sDst, sSh);
                cons_C(wb, eb, j0, sSrc, sDst, sSh);
            }
        }
    }
}

// ---------------- kernel 4: output projection + skip + RMS, 4 nodes/warp ----
// (unchanged — proven 64us)
__global__ void __launch_bounds__(256) k_out(float* __restrict__ out,
                                             const float* __restrict__ W2_0,
                                             const float* __restrict__ W2_1,
                                             const float* __restrict__ g0,
                                             const float* __restrict__ g1) {
    extern __shared__ float smo[];
    float* sW20 = smo;           // 6144  [k][o], natural layout
    float* sW21 = smo + 6144;    // 4096  [u][u'], natural layout
    float* sG   = smo + 10240;   // 96 (+32 pad)
    float* sBuf = smo + 10368;   // 8 warps * 640
    int t = threadIdx.x;
    for (int i = t; i < 6144; i += 256) sW20[i] = W2_0[i];
    for (int i = t; i < 4096; i += 256) sW21[i] = W2_1[i];
    if (t < 64) sG[t] = g0[t];
    else if (t < 96) sG[t] = g1[t - 64];
    __syncthreads();

    const float* gnsF = (const float*)d_g_ns;
    const float* gnvF = (const float*)d_g_nv;
    const float* gssF = (const float*)d_g_scs;
    const float* gsvF = (const float*)d_g_scv;

    int wid = t >> 5, l = t & 31;
    float* buf = sBuf + wid * 640;     // buf[k*5 + j]

    for (int it = 0; it < 2; ++it) {
        int nb = blockIdx.x * 64 + it * 32 + wid * 4;

        // ======== s section ========
#pragma unroll
        for (int j = 0; j < 4; ++j) {
            int nj = min(nb + j, NN - 1);
#pragma unroll
            for (int m = 0; m < 3; ++m) {
                int k = l + 32 * m;
                buf[k * 5 + j] = __ldg(gnsF + (size_t)nj * 96 + k);
            }
        }
        __syncwarp();

        float as0[4] = {0.f, 0.f, 0.f, 0.f};
        float as1[4] = {0.f, 0.f, 0.f, 0.f};
#pragma unroll 4
        for (int k = 0; k < 96; ++k) {
            float w0 = sW20[k * 64 + l];
            float w1 = sW20[k * 64 + l + 32];
            float a0 = buf[k * 5 + 0], a1 = buf[k * 5 + 1];
            float a2 = buf[k * 5 + 2], a3 = buf[k * 5 + 3];
            as0[0] += a0 * w0; as0[1] += a1 * w0; as0[2] += a2 * w0; as0[3] += a3 * w0;
            as1[0] += a0 * w1; as1[1] += a1 * w1; as1[2] += a2 * w1; as1[3] += a3 * w1;
        }
        __syncwarp();

        float vs0[4], vs1[4], ssq_s[4];
#pragma unroll
        for (int j = 0; j < 4; ++j) {
            int nj = min(nb + j, NN - 1);
            float v0 = as0[j] * 0.1020620726f + __ldg(gssF + (size_t)nj * 64 + l);
            float v1 = as1[j] * 0.1020620726f + __ldg(gssF + (size_t)nj * 64 + l + 32);
            vs0[j] = v0; vs1[j] = v1;
            ssq_s[j] = v0 * v0 + v1 * v1;
        }

        // ======== v sections ========
        float vvs[3][4];
        float ssq_v[4] = {0.f, 0.f, 0.f, 0.f};
#pragma unroll 1
        for (int c = 0; c < 3; ++c) {
#pragma unroll
            for (int j = 0; j < 4; ++j) {
                int nj = min(nb + j, NN - 1);
#pragma unroll
                for (int m = 0; m < 4; ++m) {
                    int u = l + 32 * m;
                    buf[u * 5 + j] = __ldg(gnvF + (size_t)nj * 384 + c * 128 + u);
                }
            }
            __syncwarp();

            float av[4] = {0.f, 0.f, 0.f, 0.f};
#pragma unroll 4
            for (int u = 0; u < 128; ++u) {
                float w = sW21[u * 32 + l];
                av[0] += buf[u * 5 + 0] * w;
                av[1] += buf[u * 5 + 1] * w;
                av[2] += buf[u * 5 + 2] * w;
                av[3] += buf[u * 5 + 3] * w;
            }
            __syncwarp();

            int o = l * 3 + c;
#pragma unroll
            for (int j = 0; j < 4; ++j) {
                int nj = min(nb + j, NN - 1);
                float val = av[j] * 0.0883883476f + __ldg(gsvF + (size_t)nj * 96 + o);
                vvs[c][j] = val;
                ssq_v[j] += val * val;
            }
        }

        // ======== warp reductions + writes ========
#pragma unroll
        for (int d = 16; d; d >>= 1) {
#pragma unroll
            for (int j = 0; j < 4; ++j) {
                ssq_s[j] += __shfl_xor_sync(0xffffffffu, ssq_s[j], d);
                ssq_v[j] += __shfl_xor_sync(0xffffffffu, ssq_v[j], d);
            }
        }
#pragma unroll
        for (int j = 0; j < 4; ++j) {
            int n = nb + j;
            if (n < NN) {
                float rs = rsqrtf(ssq_s[j] * (1.0f / 64.0f) + 1e-5f);
                float rv = rsqrtf(ssq_v[j] * (1.0f / 32.0f) + 1e-5f);
                out[(size_t)n * 160 + l]      = vs0[j] * rs * sG[l];
                out[(size_t)n * 160 + l + 32] = vs1[j] * rs * sG[l + 32];
                float gv = rv * sG[64 + l];
#pragma unroll
                for (int c = 0; c < 3; ++c)
                    out[(size_t)n * 160 + 64 + l * 3 + c] = vvs[c][j] * gv;
            }
        }
        __syncwarp();
    }
}

// ---------------- launch ----------------
extern "C" void kernel_launch(void* const* d_in, const int* in_sizes, int n_in,
                              void* d_out, int out_size) {
    const float* nh    = (const float*)d_in[0];
    const int*   ei    = (const int*)  d_in[1];
    const float* esh   = (const float*)d_in[2];
    const float* eattr = (const float*)d_in[3];
    const float* W1_0  = (const float*)d_in[4];
    const float* W1_1  = (const float*)d_in[5];
    const float* Wfc1  = (const float*)d_in[6];
    const float* Wfc2  = (const float*)d_in[7];
    const float* Wfc3  = (const float*)d_in[8];
    const float* W2_0  = (const float*)d_in[9];
    const float* W2_1  = (const float*)d_in[10];
    const float* Wsc0  = (const float*)d_in[11];
    const float* Wsc1  = (const float*)d_in[12];
    const float* g0    = (const float*)d_in[13];
    const float* g1    = (const float*)d_in[14];
    float* out = (float*)d_out;

    cudaFuncSetAttribute(k_edge, cudaFuncAttributeMaxDynamicSharedMemorySize, 68608);
    cudaFuncSetAttribute(k_out, cudaFuncAttributeMaxDynamicSharedMemorySize, 61952);

    k_init<<<391, 256>>>(nh, W1_0, W1_1, Wsc0, Wsc1, Wfc1, Wfc2, Wfc3);
    k_edge<<<3125, 128, 68608>>>(ei, esh, eattr);
    k_out<<<391, 256, 61952>>>(out, W2_0, W2_1, g0, g1);
}

// round 16
// speedup vs baseline: 2.2861x; 1.0795x over previous
#include <cuda_runtime.h>

#define NN 25000
#define NE 400000

#define INV_SQRT3 0.57735026919f
#define INV_SQRT2 0.70710678119f

// ---------------- scratch (device globals; allocation-free) ----------------
__device__ float4 d_g_s  [NN * 16];   // s   = s_in @ W1_0 /8           (N,64)
__device__ float4 d_g_v  [NN * 24];   // v   = v_in . W1_1 /sqrt32      (N,32,3) [u*3+c]
__device__ float4 d_g_scs[NN * 16];   // sc_s                           (N,64)
__device__ float4 d_g_scv[NN * 24];   // sc_v                           (N,96)  [u*3+c]
__device__ float4 d_g_ns [NN * 24];   // scatter accum s-part           (N,96)
__device__ float4 d_g_nv [NN * 96];   // scatter accum v-part           (N,3,128) [c][u]
__device__ float  d_W1K[8 * 64];      // Wfc1 natural [k][j], prescaled 1/sqrt(8)
__device__ float  d_W2K[64 * 64];     // Wfc2 natural [k][j], prescaled 1/8
// Wfc3 PERMUTED layout [k][R], prescaled (see R14 mapping).
__device__ float  d_W3K[64 * 256];

// ---------------- f32x2 / async helpers ----------------
#define FMA2(d, a, b) \
    asm("fma.rn.f32x2 %0, %1, %2, %0;" : "+l"(d) : "l"(a), "l"(b))
#define PACK2(d, lo, hi) \
    asm("mov.b64 %0, {%1, %2};" : "=l"(d) : "f"(lo), "f"(hi))
#define UNPACK2(lo, hi, s) \
    asm("mov.b64 {%0, %1}, %2;" : "=f"(lo), "=f"(hi) : "l"(s))

__device__ __forceinline__ void cpa16(unsigned int saddr, const float* g) {
    asm volatile("cp.async.ca.shared.global [%0], [%1], 16;"
                 :: "r"(saddr), "l"(g) : "memory");
}
#define CP_COMMIT() asm volatile("cp.async.commit_group;" ::: "memory")
#define CP_WAIT(n)  asm volatile("cp.async.wait_group %0;" :: "n"(n) : "memory")

__device__ __forceinline__ float silu_f(float x) {
    return x / (1.0f + __expf(-x));
}

__device__ __forceinline__ void red4(float* p, float a, float b, float c, float d) {
    asm volatile("red.global.add.v4.f32 [%0], {%1,%2,%3,%4};"
                 :: "l"(p), "f"(a), "f"(b), "f"(c), "f"(d) : "memory");
}

// ---------------- 8x8 register-tiled GEMM (acc stays in registers) ---------
template <int KLEN>
__device__ __forceinline__ void gemm_acc(const float* __restrict__ sAm,
                                         const float* __restrict__ sBm,
                                         unsigned long long* acc,
                                         int jt, int et) {
    const float* Ap = sAm + jt * 8;
    const float* Bp = sBm + et * 8;
#pragma unroll
    for (int i = 0; i < 32; ++i) acc[i] = 0ull;
#pragma unroll 4
    for (int k = 0; k < KLEN; ++k) {
        float4 a0 = *reinterpret_cast<const float4*>(Ap + k * 64);
        float4 a1 = *reinterpret_cast<const float4*>(Ap + k * 64 + 4);
        ulonglong2 b01 = *reinterpret_cast<const ulonglong2*>(Bp + k * 128);
        ulonglong2 b23 = *reinterpret_cast<const ulonglong2*>(Bp + k * 128 + 4);
        unsigned long long ap;
        PACK2(ap, a0.x, a0.x);
        FMA2(acc[0],  ap, b01.x); FMA2(acc[1],  ap, b01.y);
        FMA2(acc[2],  ap, b23.x); FMA2(acc[3],  ap, b23.y);
        PACK2(ap, a0.y, a0.y);
        FMA2(acc[4],  ap, b01.x); FMA2(acc[5],  ap, b01.y);
        FMA2(acc[6],  ap, b23.x); FMA2(acc[7],  ap, b23.y);
        PACK2(ap, a0.z, a0.z);
        FMA2(acc[8],  ap, b01.x); FMA2(acc[9],  ap, b01.y);
        FMA2(acc[10], ap, b23.x); FMA2(acc[11], ap, b23.y);
        PACK2(ap, a0.w, a0.w);
        FMA2(acc[12], ap, b01.x); FMA2(acc[13], ap, b01.y);
        FMA2(acc[14], ap, b23.x); FMA2(acc[15], ap, b23.y);
        PACK2(ap, a1.x, a1.x);
        FMA2(acc[16], ap, b01.x); FMA2(acc[17], ap, b01.y);
        FMA2(acc[18], ap, b23.x); FMA2(acc[19], ap, b23.y);
        PACK2(ap, a1.y, a1.y);
        FMA2(acc[20], ap, b01.x); FMA2(acc[21], ap, b01.y);
        FMA2(acc[22], ap, b23.x); FMA2(acc[23], ap, b23.y);
        PACK2(ap, a1.z, a1.z);
        FMA2(acc[24], ap, b01.x); FMA2(acc[25], ap, b01.y);
        FMA2(acc[26], ap, b23.x); FMA2(acc[27], ap, b23.y);
        PACK2(ap, a1.w, a1.w);
        FMA2(acc[28], ap, b01.x); FMA2(acc[29], ap, b01.y);
        FMA2(acc[30], ap, b23.x); FMA2(acc[31], ap, b23.y);
    }
}

// 4x8 tile for the 32-row chunk3 (A stride 32)
template <int KLEN>
__device__ __forceinline__ void gemm_acc4(const float* __restrict__ sAm,
                                          const float* __restrict__ sBm,
                                          unsigned long long* acc,
                                          int jt, int et) {
    const float* Ap = sAm + jt * 4;
    const float* Bp = sBm + et * 8;
#pragma unroll
    for (int i = 0; i < 16; ++i) acc[i] = 0ull;
#pragma unroll 4
    for (int k = 0; k < KLEN; ++k) {
        float4 a0 = *reinterpret_cast<const float4*>(Ap + k * 32);
        ulonglong2 b01 = *reinterpret_cast<const ulonglong2*>(Bp + k * 128);
        ulonglong2 b23 = *reinterpret_cast<const ulonglong2*>(Bp + k * 128 + 4);
        unsigned long long ap;
        PACK2(ap, a0.x, a0.x);
        FMA2(acc[0],  ap, b01.x); FMA2(acc[1],  ap, b01.y);
        FMA2(acc[2],  ap, b23.x); FMA2(acc[3],  ap, b23.y);
        PACK2(ap, a0.y, a0.y);
        FMA2(acc[4],  ap, b01.x); FMA2(acc[5],  ap, b01.y);
        FMA2(acc[6],  ap, b23.x); FMA2(acc[7],  ap, b23.y);
        PACK2(ap, a0.z, a0.z);
        FMA2(acc[8],  ap, b01.x); FMA2(acc[9],  ap, b01.y);
        FMA2(acc[10], ap, b23.x); FMA2(acc[11], ap, b23.y);
        PACK2(ap, a0.w, a0.w);
        FMA2(acc[12], ap, b01.x); FMA2(acc[13], ap, b01.y);
        FMA2(acc[14], ap, b23.x); FMA2(acc[15], ap, b23.y);
    }
}

// store acc with silu into sD (stride 128)
__device__ __forceinline__ void store_silu(const unsigned long long* acc,
                                           float* __restrict__ sD,
                                           int jt, int et) {
    float* D = sD + (size_t)(jt * 8) * 128 + et * 8;
#pragma unroll
    for (int j = 0; j < 8; ++j) {
#pragma unroll
        for (int i = 0; i < 4; ++i) {
            float lo, hi;
            UNPACK2(lo, hi, acc[j * 4 + i]);
            unsigned long long p;
            PACK2(p, silu_f(lo), silu_f(hi));
            *reinterpret_cast<unsigned long long*>(D + j * 128 + 2 * i) = p;
        }
    }
}

// ---------------- consume helpers (edge data from smem cache) --------------
__device__ __forceinline__ void cons_A(const float* w, int el, int j0,
                                       const int* sSrc, const int* sDst,
                                       const float4* sSh) {
    int src = sSrc[el], dst = sDst[el];
    float4 sh = sSh[el];
    float4 s = __ldg(reinterpret_cast<const float4*>(
        (const float*)d_g_s + (size_t)dst * 64 + j0));
    float* nsp = (float*)d_g_ns + (size_t)src * 96 + j0;
    red4(nsp, w[0]*s.x*sh.x, w[1]*s.y*sh.x, w[2]*s.z*sh.x, w[3]*s.w*sh.x);
    float a0 = w[4]*s.x, a1 = w[5]*s.y, a2 = w[6]*s.z, a3 = w[7]*s.w;
    float* nvp = (float*)d_g_nv + (size_t)src * 384 + j0;
    red4(nvp,       a0*sh.y, a1*sh.y, a2*sh.y, a3*sh.y);
    red4(nvp + 128, a0*sh.z, a1*sh.z, a2*sh.z, a3*sh.z);
    red4(nvp + 256, a0*sh.w, a1*sh.w, a2*sh.w, a3*sh.w);
}

__device__ __forceinline__ void cons_B(const float* w, int el, int u0,
                                       const int* sSrc, const int* sDst,
                                       const float4* sSh) {
    int src = sSrc[el], dst = sDst[el];
    float4 sh = sSh[el];
    const float4* vp = reinterpret_cast<const float4*>(
        (const float*)d_g_v + (size_t)dst * 96 + u0 * 3);
    float4 v0 = __ldg(vp), v1 = __ldg(vp + 1), v2 = __ldg(vp + 2);
    float vv[12] = {v0.x,v0.y,v0.z,v0.w, v1.x,v1.y,v1.z,v1.w,
                    v2.x,v2.y,v2.z,v2.w};
    float* nvp = (float*)d_g_nv + (size_t)src * 384;
#pragma unroll
    for (int c = 0; c < 3; ++c) {
        red4(nvp + c*128 + 64 + u0,
             w[0]*vv[0+c]*sh.x, w[1]*vv[3+c]*sh.x,
             w[2]*vv[6+c]*sh.x, w[3]*vv[9+c]*sh.x);
    }
    float m[4];
#pragma unroll
    for (int q = 0; q < 4; ++q)
        m[q] = w[4+q] * (vv[q*3]*sh.y + vv[q*3+1]*sh.z + vv[q*3+2]*sh.w);
    red4((float*)d_g_ns + (size_t)src * 96 + 64 + u0, m[0], m[1], m[2], m[3]);
}

__device__ __forceinline__ void cons_C(const float* w, int el, int u0,
                                       const int* sSrc, const int* sDst,
                                       const float4* sSh) {
    int src = sSrc[el], dst = sDst[el];
    float4 sh = sSh[el];
    const float4* vp = reinterpret_cast<const float4*>(
        (const float*)d_g_v + (size_t)dst * 96 + u0 * 3);
    float4 v0 = __ldg(vp), v1 = __ldg(vp + 1), v2 = __ldg(vp + 2);
    float vv[12] = {v0.x,v0.y,v0.z,v0.w, v1.x,v1.y,v1.z,v1.w,
                    v2.x,v2.y,v2.z,v2.w};
    float mx[4], my[4], mz[4];
#pragma unroll
    for (int q = 0; q < 4; ++q) {
        float vx = vv[q*3], vy = vv[q*3+1], vz = vv[q*3+2];
        mx[q] = w[q] * (vy*sh.w - vz*sh.z);
        my[q] = w[q] * (vz*sh.y - vx*sh.w);
        mz[q] = w[q] * (vx*sh.z - vy*sh.y);
    }
    float* nvp = (float*)d_g_nv + (size_t)src * 384;
    red4(nvp +       96 + u0, mx[0], mx[1], mx[2], mx[3]);
    red4(nvp + 128 + 96 + u0, my[0], my[1], my[2], my[3]);
    red4(nvp + 256 + 96 + u0, mz[0], mz[1], mz[2], mz[3]);
}

// ---------------- kernel 1: init (zero + prescale/permute + node prep) ------
// Node prep: 4 nodes per warp, inputs staged in stride-5 per-warp smem buffer,
// each weight LDS feeds 4 nodes (proven k_out pattern).
// smem floats: sW10 4096 | sWsc0 4096 | sW11 1024 | sWsc1 1024 | buf 8*800
// = 16640 fl = 66560 B -> 2 blocks/SM.
__global__ void __launch_bounds__(256) k_init(const float* __restrict__ nh,
                                              const float* __restrict__ W1_0,
                                              const float* __restrict__ W1_1,
                                              const float* __restrict__ Wsc0,
                                              const float* __restrict__ Wsc1,
                                              const float* __restrict__ Wfc1,
                                              const float* __restrict__ Wfc2,
                                              const float* __restrict__ Wfc3) {
    extern __shared__ float smi[];
    float* sW10  = smi;            // 4096
    float* sWsc0 = smi + 4096;     // 4096
    float* sW11  = smi + 8192;     // 1024
    float* sWsc1 = smi + 9216;     // 1024
    float* sStg  = smi + 10240;    // 8 warps * 800
    int t = threadIdx.x;
    int gid = blockIdx.x * 256 + t;
    const int GSTRIDE = 391 * 256;

    // --- grid-strided: zero accumulators (3M float4) ---
    {
        float4 z = make_float4(0.f, 0.f, 0.f, 0.f);
        for (int i = gid; i < NN * 120; i += GSTRIDE) {
            if (i < NN * 24) d_g_ns[i] = z;
            else             d_g_nv[i - NN * 24] = z;
        }
    }
    // --- grid-strided: weight prescale + W3 permute (20992 entries) ---
    for (int j = gid; j < 20992; j += GSTRIDE) {
        if (j < 512) {
            d_W1K[j] = Wfc1[j] * 0.3535533906f;
        } else if (j < 4608) {
            d_W2K[j - 512] = Wfc2[j - 512] * 0.125f;
        } else {
            int m = j - 4608;
            int k = m >> 8, R = m & 255;
            int orig = -1;
            if (R < 192) {
                int chunk = R >> 6, r = R & 63, jtp = r >> 3, q = r & 7;
                int fh, sh2;
                if (chunk == 0)      { fh = 0;   sh2 = 64;  }
                else if (chunk == 1) { fh = 32;  sh2 = 96;  }
                else                 { fh = 128; sh2 = 160; }
                orig = (q < 4) ? (fh + jtp * 4 + q) : (sh2 + jtp * 4 + q - 4);
            } else if (R < 224) {
                orig = R;   // w4 rows, identity
            }
            float v = 0.f;
            if (orig >= 0) {
                float s = 0.03125f;  // (1/sqrt(64)) * (1/sqrt(16))
                if (orig >= 192)      s *= INV_SQRT2;
                else if (orig >= 160) s *= INV_SQRT3;
                v = Wfc3[k * 224 + orig] * s;
            }
            d_W3K[m] = v;
        }
    }

    // --- load weights to smem ---
    for (int i = t; i < 4096; i += 256) { sW10[i] = W1_0[i]; sWsc0[i] = Wsc0[i]; }
    for (int i = t; i < 1024; i += 256) { sW11[i] = W1_1[i]; sWsc1[i] = Wsc1[i]; }
    __syncthreads();

    int wid = t >> 5, l = t & 31;
    float* gs  = (float*)d_g_s;
    float* gv  = (float*)d_g_v;
    float* gss = (float*)d_g_scs;
    float* gsv = (float*)d_g_scv;
    float* buf = sStg + wid * 800;   // buf[i*5 + j], i < 160, j < 4

    for (int it = 0; it < 2; ++it) {
        int nb = blockIdx.x * 64 + it * 32 + wid * 4;

        // stage 4 nodes' inputs (stride-5: conflict-free STS, broadcast reads)
#pragma unroll
        for (int j = 0; j < 4; ++j) {
            int nj = min(nb + j, NN - 1);
            const float* src = nh + (size_t)nj * 160;
#pragma unroll
            for (int m = 0; m < 5; ++m) {
                int i = l + 32 * m;
                buf[i * 5 + j] = __ldg(src + i);
            }
        }
        __syncwarp();

        // ---- s part: outputs o = l and o = l+32 for 4 nodes ----
        float a0[4] = {0,0,0,0}, a1[4] = {0,0,0,0};
        float b0[4] = {0,0,0,0}, b1[4] = {0,0,0,0};
#pragma unroll 4
        for (int u = 0; u < 64; ++u) {
            float w0  = sW10 [u * 64 + l];
            float w1  = sW10 [u * 64 + l + 32];
            float ws0 = sWsc0[u * 64 + l];
            float ws1 = sWsc0[u * 64 + l + 32];
#pragma unroll
            for (int j = 0; j < 4; ++j) {
                float x = buf[u * 5 + j];
                a0[j] += x * w0;  a1[j] += x * w1;
                b0[j] += x * ws0; b1[j] += x * ws1;
            }
        }
#pragma unroll
        for (int j = 0; j < 4; ++j) {
            int n = nb + j;
            if (n < NN) {
                gs [(size_t)n * 64 + l]      = a0[j] * 0.125f;
                gs [(size_t)n * 64 + l + 32] = a1[j] * 0.125f;
                gss[(size_t)n * 64 + l]      = b0[j] * 0.125f;
                gss[(size_t)n * 64 + l + 32] = b1[j] * 0.125f;
            }
        }

        // ---- v part: lane l = output row u'=l, components c=0..2 ----
        float va[3][4], vb[3][4];
#pragma unroll
        for (int c = 0; c < 3; ++c)
#pragma unroll
            for (int j = 0; j < 4; ++j) { va[c][j] = 0.f; vb[c][j] = 0.f; }
#pragma unroll 4
        for (int u = 0; u < 32; ++u) {
            float wv  = sW11 [u * 32 + l];
            float wsv = sWsc1[u * 32 + l];
#pragma unroll
            for (int c = 0; c < 3; ++c) {
#pragma unroll
                for (int j = 0; j < 4; ++j) {
                    float x = buf[(64 + u * 3 + c) * 5 + j];
                    va[c][j] += x * wv;
                    vb[c][j] += x * wsv;
                }
            }
        }
#pragma unroll
        for (int j = 0; j < 4; ++j) {
            int n = nb + j;
            if (n < NN) {
#pragma unroll
                for (int c = 0; c < 3; ++c) {
                    gv [(size_t)n * 96 + 3 * l + c] = va[c][j] * 0.1767766953f;
                    gsv[(size_t)n * 96 + 3 * l + c] = vb[c][j] * 0.1767766953f;
                }
            }
        }
        __syncwarp();
    }
}

// ---------------- kernel 3: fused GEMM + register consume, cp.async --------
// smem floats: buf0 [0,4096) | buf1 [4096,8192) | sB [8192,16384)
//              | sSrc [16384,16512) | sDst [16512,16640) | sSh [16640,17152)
__global__ void __launch_bounds__(128, 3) k_edge(const int* __restrict__ ei,
                                                 const float* __restrict__ esh,
                                                 const float* __restrict__ eattr) {
    extern __shared__ float sm[];
    float* sB = sm + 8192;
    int* sSrc = (int*)(sm + 16384);
    int* sDst = (int*)(sm + 16512);
    float4* sSh = (float4*)(sm + 16640);
    int t = threadIdx.x;
    int jt = t & 7, et = t >> 3;
    int ebase = blockIdx.x * 128;   // NE = 3125*128 exactly
    unsigned int sA0 = (unsigned int)__cvta_generic_to_shared(sm);

    // stage att transposed [k][e] into sB; edge data into cache; W1K into buf1
    {
        int e = ebase + t;
        const float4* ap = reinterpret_cast<const float4*>(eattr + (size_t)e * 8);
        float4 a0 = __ldg(ap), a1 = __ldg(ap + 1);
        sB[0*128+t] = a0.x; sB[1*128+t] = a0.y;
        sB[2*128+t] = a0.z; sB[3*128+t] = a0.w;
        sB[4*128+t] = a1.x; sB[5*128+t] = a1.y;
        sB[6*128+t] = a1.z; sB[7*128+t] = a1.w;
        sSrc[t] = __ldg(ei + e);
        sDst[t] = __ldg(ei + NE + e);
        sSh[t]  = __ldg(reinterpret_cast<const float4*>(esh + (size_t)e * 4));
        for (int i = t; i < 512; i += 128) sm[4096 + i] = d_W1K[i];
    }
    // prefetch W2K -> buf0 (async, hidden under MLP1)
#pragma unroll
    for (int r = 0; r < 8; ++r) {
        int idx = t + 128 * r;           // 1024 x 16B = 16KB
        cpa16(sA0 + idx * 16, d_W2K + idx * 4);
    }
    CP_COMMIT();
    __syncthreads();

    unsigned long long acc[32];

    // ---- MLP1: h1 = silu(W1K @ att) ----
    gemm_acc<8>(sm + 4096, sB, acc, jt, et);
    __syncthreads();                 // att + W1K reads done
    store_silu(acc, sB, jt, et);     // h1 -> sB
    // prefetch chunk0 -> buf1 (W1K dead)
#pragma unroll
    for (int r = 0; r < 8; ++r) {
        int idx4 = t + 128 * r;
        int k = idx4 >> 4;
        int jj = (idx4 & 15) * 4;
        cpa16(sA0 + 16384 + (k * 64 + jj) * 4, d_W3K + k * 256 + jj);
    }
    CP_COMMIT();
    CP_WAIT(1);                      // W2K ready; chunk0 in flight
    __syncthreads();                 // h1 + W2K visible

    // ---- MLP2: h2 = silu(W2K @ h1) ----
    gemm_acc<64>(sm, sB, acc, jt, et);
    __syncthreads();                 // h1 reads done
    store_silu(acc, sB, jt, et);     // h2 -> sB (in place)

    // ---- 4 chunks: gemm on alternating buf, prefetch c+1, consume regs ----
    int el0 = et * 8;
    int j0 = jt * 4;
#pragma unroll 1
    for (int c = 0; c < 4; ++c) {
        CP_WAIT(0);                  // chunk c data landed (this thread)
        __syncthreads();             // visible block-wide (+ h2 on c==0)
        const float* bufc = sm + ((c & 1) ? 0 : 4096);
        if (c < 3) gemm_acc<64>(bufc, sB, acc, jt, et);
        else       gemm_acc4<64>(bufc, sB, acc, jt, et);

        if (c < 2) {                 // prefetch full chunk c+1 (64x64)
            unsigned int dstoff = (c & 1) ? 16384u : 0u;
#pragma unroll
            for (int r = 0; r < 8; ++r) {
                int idx4 = t + 128 * r;
                int k = idx4 >> 4;
                int jj = (idx4 & 15) * 4;
                cpa16(sA0 + dstoff + (k * 64 + jj) * 4,
                      d_W3K + k * 256 + 64 * (c + 1) + jj);
            }
            CP_COMMIT();
        } else if (c == 2) {         // prefetch chunk3 (64x32, stride 32)
#pragma unroll
            for (int r = 0; r < 4; ++r) {
                int idx4 = t + 128 * r;
                int k = idx4 >> 3;
                int jj = (idx4 & 7) * 4;
                cpa16(sA0 + (k * 32 + jj) * 4, d_W3K + k * 256 + 192 + jj);
            }
            CP_COMMIT();
        }

        // consume: thread owns paired rows, edges el0..el0+7 (unrolled)
#pragma unroll
        for (int i = 0; i < 4; ++i) {
            float wa[8], wb[8];
            if (c < 3) {
#pragma unroll
                for (int j = 0; j < 8; ++j) UNPACK2(wa[j], wb[j], acc[j * 4 + i]);
            } else {
#pragma unroll
                for (int j = 0; j < 4; ++j) UNPACK2(wa[j], wb[j], acc[j * 4 + i]);
            }
            int ea = el0 + 2 * i, eb = ea + 1;
            if (c == 0) {
                cons_A(wa, ea, j0, sSrc, sDst, sSh);
                cons_A(wb, eb, j0, sSrc, sDst, sSh);
            } else if (c == 1) {
                cons_A(wa, ea, j0 + 32, sSrc, sDst, sSh);
                cons_A(wb, eb, j0 + 32, sSrc, sDst, sSh);
            } else if (c == 2) {
                cons_B(wa, ea, j0, sSrc, sDst, sSh);
                cons_B(wb, eb, j0, sSrc, sDst, sSh);
            } else {
                cons_C(wa, ea, j0, sSrc, sDst, sSh);
                cons_C(wb, eb, j0, sSrc, sDst, sSh);
            }
        }
    }
}

// ---------------- kernel 4: output projection + skip + RMS, 4 nodes/warp ----
// (unchanged — proven 64us)
__global__ void __launch_bounds__(256) k_out(float* __restrict__ out,
                                             const float* __restrict__ W2_0,
                                             const float* __restrict__ W2_1,
                                             const float* __restrict__ g0,
                                             const float* __restrict__ g1) {
    extern __shared__ float smo[];
    float* sW20 = smo;           // 6144  [k][o], natural layout
    float* sW21 = smo + 6144;    // 4096  [u][u'], natural layout
    float* sG   = smo + 10240;   // 96 (+32 pad)
    float* sBuf = smo + 10368;   // 8 warps * 640
    int t = threadIdx.x;
    for (int i = t; i < 6144; i += 256) sW20[i] = W2_0[i];
    for (int i = t; i < 4096; i += 256) sW21[i] = W2_1[i];
    if (t < 64) sG[t] = g0[t];
    else if (t < 96) sG[t] = g1[t - 64];
    __syncthreads();

    const float* gnsF = (const float*)d_g_ns;
    const float* gnvF = (const float*)d_g_nv;
    const float* gssF = (const float*)d_g_scs;
    const float* gsvF = (const float*)d_g_scv;

    int wid = t >> 5, l = t & 31;
    float* buf = sBuf + wid * 640;     // buf[k*5 + j]

    for (int it = 0; it < 2; ++it) {
        int nb = blockIdx.x * 64 + it * 32 + wid * 4;

        // ======== s section ========
#pragma unroll
        for (int j = 0; j < 4; ++j) {
            int nj = min(nb + j, NN - 1);
#pragma unroll
            for (int m = 0; m < 3; ++m) {
                int k = l + 32 * m;
                buf[k * 5 + j] = __ldg(gnsF + (size_t)nj * 96 + k);
            }
        }
        __syncwarp();

        float as0[4] = {0.f, 0.f, 0.f, 0.f};
        float as1[4] = {0.f, 0.f, 0.f, 0.f};
#pragma unroll 4
        for (int k = 0; k < 96; ++k) {
            float w0 = sW20[k * 64 + l];
            float w1 = sW20[k * 64 + l + 32];
            float a0 = buf[k * 5 + 0], a1 = buf[k * 5 + 1];
            float a2 = buf[k * 5 + 2], a3 = buf[k * 5 + 3];
            as0[0] += a0 * w0; as0[1] += a1 * w0; as0[2] += a2 * w0; as0[3] += a3 * w0;
            as1[0] += a0 * w1; as1[1] += a1 * w1; as1[2] += a2 * w1; as1[3] += a3 * w1;
        }
        __syncwarp();

        float vs0[4], vs1[4], ssq_s[4];
#pragma unroll
        for (int j = 0; j < 4; ++j) {
            int nj = min(nb + j, NN - 1);
            float v0 = as0[j] * 0.1020620726f + __ldg(gssF + (size_t)nj * 64 + l);
            float v1 = as1[j] * 0.1020620726f + __ldg(gssF + (size_t)nj * 64 + l + 32);
            vs0[j] = v0; vs1[j] = v1;
            ssq_s[j] = v0 * v0 + v1 * v1;
        }

        // ======== v sections ========
        float vvs[3][4];
        float ssq_v[4] = {0.f, 0.f, 0.f, 0.f};
#pragma unroll 1
        for (int c = 0; c < 3; ++c) {
#pragma unroll
            for (int j = 0; j < 4; ++j) {
                int nj = min(nb + j, NN - 1);
#pragma unroll
                for (int m = 0; m < 4; ++m) {
                    int u = l + 32 * m;
                    buf[u * 5 + j] = __ldg(gnvF + (size_t)nj * 384 + c * 128 + u);
                }
            }
            __syncwarp();

            float av[4] = {0.f, 0.f, 0.f, 0.f};
#pragma unroll 4
            for (int u = 0; u < 128; ++u) {
                float w = sW21[u * 32 + l];
                av[0] += buf[u * 5 + 0] * w;
                av[1] += buf[u * 5 + 1] * w;
                av[2] += buf[u * 5 + 2] * w;
                av[3] += buf[u * 5 + 3] * w;
            }
            __syncwarp();

            int o = l * 3 + c;
#pragma unroll
            for (int j = 0; j < 4; ++j) {
                int nj = min(nb + j, NN - 1);
                float val = av[j] * 0.0883883476f + __ldg(gsvF + (size_t)nj * 96 + o);
                vvs[c][j] = val;
                ssq_v[j] += val * val;
            }
        }

        // ======== warp reductions + writes ========
#pragma unroll
        for (int d = 16; d; d >>= 1) {
#pragma unroll
            for (int j = 0; j < 4; ++j) {
                ssq_s[j] += __shfl_xor_sync(0xffffffffu, ssq_s[j], d);
                ssq_v[j] += __shfl_xor_sync(0xffffffffu, ssq_v[j], d);
            }
        }
#pragma unroll
        for (int j = 0; j < 4; ++j) {
            int n = nb + j;
            if (n < NN) {
                float rs = rsqrtf(ssq_s[j] * (1.0f / 64.0f) + 1e-5f);
                float rv = rsqrtf(ssq_v[j] * (1.0f / 32.0f) + 1e-5f);
                out[(size_t)n * 160 + l]      = vs0[j] * rs * sG[l];
                out[(size_t)n * 160 + l + 32] = vs1[j] * rs * sG[l + 32];
                float gv = rv * sG[64 + l];
#pragma unroll
                for (int c = 0; c < 3; ++c)
                    out[(size_t)n * 160 + 64 + l * 3 + c] = vvs[c][j] * gv;
            }
        }
        __syncwarp();
    }
}

// ---------------- launch ----------------
extern "C" void kernel_launch(void* const* d_in, const int* in_sizes, int n_in,
                              void* d_out, int out_size) {
    const float* nh    = (const float*)d_in[0];
    const int*   ei    = (const int*)  d_in[1];
    const float* esh   = (const float*)d_in[2];
    const float* eattr = (const float*)d_in[3];
    const float* W1_0  = (const float*)d_in[4];
    const float* W1_1  = (const float*)d_in[5];
    const float* Wfc1  = (const float*)d_in[6];
    const float* Wfc2  = (const float*)d_in[7];
    const float* Wfc3  = (const float*)d_in[8];
    const float* W2_0  = (const float*)d_in[9];
    const float* W2_1  = (const float*)d_in[10];
    const float* Wsc0  = (const float*)d_in[11];
    const float* Wsc1  = (const float*)d_in[12];
    const float* g0    = (const float*)d_in[13];
    const float* g1    = (const float*)d_in[14];
    float* out = (float*)d_out;

    cudaFuncSetAttribute(k_init, cudaFuncAttributeMaxDynamicSharedMemorySize, 66560);
    cudaFuncSetAttribute(k_edge, cudaFuncAttributeMaxDynamicSharedMemorySize, 68608);
    cudaFuncSetAttribute(k_out, cudaFuncAttributeMaxDynamicSharedMemorySize, 61952);

    k_init<<<391, 256, 66560>>>(nh, W1_0, W1_1, Wsc0, Wsc1, Wfc1, Wfc2, Wfc3);
    k_edge<<<3125, 128, 68608>>>(ei, esh, eattr);
    k_out<<<391, 256, 61952>>>(out, W2_0, W2_1, g0, g1);
}